// round 2
// baseline (speedup 1.0000x reference)
#include <cuda_runtime.h>
#include <math.h>

// Problem constants
#define Bn 4
#define Sn 2048
#define Hn 512
#define NHn 8
#define DHn 64
#define Fn 2048
#define Ln 4
#define Mn (Bn * Sn)  // 8192

// Scratch (device globals; no allocation allowed)
__device__ float g_x[Mn * Hn];
__device__ float g_q[Mn * Hn];
__device__ float g_k[Mn * Hn];
__device__ float g_v[Mn * Hn];
__device__ float g_ctx[Mn * Hn];
__device__ float g_attn[Mn * Hn];
__device__ float g_ffn[Mn * Fn];
__device__ float g_sc[(size_t)Bn * NHn * Sn * Sn];  // 512 MB scores/probs

// ---------------------------------------------------------------------------
// Generic tiled GEMM: C[M,N] = A[M,K] * W[K,N] + bias (+res / gelu epilogue)
// BM=BN=64, BK=16, 256 threads, 4x4 per thread.
// EPI: 0 = bias only, 1 = bias + residual, 2 = bias then exact GELU
// ---------------------------------------------------------------------------
template <int EPI>
__global__ void __launch_bounds__(256) gemm_kernel(
    const float* __restrict__ A, const float* __restrict__ W,
    const float* __restrict__ bias, const float* __restrict__ res,
    float* __restrict__ C, int K, int N)
{
    __shared__ __align__(16) float As[16][68];
    __shared__ __align__(16) float Ws[16][68];
    const int tid = threadIdx.x;
    const int tx = tid & 15, ty = tid >> 4;
    const int m0 = blockIdx.y << 6, n0 = blockIdx.x << 6;
    const int lam = tid >> 2, lak = (tid & 3) << 2;      // A tile load map
    const int lwk = tid >> 4, lwn = (tid & 15) << 2;     // W tile load map
    const float* Ap = A + (size_t)(m0 + lam) * K + lak;
    const float* Wp = W + (size_t)lwk * N + (n0 + lwn);

    float acc[4][4] = {};
    for (int k0 = 0; k0 < K; k0 += 16) {
        float4 av = *(const float4*)(Ap + k0);
        float4 wv = *(const float4*)(Wp + (size_t)k0 * N);
        As[lak + 0][lam] = av.x;
        As[lak + 1][lam] = av.y;
        As[lak + 2][lam] = av.z;
        As[lak + 3][lam] = av.w;
        *(float4*)&Ws[lwk][lwn] = wv;
        __syncthreads();
#pragma unroll
        for (int kk = 0; kk < 16; kk++) {
            float4 a4 = *(const float4*)&As[kk][ty << 2];
            float4 b4 = *(const float4*)&Ws[kk][tx << 2];
            float a[4] = {a4.x, a4.y, a4.z, a4.w};
            float b[4] = {b4.x, b4.y, b4.z, b4.w};
#pragma unroll
            for (int i = 0; i < 4; i++)
#pragma unroll
                for (int j = 0; j < 4; j++) acc[i][j] = fmaf(a[i], b[j], acc[i][j]);
        }
        __syncthreads();
    }

    const int n = n0 + (tx << 2);
    float4 bv = *(const float4*)(bias + n);
    float bb[4] = {bv.x, bv.y, bv.z, bv.w};
#pragma unroll
    for (int i = 0; i < 4; i++) {
        const int m = m0 + (ty << 2) + i;
        float o[4];
#pragma unroll
        for (int j = 0; j < 4; j++) o[j] = acc[i][j] + bb[j];
        if (EPI == 1) {
            float4 rv = *(const float4*)(res + (size_t)m * N + n);
            o[0] += rv.x; o[1] += rv.y; o[2] += rv.z; o[3] += rv.w;
        }
        if (EPI == 2) {
#pragma unroll
            for (int j = 0; j < 4; j++)
                o[j] = 0.5f * o[j] * (1.0f + erff(o[j] * 0.7071067811865475f));
        }
        float4 ov = make_float4(o[0], o[1], o[2], o[3]);
        *(float4*)(C + (size_t)m * N + n) = ov;
    }
}

// ---------------------------------------------------------------------------
// scores[b,h,q,k] = dot(Q[b,q,h,:], K[b,k,h,:]) / scale(b,q,k) + pb[h,q,k]
//                   + mask[b,k]
// One 64x64 tile of (q,k) per block, full DH=64 in smem (transposed: [d][row]).
// ---------------------------------------------------------------------------
__global__ void __launch_bounds__(256) scores_kernel(
    const float* __restrict__ Q, const float* __restrict__ Kt,
    const int* __restrict__ ts, const float* __restrict__ pb,
    const float* __restrict__ mask, float* __restrict__ Sc)
{
    __shared__ __align__(16) float Qs[64][68];
    __shared__ __align__(16) float Ks[64][68];
    const int tid = threadIdx.x;
    const int bh = blockIdx.z, b = bh >> 3, h = bh & 7;
    const int q0 = blockIdx.y << 6, k0 = blockIdx.x << 6;
    const int row = tid >> 2, dg = (tid & 3) << 4;
    const float* qp = Q + (size_t)(b * Sn + q0 + row) * Hn + h * DHn + dg;
    const float* kp = Kt + (size_t)(b * Sn + k0 + row) * Hn + h * DHn + dg;
#pragma unroll
    for (int c = 0; c < 4; c++) {
        const int d = dg + (c << 2);
        float4 v = *(const float4*)(qp + (c << 2));
        Qs[d + 0][row] = v.x; Qs[d + 1][row] = v.y;
        Qs[d + 2][row] = v.z; Qs[d + 3][row] = v.w;
        float4 w = *(const float4*)(kp + (c << 2));
        Ks[d + 0][row] = w.x; Ks[d + 1][row] = w.y;
        Ks[d + 2][row] = w.z; Ks[d + 3][row] = w.w;
    }
    __syncthreads();

    const int tx = tid & 15, ty = tid >> 4;
    float acc[4][4] = {};
#pragma unroll 16
    for (int d = 0; d < 64; d++) {
        float4 a4 = *(const float4*)&Qs[d][ty << 2];
        float4 b4 = *(const float4*)&Ks[d][tx << 2];
        float a[4] = {a4.x, a4.y, a4.z, a4.w};
        float b[4] = {b4.x, b4.y, b4.z, b4.w};
#pragma unroll
        for (int i = 0; i < 4; i++)
#pragma unroll
            for (int j = 0; j < 4; j++) acc[i][j] = fmaf(a[i], b[j], acc[i][j]);
    }

    int tq[4], tk[4];
    float mk[4];
#pragma unroll
    for (int i = 0; i < 4; i++) tq[i] = ts[b * Sn + q0 + (ty << 2) + i];
#pragma unroll
    for (int j = 0; j < 4; j++) {
        tk[j] = ts[b * Sn + k0 + (tx << 2) + j];
        mk[j] = mask[b * Sn + k0 + (tx << 2) + j];
    }
#pragma unroll
    for (int i = 0; i < 4; i++) {
        const int q = q0 + (ty << 2) + i;
        float4 pbv = *(const float4*)(pb + ((size_t)h * Sn + q) * Sn + k0 + (tx << 2));
        float pbb[4] = {pbv.x, pbv.y, pbv.z, pbv.w};
        float o[4];
#pragma unroll
        for (int j = 0; j < 4; j++) {
            float lag = (float)(tq[i] - tk[j]) * (1.0f / 60000.0f);
            float sc = 9.0f - 1.0f / (fmaxf(lag, 0.0f) + 1.0f);
            o[j] = acc[i][j] / sc + pbb[j] + mk[j];
        }
        float4 ov = make_float4(o[0], o[1], o[2], o[3]);
        *(float4*)(Sc + ((size_t)bh * Sn + q) * Sn + k0 + (tx << 2)) = ov;
    }
}

// ---------------------------------------------------------------------------
// Row softmax over last axis (Sn = 2048), in place. One block per row.
// ---------------------------------------------------------------------------
__global__ void __launch_bounds__(256) softmax_kernel(float* __restrict__ Sc)
{
    const size_t base = (size_t)blockIdx.x * Sn;
    const int tid = threadIdx.x;
    __shared__ float sh[8], sh2[8];
    float v[8];
    float mx = -3.4e38f;
#pragma unroll
    for (int i = 0; i < 8; i++) {
        v[i] = Sc[base + tid + (i << 8)];
        mx = fmaxf(mx, v[i]);
    }
    for (int o = 16; o; o >>= 1) mx = fmaxf(mx, __shfl_xor_sync(0xffffffffu, mx, o));
    if ((tid & 31) == 0) sh[tid >> 5] = mx;
    __syncthreads();
    mx = sh[0];
#pragma unroll
    for (int i = 1; i < 8; i++) mx = fmaxf(mx, sh[i]);

    float sum = 0.0f;
#pragma unroll
    for (int i = 0; i < 8; i++) { v[i] = expf(v[i] - mx); sum += v[i]; }
    for (int o = 16; o; o >>= 1) sum += __shfl_xor_sync(0xffffffffu, sum, o);
    if ((tid & 31) == 0) sh2[tid >> 5] = sum;
    __syncthreads();
    sum = 0.0f;
#pragma unroll
    for (int i = 0; i < 8; i++) sum += sh2[i];
    const float inv = 1.0f / sum;
#pragma unroll
    for (int i = 0; i < 8; i++) Sc[base + tid + (i << 8)] = v[i] * inv;
}

// ---------------------------------------------------------------------------
// ctx[b,q,h,d] = sum_k P[b,h,q,k] * V[b,k,h,d].  Per (b,h): M=2048,N=64,K=2048.
// 64(q) x 64(d) tile per block, K chunks of 32.
// ---------------------------------------------------------------------------
__global__ void __launch_bounds__(256) ctx_kernel(
    const float* __restrict__ P, const float* __restrict__ V, float* __restrict__ C)
{
    __shared__ __align__(16) float Ps[32][68];
    __shared__ __align__(16) float Vs[32][68];
    const int tid = threadIdx.x;
    const int bh = blockIdx.y, b = bh >> 3, h = bh & 7;
    const int q0 = blockIdx.x << 6;
    const int tx = tid & 15, ty = tid >> 4;
    const int lq = tid >> 2, lk = (tid & 3) << 3;
    const int vk = tid >> 3, vd = (tid & 7) << 3;
    const float* Pbase = P + ((size_t)bh * Sn + q0 + lq) * Sn + lk;
    const float* Vbase = V + (size_t)(b * Sn + vk) * Hn + h * DHn + vd;

    float acc[4][4] = {};
    for (int kc = 0; kc < Sn; kc += 32) {
        float4 p0 = *(const float4*)(Pbase + kc);
        float4 p1 = *(const float4*)(Pbase + kc + 4);
        Ps[lk + 0][lq] = p0.x; Ps[lk + 1][lq] = p0.y;
        Ps[lk + 2][lq] = p0.z; Ps[lk + 3][lq] = p0.w;
        Ps[lk + 4][lq] = p1.x; Ps[lk + 5][lq] = p1.y;
        Ps[lk + 6][lq] = p1.z; Ps[lk + 7][lq] = p1.w;
        const float* vp = Vbase + (size_t)kc * Hn;
        *(float4*)&Vs[vk][vd] = *(const float4*)vp;
        *(float4*)&Vs[vk][vd + 4] = *(const float4*)(vp + 4);
        __syncthreads();
#pragma unroll
        for (int kk = 0; kk < 32; kk++) {
            float4 a4 = *(const float4*)&Ps[kk][ty << 2];
            float4 b4 = *(const float4*)&Vs[kk][tx << 2];
            float a[4] = {a4.x, a4.y, a4.z, a4.w};
            float bb[4] = {b4.x, b4.y, b4.z, b4.w};
#pragma unroll
            for (int i = 0; i < 4; i++)
#pragma unroll
                for (int j = 0; j < 4; j++) acc[i][j] = fmaf(a[i], bb[j], acc[i][j]);
        }
        __syncthreads();
    }
#pragma unroll
    for (int i = 0; i < 4; i++) {
        const int q = q0 + (ty << 2) + i;
        float4 ov = make_float4(acc[i][0], acc[i][1], acc[i][2], acc[i][3]);
        *(float4*)(C + (size_t)(b * Sn + q) * Hn + h * DHn + (tx << 2)) = ov;
    }
}

// ---------------------------------------------------------------------------
// LayerNorm over H=512, one block (256 thr) per row. in may equal out.
// ---------------------------------------------------------------------------
__global__ void __launch_bounds__(256) ln_kernel(
    const float* __restrict__ in, const float* __restrict__ g,
    const float* __restrict__ bta, float* __restrict__ out)
{
    const size_t base = (size_t)blockIdx.x * Hn;
    const int tid = threadIdx.x;
    __shared__ float sh[8], sh2[8];
    float x0 = in[base + tid], x1 = in[base + tid + 256];
    float s = x0 + x1;
    for (int o = 16; o; o >>= 1) s += __shfl_xor_sync(0xffffffffu, s, o);
    if ((tid & 31) == 0) sh[tid >> 5] = s;
    __syncthreads();
    s = 0.0f;
#pragma unroll
    for (int i = 0; i < 8; i++) s += sh[i];
    const float mean = s * (1.0f / Hn);
    const float d0 = x0 - mean, d1 = x1 - mean;
    float vv = d0 * d0 + d1 * d1;
    for (int o = 16; o; o >>= 1) vv += __shfl_xor_sync(0xffffffffu, vv, o);
    if ((tid & 31) == 0) sh2[tid >> 5] = vv;
    __syncthreads();
    vv = 0.0f;
#pragma unroll
    for (int i = 0; i < 8; i++) vv += sh2[i];
    const float inv = rsqrtf(vv * (1.0f / Hn) + 1e-12f);
    out[base + tid] = d0 * inv * g[tid] + bta[tid];
    out[base + tid + 256] = d1 * inv * g[tid + 256] + bta[tid + 256];
}

// ---------------------------------------------------------------------------
extern "C" void kernel_launch(void* const* d_in, const int* in_sizes, int n_in,
                              void* d_out, int out_size)
{
    (void)in_sizes; (void)n_in; (void)out_size;
    const float* qs   = (const float*)d_in[0];
    const float* mask = (const float*)d_in[1];
    const float* pb   = (const float*)d_in[2];
    const int*   ts   = (const int*)d_in[3];
    const float* wq  = (const float*)d_in[4];  const float* bq  = (const float*)d_in[5];
    const float* wk  = (const float*)d_in[6];  const float* bk  = (const float*)d_in[7];
    const float* wv  = (const float*)d_in[8];  const float* bv  = (const float*)d_in[9];
    const float* wo  = (const float*)d_in[10]; const float* bo  = (const float*)d_in[11];
    const float* l1g = (const float*)d_in[12]; const float* l1b = (const float*)d_in[13];
    const float* wi  = (const float*)d_in[14]; const float* bi  = (const float*)d_in[15];
    const float* wo2 = (const float*)d_in[16]; const float* bo2 = (const float*)d_in[17];
    const float* l2g = (const float*)d_in[18]; const float* l2b = (const float*)d_in[19];

    float *x, *q, *k, *v, *ctx, *attn, *ffn, *sc;
    cudaGetSymbolAddress((void**)&x,    g_x);
    cudaGetSymbolAddress((void**)&q,    g_q);
    cudaGetSymbolAddress((void**)&k,    g_k);
    cudaGetSymbolAddress((void**)&v,    g_v);
    cudaGetSymbolAddress((void**)&ctx,  g_ctx);
    cudaGetSymbolAddress((void**)&attn, g_attn);
    cudaGetSymbolAddress((void**)&ffn,  g_ffn);
    cudaGetSymbolAddress((void**)&sc,   g_sc);

    cudaMemcpyAsync(x, qs, sizeof(float) * (size_t)Mn * Hn,
                    cudaMemcpyDeviceToDevice, 0);

    dim3 gproj(Hn / 64, Mn / 64);          // (8, 128)
    dim3 gff(Fn / 64, Mn / 64);            // (32, 128)
    dim3 gsc(Sn / 64, Sn / 64, Bn * NHn);  // (32, 32, 32)
    dim3 gctx(Sn / 64, Bn * NHn);          // (32, 32)

    for (int l = 0; l < Ln; l++) {
        const size_t wOff  = (size_t)l * Hn * Hn;
        const size_t bOff  = (size_t)l * Hn;
        const size_t wiOff = (size_t)l * Hn * Fn;
        const size_t biOff = (size_t)l * Fn;

        gemm_kernel<0><<<gproj, 256>>>(x, wq + wOff, bq + bOff, nullptr, q, Hn, Hn);
        gemm_kernel<0><<<gproj, 256>>>(x, wk + wOff, bk + bOff, nullptr, k, Hn, Hn);
        gemm_kernel<0><<<gproj, 256>>>(x, wv + wOff, bv + bOff, nullptr, v, Hn, Hn);

        scores_kernel<<<gsc, 256>>>(q, k, ts, pb, mask, sc);
        softmax_kernel<<<Bn * NHn * Sn, 256>>>(sc);
        ctx_kernel<<<gctx, 256>>>(sc, v, ctx);

        gemm_kernel<1><<<gproj, 256>>>(ctx, wo + wOff, bo + bOff, x, attn, Hn, Hn);
        ln_kernel<<<Mn, 256>>>(attn, l1g + bOff, l1b + bOff, attn);

        gemm_kernel<2><<<gff, 256>>>(attn, wi + wiOff, bi + biOff, nullptr, ffn, Hn, Fn);
        gemm_kernel<1><<<gproj, 256>>>(ffn, wo2 + wiOff, bo2 + bOff, attn, x, Fn, Hn);

        float* lnout = (l == Ln - 1) ? (float*)d_out : x;
        ln_kernel<<<Mn, 256>>>(x, l2g + bOff, l2b + bOff, lnout);
    }
}

// round 4
// speedup vs baseline: 1.4914x; 1.4914x over previous
#include <cuda_runtime.h>
#include <cuda_bf16.h>
#include <math.h>
#include <stdint.h>

// Problem constants
#define Bn 4
#define Sn 2048
#define Hn 512
#define NHn 8
#define DHn 64
#define Fn 2048
#define Ln 4
#define Mn (Bn * Sn)  // 8192

// ---------------- scratch (device globals; no allocation allowed) ----------
__device__ float g_x[Mn * Hn];
__device__ float g_q[Mn * Hn];
__device__ float g_k[Mn * Hn];
__device__ float g_v[Mn * Hn];
__device__ float g_ctx[Mn * Hn];
__device__ float g_attn[Mn * Hn];
__device__ float g_ffn[Mn * Fn];
__device__ float g_sc[(size_t)Bn * NHn * Sn * Sn];  // 512 MB scores/probs

// bf16 hi/lo split buffers
__device__ __nv_bfloat16 g_wqh[Ln * Hn * Hn], g_wql[Ln * Hn * Hn];
__device__ __nv_bfloat16 g_wkh[Ln * Hn * Hn], g_wkl[Ln * Hn * Hn];
__device__ __nv_bfloat16 g_wvh[Ln * Hn * Hn], g_wvl[Ln * Hn * Hn];
__device__ __nv_bfloat16 g_woh[Ln * Hn * Hn], g_wol[Ln * Hn * Hn];
__device__ __nv_bfloat16 g_wih[Ln * Hn * Fn], g_wil[Ln * Hn * Fn];
__device__ __nv_bfloat16 g_w2h[Ln * Fn * Hn], g_w2l[Ln * Fn * Hn];
__device__ __nv_bfloat16 g_ah[(size_t)Mn * Fn], g_al[(size_t)Mn * Fn];

// ---------------- helpers ---------------------------------------------------
__device__ __forceinline__ uint32_t cvta_smem(const void* p) {
    uint32_t a;
    asm("{ .reg .u64 t; cvta.to.shared.u64 t, %1; cvt.u32.u64 %0, t; }"
        : "=r"(a) : "l"(p));
    return a;
}

#define CP16(dst, src) \
    asm volatile("cp.async.cg.shared.global [%0], [%1], 16;" :: "r"(dst), "l"(src))
#define CP_COMMIT() asm volatile("cp.async.commit_group;" ::: "memory")
#define CP_WAIT0()  asm volatile("cp.async.wait_group 0;" ::: "memory")

#define LDSM4(r, addr)                                                          \
    asm volatile("ldmatrix.sync.aligned.m8n8.x4.shared.b16 {%0,%1,%2,%3}, [%4];"\
        : "=r"((r)[0]), "=r"((r)[1]), "=r"((r)[2]), "=r"((r)[3]) : "r"(addr))
#define LDSM4T(r01, r23, addr)                                                  \
    asm volatile("ldmatrix.sync.aligned.m8n8.x4.trans.shared.b16 {%0,%1,%2,%3}, [%4];"\
        : "=r"((r01)[0]), "=r"((r01)[1]), "=r"((r23)[0]), "=r"((r23)[1]) : "r"(addr))

__device__ __forceinline__ void mma16816(float* c, const uint32_t* a, const uint32_t* b) {
    asm volatile(
        "mma.sync.aligned.m16n8k16.row.col.f32.bf16.bf16.f32 "
        "{%0,%1,%2,%3}, {%4,%5,%6,%7}, {%8,%9}, {%0,%1,%2,%3};"
        : "+f"(c[0]), "+f"(c[1]), "+f"(c[2]), "+f"(c[3])
        : "r"(a[0]), "r"(a[1]), "r"(a[2]), "r"(a[3]), "r"(b[0]), "r"(b[1]));
}

// smem stage layout (padded rows: A 80B/row of 32 bf16, B 272B/row of 128 bf16)
#define OFF_AH 0
#define OFF_AL 10240
#define OFF_BH 20480
#define OFF_BL 29184
#define STAGE_BYTES 37888   // x2 stages = 75776

// ---------------------------------------------------------------------------
// Split fp32 -> bf16 hi + bf16 lo residual. n must be a multiple of 8.
// ---------------------------------------------------------------------------
__global__ void __launch_bounds__(256) split_kernel(
    const float* __restrict__ x, __nv_bfloat16* __restrict__ h,
    __nv_bfloat16* __restrict__ l, int n)
{
    int i = (blockIdx.x * 256 + threadIdx.x) * 8;
    if (i >= n) return;
    float4 a = *(const float4*)(x + i);
    float4 b = *(const float4*)(x + i + 4);
    float v[8] = {a.x, a.y, a.z, a.w, b.x, b.y, b.z, b.w};
    __align__(16) __nv_bfloat16 hh[8];
    __align__(16) __nv_bfloat16 ll[8];
#pragma unroll
    for (int j = 0; j < 8; j++) {
        hh[j] = __float2bfloat16(v[j]);
        ll[j] = __float2bfloat16(v[j] - __bfloat162float(hh[j]));
    }
    *(uint4*)(h + i) = *(const uint4*)hh;
    *(uint4*)(l + i) = *(const uint4*)ll;
}

// ---------------------------------------------------------------------------
// HMMA split-bf16 GEMM: C[M,N] = A[M,K]*W[K,N] (+bias / +res / GELU)
// CTA tile 128x128, BK=32, 8 warps (2x4), warp tile 64x32, double-buffered
// cp.async. 3 passes: Ah*Bh + Ah*Bl + Al*Bh accumulated in fp32.
// EPI: 0 = bias, 1 = bias+res, 2 = bias then exact GELU.
// ---------------------------------------------------------------------------
template <int EPI>
__global__ void __launch_bounds__(256) hmma_gemm(
    const __nv_bfloat16* __restrict__ Ahp, const __nv_bfloat16* __restrict__ Alp,
    const __nv_bfloat16* __restrict__ Bhp, const __nv_bfloat16* __restrict__ Blp,
    const float* __restrict__ bias, const float* __restrict__ res,
    float* __restrict__ C, int K, int N)
{
    extern __shared__ char smem[];
    const uint32_t sb = cvta_smem(smem);
    const int tid = threadIdx.x, lane = tid & 31, warp = tid >> 5;
    const int m0 = blockIdx.y << 7, n0 = blockIdx.x << 7;
    const int wm0 = (warp >> 2) << 6, wn0 = (warp & 3) << 5;

    const int ar = tid >> 2, ac = tid & 3;   // A chunks: rows ar, ar+64
    const int br = tid >> 4, bc = tid & 15;  // B chunks: k rows br, br+16

    auto load_stage = [&](int st, int kc) {
        const int k0 = kc << 5;
        const uint32_t s = sb + st * STAGE_BYTES;
        const size_t aoff0 = (size_t)(m0 + ar) * K + k0 + ac * 8;
        const size_t aoff1 = (size_t)(m0 + ar + 64) * K + k0 + ac * 8;
        CP16(s + OFF_AH + ar * 80 + ac * 16, Ahp + aoff0);
        CP16(s + OFF_AH + (ar + 64) * 80 + ac * 16, Ahp + aoff1);
        CP16(s + OFF_AL + ar * 80 + ac * 16, Alp + aoff0);
        CP16(s + OFF_AL + (ar + 64) * 80 + ac * 16, Alp + aoff1);
        const size_t boff0 = (size_t)(k0 + br) * N + n0 + bc * 8;
        const size_t boff1 = (size_t)(k0 + br + 16) * N + n0 + bc * 8;
        CP16(s + OFF_BH + br * 272 + bc * 16, Bhp + boff0);
        CP16(s + OFF_BH + (br + 16) * 272 + bc * 16, Bhp + boff1);
        CP16(s + OFF_BL + br * 272 + bc * 16, Blp + boff0);
        CP16(s + OFF_BL + (br + 16) * 272 + bc * 16, Blp + boff1);
        CP_COMMIT();
    };

    float acc[4][4][4];
#pragma unroll
    for (int i = 0; i < 4; i++)
#pragma unroll
        for (int j = 0; j < 4; j++)
#pragma unroll
            for (int r = 0; r < 4; r++) acc[i][j][r] = 0.0f;

    const int nch = K >> 5;
    load_stage(0, 0);

    for (int kc = 0; kc < nch; kc++) {
        const int cur = kc & 1;
        CP_WAIT0();
        __syncthreads();
        if (kc + 1 < nch) load_stage(cur ^ 1, kc + 1);

        const uint32_t s = sb + cur * STAGE_BYTES;
#pragma unroll
        for (int ks = 0; ks < 2; ks++) {
            uint32_t a[2][4][4];
            uint32_t b[2][4][2];
            const uint32_t aoff =
                (wm0 + (lane & 15)) * 80 + ((ks << 4) + ((lane >> 4) << 3)) * 2;
#pragma unroll
            for (int v = 0; v < 2; v++) {
                const uint32_t base = s + (v ? OFF_AL : OFF_AH) + aoff;
#pragma unroll
                for (int mt = 0; mt < 4; mt++) LDSM4(a[v][mt], base + mt * (16 * 80));
            }
            const uint32_t boff =
                ((ks << 4) + (lane & 15)) * 272 + (wn0 + ((lane >> 4) << 3)) * 2;
#pragma unroll
            for (int v = 0; v < 2; v++) {
                const uint32_t base = s + (v ? OFF_BL : OFF_BH) + boff;
                LDSM4T(b[v][0], b[v][1], base);
                LDSM4T(b[v][2], b[v][3], base + 32);
            }
            // pass 1: Ah * Bh
#pragma unroll
            for (int mt = 0; mt < 4; mt++)
#pragma unroll
                for (int nt = 0; nt < 4; nt++) mma16816(acc[mt][nt], a[0][mt], b[0][nt]);
            // pass 2: Ah * Bl
#pragma unroll
            for (int mt = 0; mt < 4; mt++)
#pragma unroll
                for (int nt = 0; nt < 4; nt++) mma16816(acc[mt][nt], a[0][mt], b[1][nt]);
            // pass 3: Al * Bh
#pragma unroll
            for (int mt = 0; mt < 4; mt++)
#pragma unroll
                for (int nt = 0; nt < 4; nt++) mma16816(acc[mt][nt], a[1][mt], b[0][nt]);
        }
    }

    // Epilogue: c0,c1 -> (row, col..col+1), c2,c3 -> (row+8, col..col+1)
#pragma unroll
    for (int mt = 0; mt < 4; mt++) {
        const int m = m0 + wm0 + mt * 16 + (lane >> 2);
#pragma unroll
        for (int nt = 0; nt < 4; nt++) {
            const int n = n0 + wn0 + nt * 8 + (lane & 3) * 2;
            float2 bv = *(const float2*)(bias + n);
            float o0 = acc[mt][nt][0] + bv.x;
            float o1 = acc[mt][nt][1] + bv.y;
            float o2 = acc[mt][nt][2] + bv.x;
            float o3 = acc[mt][nt][3] + bv.y;
            if (EPI == 1) {
                float2 r0 = *(const float2*)(res + (size_t)m * N + n);
                float2 r1 = *(const float2*)(res + (size_t)(m + 8) * N + n);
                o0 += r0.x; o1 += r0.y; o2 += r1.x; o3 += r1.y;
            }
            if (EPI == 2) {
                o0 = 0.5f * o0 * (1.0f + erff(o0 * 0.7071067811865475f));
                o1 = 0.5f * o1 * (1.0f + erff(o1 * 0.7071067811865475f));
                o2 = 0.5f * o2 * (1.0f + erff(o2 * 0.7071067811865475f));
                o3 = 0.5f * o3 * (1.0f + erff(o3 * 0.7071067811865475f));
            }
            *(float2*)(C + (size_t)m * N + n) = make_float2(o0, o1);
            *(float2*)(C + (size_t)(m + 8) * N + n) = make_float2(o2, o3);
        }
    }
}

// ---------------------------------------------------------------------------
// scores[b,h,q,k] = dot(Q,K)/scale + pb + mask   (fp32)
// ---------------------------------------------------------------------------
__global__ void __launch_bounds__(256) scores_kernel(
    const float* __restrict__ Q, const float* __restrict__ Kt,
    const int* __restrict__ ts, const float* __restrict__ pb,
    const float* __restrict__ mask, float* __restrict__ Sc)
{
    __shared__ __align__(16) float Qs[64][68];
    __shared__ __align__(16) float Ks[64][68];
    const int tid = threadIdx.x;
    const int bh = blockIdx.z, b = bh >> 3, h = bh & 7;
    const int q0 = blockIdx.y << 6, k0 = blockIdx.x << 6;
    const int row = tid >> 2, dg = (tid & 3) << 4;
    const float* qp = Q + (size_t)(b * Sn + q0 + row) * Hn + h * DHn + dg;
    const float* kp = Kt + (size_t)(b * Sn + k0 + row) * Hn + h * DHn + dg;
#pragma unroll
    for (int c = 0; c < 4; c++) {
        const int d = dg + (c << 2);
        float4 v = *(const float4*)(qp + (c << 2));
        Qs[d + 0][row] = v.x; Qs[d + 1][row] = v.y;
        Qs[d + 2][row] = v.z; Qs[d + 3][row] = v.w;
        float4 w = *(const float4*)(kp + (c << 2));
        Ks[d + 0][row] = w.x; Ks[d + 1][row] = w.y;
        Ks[d + 2][row] = w.z; Ks[d + 3][row] = w.w;
    }
    __syncthreads();

    const int tx = tid & 15, ty = tid >> 4;
    float acc[4][4] = {};
#pragma unroll 16
    for (int d = 0; d < 64; d++) {
        float4 a4 = *(const float4*)&Qs[d][ty << 2];
        float4 b4 = *(const float4*)&Ks[d][tx << 2];
        float a[4] = {a4.x, a4.y, a4.z, a4.w};
        float bb[4] = {b4.x, b4.y, b4.z, b4.w};
#pragma unroll
        for (int i = 0; i < 4; i++)
#pragma unroll
            for (int j = 0; j < 4; j++) acc[i][j] = fmaf(a[i], bb[j], acc[i][j]);
    }

    int tq[4], tk[4];
    float mk[4];
#pragma unroll
    for (int i = 0; i < 4; i++) tq[i] = ts[b * Sn + q0 + (ty << 2) + i];
#pragma unroll
    for (int j = 0; j < 4; j++) {
        tk[j] = ts[b * Sn + k0 + (tx << 2) + j];
        mk[j] = mask[b * Sn + k0 + (tx << 2) + j];
    }
#pragma unroll
    for (int i = 0; i < 4; i++) {
        const int q = q0 + (ty << 2) + i;
        float4 pbv = *(const float4*)(pb + ((size_t)h * Sn + q) * Sn + k0 + (tx << 2));
        float pbb[4] = {pbv.x, pbv.y, pbv.z, pbv.w};
        float o[4];
#pragma unroll
        for (int j = 0; j < 4; j++) {
            float lag = (float)(tq[i] - tk[j]) * (1.0f / 60000.0f);
            float sc = 9.0f - 1.0f / (fmaxf(lag, 0.0f) + 1.0f);
            o[j] = acc[i][j] / sc + pbb[j] + mk[j];
        }
        *(float4*)(Sc + ((size_t)bh * Sn + q) * Sn + k0 + (tx << 2)) =
            make_float4(o[0], o[1], o[2], o[3]);
    }
}

__global__ void __launch_bounds__(256) softmax_kernel(float* __restrict__ Sc)
{
    const size_t base = (size_t)blockIdx.x * Sn;
    const int tid = threadIdx.x;
    __shared__ float sh[8], sh2[8];
    float v[8];
    float mx = -3.4e38f;
#pragma unroll
    for (int i = 0; i < 8; i++) {
        v[i] = Sc[base + tid + (i << 8)];
        mx = fmaxf(mx, v[i]);
    }
    for (int o = 16; o; o >>= 1) mx = fmaxf(mx, __shfl_xor_sync(0xffffffffu, mx, o));
    if ((tid & 31) == 0) sh[tid >> 5] = mx;
    __syncthreads();
    mx = sh[0];
#pragma unroll
    for (int i = 1; i < 8; i++) mx = fmaxf(mx, sh[i]);

    float sum = 0.0f;
#pragma unroll
    for (int i = 0; i < 8; i++) { v[i] = expf(v[i] - mx); sum += v[i]; }
    for (int o = 16; o; o >>= 1) sum += __shfl_xor_sync(0xffffffffu, sum, o);
    if ((tid & 31) == 0) sh2[tid >> 5] = sum;
    __syncthreads();
    sum = 0.0f;
#pragma unroll
    for (int i = 0; i < 8; i++) sum += sh2[i];
    const float inv = 1.0f / sum;
#pragma unroll
    for (int i = 0; i < 8; i++) Sc[base + tid + (i << 8)] = v[i] * inv;
}

__global__ void __launch_bounds__(256) ctx_kernel(
    const float* __restrict__ P, const float* __restrict__ V, float* __restrict__ C)
{
    __shared__ __align__(16) float Ps[32][68];
    __shared__ __align__(16) float Vs[32][68];
    const int tid = threadIdx.x;
    const int bh = blockIdx.y, b = bh >> 3, h = bh & 7;
    const int q0 = blockIdx.x << 6;
    const int tx = tid & 15, ty = tid >> 4;
    const int lq = tid >> 2, lk = (tid & 3) << 3;
    const int vk = tid >> 3, vd = (tid & 7) << 3;
    const float* Pbase = P + ((size_t)bh * Sn + q0 + lq) * Sn + lk;
    const float* Vbase = V + (size_t)(b * Sn + vk) * Hn + h * DHn + vd;

    float acc[4][4] = {};
    for (int kc = 0; kc < Sn; kc += 32) {
        float4 p0 = *(const float4*)(Pbase + kc);
        float4 p1 = *(const float4*)(Pbase + kc + 4);
        Ps[lk + 0][lq] = p0.x; Ps[lk + 1][lq] = p0.y;
        Ps[lk + 2][lq] = p0.z; Ps[lk + 3][lq] = p0.w;
        Ps[lk + 4][lq] = p1.x; Ps[lk + 5][lq] = p1.y;
        Ps[lk + 6][lq] = p1.z; Ps[lk + 7][lq] = p1.w;
        const float* vp = Vbase + (size_t)kc * Hn;
        *(float4*)&Vs[vk][vd] = *(const float4*)vp;
        *(float4*)&Vs[vk][vd + 4] = *(const float4*)(vp + 4);
        __syncthreads();
#pragma unroll
        for (int kk = 0; kk < 32; kk++) {
            float4 a4 = *(const float4*)&Ps[kk][ty << 2];
            float4 b4 = *(const float4*)&Vs[kk][tx << 2];
            float a[4] = {a4.x, a4.y, a4.z, a4.w};
            float bb[4] = {b4.x, b4.y, b4.z, b4.w};
#pragma unroll
            for (int i = 0; i < 4; i++)
#pragma unroll
                for (int j = 0; j < 4; j++) acc[i][j] = fmaf(a[i], bb[j], acc[i][j]);
        }
        __syncthreads();
    }
#pragma unroll
    for (int i = 0; i < 4; i++) {
        const int q = q0 + (ty << 2) + i;
        *(float4*)(C + (size_t)(b * Sn + q) * Hn + h * DHn + (tx << 2)) =
            make_float4(acc[i][0], acc[i][1], acc[i][2], acc[i][3]);
    }
}

__global__ void __launch_bounds__(256) ln_kernel(
    const float* __restrict__ in, const float* __restrict__ g,
    const float* __restrict__ bta, float* __restrict__ out)
{
    const size_t base = (size_t)blockIdx.x * Hn;
    const int tid = threadIdx.x;
    __shared__ float sh[8], sh2[8];
    float x0 = in[base + tid], x1 = in[base + tid + 256];
    float s = x0 + x1;
    for (int o = 16; o; o >>= 1) s += __shfl_xor_sync(0xffffffffu, s, o);
    if ((tid & 31) == 0) sh[tid >> 5] = s;
    __syncthreads();
    s = 0.0f;
#pragma unroll
    for (int i = 0; i < 8; i++) s += sh[i];
    const float mean = s * (1.0f / Hn);
    const float d0 = x0 - mean, d1 = x1 - mean;
    float vv = d0 * d0 + d1 * d1;
    for (int o = 16; o; o >>= 1) vv += __shfl_xor_sync(0xffffffffu, vv, o);
    if ((tid & 31) == 0) sh2[tid >> 5] = vv;
    __syncthreads();
    vv = 0.0f;
#pragma unroll
    for (int i = 0; i < 8; i++) vv += sh2[i];
    const float inv = rsqrtf(vv * (1.0f / Hn) + 1e-12f);
    out[base + tid] = d0 * inv * g[tid] + bta[tid];
    out[base + tid + 256] = d1 * inv * g[tid + 256] + bta[tid + 256];
}

// ---------------------------------------------------------------------------
extern "C" void kernel_launch(void* const* d_in, const int* in_sizes, int n_in,
                              void* d_out, int out_size)
{
    (void)in_sizes; (void)n_in; (void)out_size;
    const float* qs   = (const float*)d_in[0];
    const float* mask = (const float*)d_in[1];
    const float* pb   = (const float*)d_in[2];
    const int*   ts   = (const int*)d_in[3];
    const float* wq  = (const float*)d_in[4];  const float* bq  = (const float*)d_in[5];
    const float* wk  = (const float*)d_in[6];  const float* bk  = (const float*)d_in[7];
    const float* wv  = (const float*)d_in[8];  const float* bv  = (const float*)d_in[9];
    const float* wo  = (const float*)d_in[10]; const float* bo  = (const float*)d_in[11];
    const float* l1g = (const float*)d_in[12]; const float* l1b = (const float*)d_in[13];
    const float* wi  = (const float*)d_in[14]; const float* bi  = (const float*)d_in[15];
    const float* wo2 = (const float*)d_in[16]; const float* bo2 = (const float*)d_in[17];
    const float* l2g = (const float*)d_in[18]; const float* l2b = (const float*)d_in[19];

    float *x, *q, *k, *v, *ctx, *attn, *ffn, *sc;
    cudaGetSymbolAddress((void**)&x,    g_x);
    cudaGetSymbolAddress((void**)&q,    g_q);
    cudaGetSymbolAddress((void**)&k,    g_k);
    cudaGetSymbolAddress((void**)&v,    g_v);
    cudaGetSymbolAddress((void**)&ctx,  g_ctx);
    cudaGetSymbolAddress((void**)&attn, g_attn);
    cudaGetSymbolAddress((void**)&ffn,  g_ffn);
    cudaGetSymbolAddress((void**)&sc,   g_sc);

    __nv_bfloat16 *wqh, *wql, *wkh, *wkl, *wvh, *wvl, *woh, *wol;
    __nv_bfloat16 *wih, *wil, *w2h, *w2l, *ah, *al;
    cudaGetSymbolAddress((void**)&wqh, g_wqh); cudaGetSymbolAddress((void**)&wql, g_wql);
    cudaGetSymbolAddress((void**)&wkh, g_wkh); cudaGetSymbolAddress((void**)&wkl, g_wkl);
    cudaGetSymbolAddress((void**)&wvh, g_wvh); cudaGetSymbolAddress((void**)&wvl, g_wvl);
    cudaGetSymbolAddress((void**)&woh, g_woh); cudaGetSymbolAddress((void**)&wol, g_wol);
    cudaGetSymbolAddress((void**)&wih, g_wih); cudaGetSymbolAddress((void**)&wil, g_wil);
    cudaGetSymbolAddress((void**)&w2h, g_w2h); cudaGetSymbolAddress((void**)&w2l, g_w2l);
    cudaGetSymbolAddress((void**)&ah,  g_ah);  cudaGetSymbolAddress((void**)&al,  g_al);

    const int HM_SMEM = 2 * STAGE_BYTES;  // 75776
    cudaFuncSetAttribute(hmma_gemm<0>, cudaFuncAttributeMaxDynamicSharedMemorySize, HM_SMEM);
    cudaFuncSetAttribute(hmma_gemm<1>, cudaFuncAttributeMaxDynamicSharedMemorySize, HM_SMEM);
    cudaFuncSetAttribute(hmma_gemm<2>, cudaFuncAttributeMaxDynamicSharedMemorySize, HM_SMEM);

    // Split all weights (deterministic; runs every call)
    const int WNH = Ln * Hn * Hn, WNF = Ln * Hn * Fn;
    split_kernel<<<WNH / 2048, 256>>>(wq,  wqh, wql, WNH);
    split_kernel<<<WNH / 2048, 256>>>(wk,  wkh, wkl, WNH);
    split_kernel<<<WNH / 2048, 256>>>(wv,  wvh, wvl, WNH);
    split_kernel<<<WNH / 2048, 256>>>(wo,  woh, wol, WNH);
    split_kernel<<<WNF / 2048, 256>>>(wi,  wih, wil, WNF);
    split_kernel<<<WNF / 2048, 256>>>(wo2, w2h, w2l, WNF);

    cudaMemcpyAsync(x, qs, sizeof(float) * (size_t)Mn * Hn,
                    cudaMemcpyDeviceToDevice, 0);

    dim3 gproj(Hn / 128, Mn / 128);        // (4, 64)
    dim3 gff(Fn / 128, Mn / 128);          // (16, 64)
    dim3 gsc(Sn / 64, Sn / 64, Bn * NHn);  // (32, 32, 32)
    dim3 gctx(Sn / 64, Bn * NHn);          // (32, 32)
    const int AH = Mn * Hn, AF = Mn * Fn;

    for (int l = 0; l < Ln; l++) {
        const size_t wOff  = (size_t)l * Hn * Hn;
        const size_t bOff  = (size_t)l * Hn;
        const size_t wiOff = (size_t)l * Hn * Fn;
        const size_t biOff = (size_t)l * Fn;

        split_kernel<<<AH / 2048, 256>>>(x, ah, al, AH);
        hmma_gemm<0><<<gproj, 256, HM_SMEM>>>(ah, al, wqh + wOff, wql + wOff,
                                              bq + bOff, nullptr, q, Hn, Hn);
        hmma_gemm<0><<<gproj, 256, HM_SMEM>>>(ah, al, wkh + wOff, wkl + wOff,
                                              bk + bOff, nullptr, k, Hn, Hn);
        hmma_gemm<0><<<gproj, 256, HM_SMEM>>>(ah, al, wvh + wOff, wvl + wOff,
                                              bv + bOff, nullptr, v, Hn, Hn);

        scores_kernel<<<gsc, 256>>>(q, k, ts, pb, mask, sc);
        softmax_kernel<<<Bn * NHn * Sn, 256>>>(sc);
        ctx_kernel<<<gctx, 256>>>(sc, v, ctx);

        split_kernel<<<AH / 2048, 256>>>(ctx, ah, al, AH);
        hmma_gemm<1><<<gproj, 256, HM_SMEM>>>(ah, al, woh + wOff, wol + wOff,
                                              bo + bOff, x, attn, Hn, Hn);
        ln_kernel<<<Mn, 256>>>(attn, l1g + bOff, l1b + bOff, attn);

        split_kernel<<<AH / 2048, 256>>>(attn, ah, al, AH);
        hmma_gemm<2><<<gff, 256, HM_SMEM>>>(ah, al, wih + wiOff, wil + wiOff,
                                            bi + biOff, nullptr, ffn, Hn, Fn);

        split_kernel<<<AF / 2048, 256>>>(ffn, ah, al, AF);
        hmma_gemm<1><<<gproj, 256, HM_SMEM>>>(ah, al, w2h + wiOff, w2l + wiOff,
                                              bo2 + bOff, attn, x, Fn, Hn);

        float* lnout = (l == Ln - 1) ? (float*)d_out : x;
        ln_kernel<<<Mn, 256>>>(x, l2g + bOff, l2b + bOff, lnout);
    }
}

// round 5
// speedup vs baseline: 1.9570x; 1.3122x over previous
#include <cuda_runtime.h>
#include <cuda_bf16.h>
#include <math.h>
#include <stdint.h>

// Problem constants
#define Bn 4
#define Sn 2048
#define Hn 512
#define NHn 8
#define DHn 64
#define Fn 2048
#define Ln 4
#define Mn (Bn * Sn)  // 8192
#define L2E 1.4426950408889634f

// ---------------- scratch (device globals; no allocation allowed) ----------
__device__ float g_x[Mn * Hn];
__device__ float g_attn[Mn * Hn];

__device__ __nv_bfloat16 g_qh[Mn * Hn], g_ql[Mn * Hn];
__device__ __nv_bfloat16 g_kh[Mn * Hn], g_kl[Mn * Hn];
__device__ __nv_bfloat16 g_vh[Mn * Hn], g_vl[Mn * Hn];
__device__ __nv_bfloat16 g_ch[Mn * Hn], g_cl[Mn * Hn];   // ctx
__device__ __nv_bfloat16 g_xh[Mn * Hn], g_xl[Mn * Hn];
__device__ __nv_bfloat16 g_th[Mn * Hn], g_tl[Mn * Hn];   // attn (post ln1)
__device__ __nv_bfloat16 g_fh[(size_t)Mn * Fn], g_fl[(size_t)Mn * Fn];

// weight hi/lo
__device__ __nv_bfloat16 g_wqh[Ln * Hn * Hn], g_wql[Ln * Hn * Hn];
__device__ __nv_bfloat16 g_wkh[Ln * Hn * Hn], g_wkl[Ln * Hn * Hn];
__device__ __nv_bfloat16 g_wvh[Ln * Hn * Hn], g_wvl[Ln * Hn * Hn];
__device__ __nv_bfloat16 g_woh[Ln * Hn * Hn], g_wol[Ln * Hn * Hn];
__device__ __nv_bfloat16 g_wih[Ln * Hn * Fn], g_wil[Ln * Hn * Fn];
__device__ __nv_bfloat16 g_w2h[Ln * Fn * Hn], g_w2l[Ln * Fn * Hn];

// ---------------- helpers ---------------------------------------------------
__device__ __forceinline__ uint32_t cvta_smem(const void* p) {
    uint32_t a;
    asm("{ .reg .u64 t; cvta.to.shared.u64 t, %1; cvt.u32.u64 %0, t; }"
        : "=r"(a) : "l"(p));
    return a;
}

#define CP16(dst, src) \
    asm volatile("cp.async.cg.shared.global [%0], [%1], 16;" :: "r"(dst), "l"(src))
#define CP_COMMIT() asm volatile("cp.async.commit_group;" ::: "memory")
#define CP_WAIT0()  asm volatile("cp.async.wait_group 0;" ::: "memory")
#define CP_WAIT1()  asm volatile("cp.async.wait_group 1;" ::: "memory")

#define LDSM4(r, addr)                                                          \
    asm volatile("ldmatrix.sync.aligned.m8n8.x4.shared.b16 {%0,%1,%2,%3}, [%4];"\
        : "=r"((r)[0]), "=r"((r)[1]), "=r"((r)[2]), "=r"((r)[3]) : "r"(addr))
#define LDSM4T(r01, r23, addr)                                                  \
    asm volatile("ldmatrix.sync.aligned.m8n8.x4.trans.shared.b16 {%0,%1,%2,%3}, [%4];"\
        : "=r"((r01)[0]), "=r"((r01)[1]), "=r"((r23)[0]), "=r"((r23)[1]) : "r"(addr))

__device__ __forceinline__ void mma16816(float* c, const uint32_t* a, const uint32_t* b) {
    asm volatile(
        "mma.sync.aligned.m16n8k16.row.col.f32.bf16.bf16.f32 "
        "{%0,%1,%2,%3}, {%4,%5,%6,%7}, {%8,%9}, {%0,%1,%2,%3};"
        : "+f"(c[0]), "+f"(c[1]), "+f"(c[2]), "+f"(c[3])
        : "r"(a[0]), "r"(a[1]), "r"(a[2]), "r"(a[3]), "r"(b[0]), "r"(b[1]));
}

__device__ __forceinline__ uint32_t pack_bf16(float lo, float hi) {
    uint32_t r;
    asm("cvt.rn.satfinite.bf16x2.f32 %0, %1, %2;" : "=r"(r) : "f"(hi), "f"(lo));
    return r;
}
__device__ __forceinline__ float bf16lo_f(uint32_t u) { return __uint_as_float(u << 16); }
__device__ __forceinline__ float bf16hi_f(uint32_t u) { return __uint_as_float(u & 0xffff0000u); }
__device__ __forceinline__ float ex2f(float x) {
    float y;
    asm("ex2.approx.ftz.f32 %0, %1;" : "=f"(y) : "f"(x));
    return y;
}

// smem stage layout for dense GEMM (padded rows: A 80B, B 272B)
#define OFF_AH 0
#define OFF_AL 10240
#define OFF_BH 20480
#define OFF_BL 29184
#define STAGE_BYTES 37888   // x2 stages = 75776

// ---------------------------------------------------------------------------
// Split fp32 -> bf16 hi + lo residual. n multiple of 8.
// ---------------------------------------------------------------------------
__global__ void __launch_bounds__(256) split_kernel(
    const float* __restrict__ x, __nv_bfloat16* __restrict__ h,
    __nv_bfloat16* __restrict__ l, int n)
{
    int i = (blockIdx.x * 256 + threadIdx.x) * 8;
    if (i >= n) return;
    float4 a = *(const float4*)(x + i);
    float4 b = *(const float4*)(x + i + 4);
    float v[8] = {a.x, a.y, a.z, a.w, b.x, b.y, b.z, b.w};
    __align__(16) __nv_bfloat16 hh[8];
    __align__(16) __nv_bfloat16 ll[8];
#pragma unroll
    for (int j = 0; j < 8; j++) {
        hh[j] = __float2bfloat16(v[j]);
        ll[j] = __float2bfloat16(v[j] - __bfloat162float(hh[j]));
    }
    *(uint4*)(h + i) = *(const uint4*)hh;
    *(uint4*)(l + i) = *(const uint4*)ll;
}

// ---------------------------------------------------------------------------
// HMMA split-bf16 GEMM. CTA 128x128, BK=32, 8 warps, 3 passes.
// EPI 0: bias -> bf16 hi/lo out.  EPI 1: bias + res -> fp32 out.
// EPI 2: bias + GELU -> bf16 hi/lo out.
// ---------------------------------------------------------------------------
template <int EPI>
__global__ void __launch_bounds__(256) hmma_gemm(
    const __nv_bfloat16* __restrict__ Ahp, const __nv_bfloat16* __restrict__ Alp,
    const __nv_bfloat16* __restrict__ Bhp, const __nv_bfloat16* __restrict__ Blp,
    const float* __restrict__ bias, const float* __restrict__ res,
    float* __restrict__ C, __nv_bfloat16* __restrict__ Cho,
    __nv_bfloat16* __restrict__ Clo, int K, int N)
{
    extern __shared__ char smem[];
    const uint32_t sb = cvta_smem(smem);
    const int tid = threadIdx.x, lane = tid & 31, warp = tid >> 5;
    const int m0 = blockIdx.y << 7, n0 = blockIdx.x << 7;
    const int wm0 = (warp >> 2) << 6, wn0 = (warp & 3) << 5;

    const int ar = tid >> 2, ac = tid & 3;
    const int br = tid >> 4, bc = tid & 15;

    auto load_stage = [&](int st, int kc) {
        const int k0 = kc << 5;
        const uint32_t s = sb + st * STAGE_BYTES;
        const size_t aoff0 = (size_t)(m0 + ar) * K + k0 + ac * 8;
        const size_t aoff1 = (size_t)(m0 + ar + 64) * K + k0 + ac * 8;
        CP16(s + OFF_AH + ar * 80 + ac * 16, Ahp + aoff0);
        CP16(s + OFF_AH + (ar + 64) * 80 + ac * 16, Ahp + aoff1);
        CP16(s + OFF_AL + ar * 80 + ac * 16, Alp + aoff0);
        CP16(s + OFF_AL + (ar + 64) * 80 + ac * 16, Alp + aoff1);
        const size_t boff0 = (size_t)(k0 + br) * N + n0 + bc * 8;
        const size_t boff1 = (size_t)(k0 + br + 16) * N + n0 + bc * 8;
        CP16(s + OFF_BH + br * 272 + bc * 16, Bhp + boff0);
        CP16(s + OFF_BH + (br + 16) * 272 + bc * 16, Bhp + boff1);
        CP16(s + OFF_BL + br * 272 + bc * 16, Blp + boff0);
        CP16(s + OFF_BL + (br + 16) * 272 + bc * 16, Blp + boff1);
        CP_COMMIT();
    };

    float acc[4][4][4];
#pragma unroll
    for (int i = 0; i < 4; i++)
#pragma unroll
        for (int j = 0; j < 4; j++)
#pragma unroll
            for (int r = 0; r < 4; r++) acc[i][j][r] = 0.0f;

    const int nch = K >> 5;
    load_stage(0, 0);

    for (int kc = 0; kc < nch; kc++) {
        const int cur = kc & 1;
        CP_WAIT0();
        __syncthreads();
        if (kc + 1 < nch) load_stage(cur ^ 1, kc + 1);

        const uint32_t s = sb + cur * STAGE_BYTES;
#pragma unroll
        for (int ks = 0; ks < 2; ks++) {
            uint32_t a[2][4][4];
            uint32_t b[2][4][2];
            const uint32_t aoff =
                (wm0 + (lane & 15)) * 80 + ((ks << 4) + ((lane >> 4) << 3)) * 2;
#pragma unroll
            for (int v = 0; v < 2; v++) {
                const uint32_t base = s + (v ? OFF_AL : OFF_AH) + aoff;
#pragma unroll
                for (int mt = 0; mt < 4; mt++) LDSM4(a[v][mt], base + mt * (16 * 80));
            }
            const uint32_t boff =
                ((ks << 4) + (lane & 15)) * 272 + (wn0 + ((lane >> 4) << 3)) * 2;
#pragma unroll
            for (int v = 0; v < 2; v++) {
                const uint32_t base = s + (v ? OFF_BL : OFF_BH) + boff;
                LDSM4T(b[v][0], b[v][1], base);
                LDSM4T(b[v][2], b[v][3], base + 32);
            }
#pragma unroll
            for (int mt = 0; mt < 4; mt++)
#pragma unroll
                for (int nt = 0; nt < 4; nt++) mma16816(acc[mt][nt], a[0][mt], b[0][nt]);
#pragma unroll
            for (int mt = 0; mt < 4; mt++)
#pragma unroll
                for (int nt = 0; nt < 4; nt++) mma16816(acc[mt][nt], a[0][mt], b[1][nt]);
#pragma unroll
            for (int mt = 0; mt < 4; mt++)
#pragma unroll
                for (int nt = 0; nt < 4; nt++) mma16816(acc[mt][nt], a[1][mt], b[0][nt]);
        }
    }

#pragma unroll
    for (int mt = 0; mt < 4; mt++) {
        const int m = m0 + wm0 + mt * 16 + (lane >> 2);
#pragma unroll
        for (int nt = 0; nt < 4; nt++) {
            const int n = n0 + wn0 + nt * 8 + (lane & 3) * 2;
            float2 bv = *(const float2*)(bias + n);
            float o0 = acc[mt][nt][0] + bv.x;
            float o1 = acc[mt][nt][1] + bv.y;
            float o2 = acc[mt][nt][2] + bv.x;
            float o3 = acc[mt][nt][3] + bv.y;
            if (EPI == 1) {
                float2 r0 = *(const float2*)(res + (size_t)m * N + n);
                float2 r1 = *(const float2*)(res + (size_t)(m + 8) * N + n);
                o0 += r0.x; o1 += r0.y; o2 += r1.x; o3 += r1.y;
                *(float2*)(C + (size_t)m * N + n) = make_float2(o0, o1);
                *(float2*)(C + (size_t)(m + 8) * N + n) = make_float2(o2, o3);
            } else {
                if (EPI == 2) {
                    o0 = 0.5f * o0 * (1.0f + erff(o0 * 0.7071067811865475f));
                    o1 = 0.5f * o1 * (1.0f + erff(o1 * 0.7071067811865475f));
                    o2 = 0.5f * o2 * (1.0f + erff(o2 * 0.7071067811865475f));
                    o3 = 0.5f * o3 * (1.0f + erff(o3 * 0.7071067811865475f));
                }
                uint32_t h0 = pack_bf16(o0, o1);
                uint32_t h1 = pack_bf16(o2, o3);
                *(uint32_t*)(Cho + (size_t)m * N + n) = h0;
                *(uint32_t*)(Clo + (size_t)m * N + n) =
                    pack_bf16(o0 - bf16lo_f(h0), o1 - bf16hi_f(h0));
                *(uint32_t*)(Cho + (size_t)(m + 8) * N + n) = h1;
                *(uint32_t*)(Clo + (size_t)(m + 8) * N + n) =
                    pack_bf16(o2 - bf16lo_f(h1), o3 - bf16hi_f(h1));
            }
        }
    }
}

// ---------------------------------------------------------------------------
// Flash attention: per CTA one (b,h) x 128 q-rows. 8 warps x 16 q-rows.
// k-tiles of 64, double-buffered cp.async. 3-pass hi/lo bf16 MMA both GEMMs.
// smem: Q hi/lo (2x18432) then 2 KV stages of 36864 (Kh,Kl,Vh,Vl @ 9216 each).
// ---------------------------------------------------------------------------
#define FSTG 36864
__global__ void __launch_bounds__(256) flash_kernel(
    const __nv_bfloat16* __restrict__ Qh, const __nv_bfloat16* __restrict__ Ql,
    const __nv_bfloat16* __restrict__ Kh, const __nv_bfloat16* __restrict__ Kl,
    const __nv_bfloat16* __restrict__ Vh, const __nv_bfloat16* __restrict__ Vl,
    const int* __restrict__ ts, const float* __restrict__ pb,
    const float* __restrict__ mask,
    __nv_bfloat16* __restrict__ Ch, __nv_bfloat16* __restrict__ Cl)
{
    extern __shared__ char smem[];
    const uint32_t sb = cvta_smem(smem);
    const int tid = threadIdx.x, lane = tid & 31, warp = tid >> 5;
    const int qb = blockIdx.x << 7;
    const int bh = blockIdx.y, b = bh & 3, h = bh >> 2;
    const uint32_t sQ = sb;
    const uint32_t sKV = sb + 36864;

    // Q + stage 0
#pragma unroll
    for (int i = 0; i < 4; i++) {
        int idx = tid + (i << 8);
        int r = idx >> 3, c = idx & 7;
        size_t off = ((size_t)(b * Sn + qb + r)) * Hn + h * 64 + c * 8;
        CP16(sQ + r * 144 + c * 16, Qh + off);
        CP16(sQ + 18432 + r * 144 + c * 16, Ql + off);
    }
#pragma unroll
    for (int i = 0; i < 2; i++) {
        int idx = tid + (i << 8);
        int r = idx >> 3, c = idx & 7;
        size_t off = ((size_t)(b * Sn + r)) * Hn + h * 64 + c * 8;
        uint32_t d = sKV + r * 144 + c * 16;
        CP16(d, Kh + off); CP16(d + 9216, Kl + off);
        CP16(d + 18432, Vh + off); CP16(d + 27648, Vl + off);
    }
    CP_COMMIT();

    const int qr0 = qb + (warp << 4) + (lane >> 2);
    const int tq0 = ts[b * Sn + qr0];
    const int tq1 = ts[b * Sn + qr0 + 8];

    uint32_t aqh[4][4], aql[4][4];
    float oacc[8][4];
#pragma unroll
    for (int t = 0; t < 8; t++)
#pragma unroll
        for (int r = 0; r < 4; r++) oacc[t][r] = 0.0f;
    float m0 = -1e30f, m1 = -1e30f, l0 = 0.0f, l1 = 0.0f;

    for (int it = 0; it < 32; it++) {
        if (it + 1 < 32) {
            const uint32_t s = sKV + ((it + 1) & 1) * FSTG;
            const int k0n = (it + 1) << 6;
#pragma unroll
            for (int i = 0; i < 2; i++) {
                int idx = tid + (i << 8);
                int r = idx >> 3, c = idx & 7;
                size_t off = ((size_t)(b * Sn + k0n + r)) * Hn + h * 64 + c * 8;
                uint32_t d = s + r * 144 + c * 16;
                CP16(d, Kh + off); CP16(d + 9216, Kl + off);
                CP16(d + 18432, Vh + off); CP16(d + 27648, Vl + off);
            }
        }
        CP_COMMIT();
        CP_WAIT1();
        __syncthreads();

        if (it == 0) {
#pragma unroll
            for (int kc = 0; kc < 4; kc++) {
                uint32_t a = sQ + ((warp << 4) + (lane & 15)) * 144 +
                             ((kc << 4) + ((lane >> 4) << 3)) * 2;
                LDSM4(aqh[kc], a);
                LDSM4(aql[kc], a + 18432);
            }
        }

        const uint32_t stg = sKV + (it & 1) * FSTG;
        float sacc[8][4];
#pragma unroll
        for (int t = 0; t < 8; t++)
#pragma unroll
            for (int r = 0; r < 4; r++) sacc[t][r] = 0.0f;

#pragma unroll
        for (int kc = 0; kc < 4; kc++) {
            uint32_t kbh[4][4], kbl[4][4];
#pragma unroll
            for (int nb = 0; nb < 4; nb++) {
                uint32_t a = stg + ((nb << 4) + (lane & 15)) * 144 +
                             ((kc << 4) + ((lane >> 4) << 3)) * 2;
                LDSM4(kbh[nb], a);
                LDSM4(kbl[nb], a + 9216);
            }
#pragma unroll
            for (int t = 0; t < 8; t++) {
                uint32_t bh_[2] = {kbh[t >> 1][t & 1], kbh[t >> 1][(t & 1) + 2]};
                uint32_t bl_[2] = {kbl[t >> 1][t & 1], kbl[t >> 1][(t & 1) + 2]};
                mma16816(sacc[t], aqh[kc], bh_);
                mma16816(sacc[t], aqh[kc], bl_);
                mma16816(sacc[t], aql[kc], bh_);
            }
        }

        // epilogue: scale + pb + mask, online softmax
        const int k0 = it << 6;
        float tm0 = -1e30f, tm1 = -1e30f;
#pragma unroll
        for (int t = 0; t < 8; t++) {
            const int n = k0 + (t << 3) + ((lane & 3) << 1);
            int2 tk = *(const int2*)(ts + b * Sn + n);
            float2 mk = *(const float2*)(mask + b * Sn + n);
            float2 p0 = *(const float2*)(pb + ((size_t)h * Sn + qr0) * Sn + n);
            float2 p1 = *(const float2*)(pb + ((size_t)h * Sn + qr0 + 8) * Sn + n);
            float lg, sc;
            lg = (float)(tq0 - tk.x) * (1.0f / 60000.0f);
            sc = 9.0f - 1.0f / (fmaxf(lg, 0.0f) + 1.0f);
            sacc[t][0] = sacc[t][0] / sc + p0.x + mk.x;
            lg = (float)(tq0 - tk.y) * (1.0f / 60000.0f);
            sc = 9.0f - 1.0f / (fmaxf(lg, 0.0f) + 1.0f);
            sacc[t][1] = sacc[t][1] / sc + p0.y + mk.y;
            lg = (float)(tq1 - tk.x) * (1.0f / 60000.0f);
            sc = 9.0f - 1.0f / (fmaxf(lg, 0.0f) + 1.0f);
            sacc[t][2] = sacc[t][2] / sc + p1.x + mk.x;
            lg = (float)(tq1 - tk.y) * (1.0f / 60000.0f);
            sc = 9.0f - 1.0f / (fmaxf(lg, 0.0f) + 1.0f);
            sacc[t][3] = sacc[t][3] / sc + p1.y + mk.y;
            tm0 = fmaxf(tm0, fmaxf(sacc[t][0], sacc[t][1]));
            tm1 = fmaxf(tm1, fmaxf(sacc[t][2], sacc[t][3]));
        }
        tm0 = fmaxf(tm0, __shfl_xor_sync(0xffffffffu, tm0, 1));
        tm0 = fmaxf(tm0, __shfl_xor_sync(0xffffffffu, tm0, 2));
        tm1 = fmaxf(tm1, __shfl_xor_sync(0xffffffffu, tm1, 1));
        tm1 = fmaxf(tm1, __shfl_xor_sync(0xffffffffu, tm1, 2));
        const float mn0 = fmaxf(m0, tm0), mn1 = fmaxf(m1, tm1);
        const float c0 = ex2f((m0 - mn0) * L2E), c1 = ex2f((m1 - mn1) * L2E);
        m0 = mn0; m1 = mn1;

        float rs0 = 0.0f, rs1 = 0.0f;
        uint32_t aph[4][4], apl[4][4];
#pragma unroll
        for (int t = 0; t < 8; t++) {
            float p00 = ex2f((sacc[t][0] - m0) * L2E);
            float p01 = ex2f((sacc[t][1] - m0) * L2E);
            float p10 = ex2f((sacc[t][2] - m1) * L2E);
            float p11 = ex2f((sacc[t][3] - m1) * L2E);
            rs0 += p00 + p01; rs1 += p10 + p11;
            uint32_t h0 = pack_bf16(p00, p01);
            uint32_t h1 = pack_bf16(p10, p11);
            const int kc2 = t >> 1, hf = (t & 1) << 1;
            aph[kc2][hf] = h0; aph[kc2][hf + 1] = h1;
            apl[kc2][hf] = pack_bf16(p00 - bf16lo_f(h0), p01 - bf16hi_f(h0));
            apl[kc2][hf + 1] = pack_bf16(p10 - bf16lo_f(h1), p11 - bf16hi_f(h1));
        }
        rs0 += __shfl_xor_sync(0xffffffffu, rs0, 1);
        rs0 += __shfl_xor_sync(0xffffffffu, rs0, 2);
        rs1 += __shfl_xor_sync(0xffffffffu, rs1, 1);
        rs1 += __shfl_xor_sync(0xffffffffu, rs1, 2);
        l0 = l0 * c0 + rs0;
        l1 = l1 * c1 + rs1;
#pragma unroll
        for (int t = 0; t < 8; t++) {
            oacc[t][0] *= c0; oacc[t][1] *= c0;
            oacc[t][2] *= c1; oacc[t][3] *= c1;
        }

        // ctx: O += P * V
#pragma unroll
        for (int kc2 = 0; kc2 < 4; kc2++) {
            uint32_t vfh[8][2], vfl[8][2];
#pragma unroll
            for (int dnb = 0; dnb < 4; dnb++) {
                uint32_t a = stg + 18432 + ((kc2 << 4) + (lane & 15)) * 144 +
                             ((dnb << 4) + ((lane >> 4) << 3)) * 2;
                LDSM4T(vfh[2 * dnb], vfh[2 * dnb + 1], a);
                LDSM4T(vfl[2 * dnb], vfl[2 * dnb + 1], a + 9216);
            }
#pragma unroll
            for (int t = 0; t < 8; t++) {
                mma16816(oacc[t], aph[kc2], vfh[t]);
                mma16816(oacc[t], aph[kc2], vfl[t]);
                mma16816(oacc[t], apl[kc2], vfh[t]);
            }
        }
        __syncthreads();
    }

    const float inv0 = 1.0f / l0, inv1 = 1.0f / l1;
#pragma unroll
    for (int t = 0; t < 8; t++) {
        const int d = (t << 3) + ((lane & 3) << 1);
        const size_t o0 = ((size_t)(b * Sn + qr0)) * Hn + h * 64 + d;
        const size_t o1 = ((size_t)(b * Sn + qr0 + 8)) * Hn + h * 64 + d;
        float v0 = oacc[t][0] * inv0, v1 = oacc[t][1] * inv0;
        float v2 = oacc[t][2] * inv1, v3 = oacc[t][3] * inv1;
        uint32_t h0 = pack_bf16(v0, v1), h1 = pack_bf16(v2, v3);
        *(uint32_t*)(Ch + o0) = h0;
        *(uint32_t*)(Cl + o0) = pack_bf16(v0 - bf16lo_f(h0), v1 - bf16hi_f(h0));
        *(uint32_t*)(Ch + o1) = h1;
        *(uint32_t*)(Cl + o1) = pack_bf16(v2 - bf16lo_f(h1), v3 - bf16hi_f(h1));
    }
}

// ---------------------------------------------------------------------------
// LayerNorm over H=512; optional bf16 hi/lo outputs.
// ---------------------------------------------------------------------------
__global__ void __launch_bounds__(256) ln_kernel(
    const float* __restrict__ in, const float* __restrict__ g,
    const float* __restrict__ bta, float* __restrict__ out,
    __nv_bfloat16* __restrict__ ho, __nv_bfloat16* __restrict__ lo_)
{
    const size_t base = (size_t)blockIdx.x * Hn;
    const int tid = threadIdx.x;
    __shared__ float sh[8], sh2[8];
    float x0 = in[base + tid], x1 = in[base + tid + 256];
    float s = x0 + x1;
    for (int o = 16; o; o >>= 1) s += __shfl_xor_sync(0xffffffffu, s, o);
    if ((tid & 31) == 0) sh[tid >> 5] = s;
    __syncthreads();
    s = 0.0f;
#pragma unroll
    for (int i = 0; i < 8; i++) s += sh[i];
    const float mean = s * (1.0f / Hn);
    const float d0 = x0 - mean, d1 = x1 - mean;
    float vv = d0 * d0 + d1 * d1;
    for (int o = 16; o; o >>= 1) vv += __shfl_xor_sync(0xffffffffu, vv, o);
    if ((tid & 31) == 0) sh2[tid >> 5] = vv;
    __syncthreads();
    vv = 0.0f;
#pragma unroll
    for (int i = 0; i < 8; i++) vv += sh2[i];
    const float inv = rsqrtf(vv * (1.0f / Hn) + 1e-12f);
    const float y0 = d0 * inv * g[tid] + bta[tid];
    const float y1 = d1 * inv * g[tid + 256] + bta[tid + 256];
    out[base + tid] = y0;
    out[base + tid + 256] = y1;
    if (ho) {
        __nv_bfloat16 h0 = __float2bfloat16(y0);
        __nv_bfloat16 h1 = __float2bfloat16(y1);
        ho[base + tid] = h0;
        ho[base + tid + 256] = h1;
        lo_[base + tid] = __float2bfloat16(y0 - __bfloat162float(h0));
        lo_[base + tid + 256] = __float2bfloat16(y1 - __bfloat162float(h1));
    }
}

// ---------------------------------------------------------------------------
extern "C" void kernel_launch(void* const* d_in, const int* in_sizes, int n_in,
                              void* d_out, int out_size)
{
    (void)in_sizes; (void)n_in; (void)out_size;
    const float* qs   = (const float*)d_in[0];
    const float* mask = (const float*)d_in[1];
    const float* pb   = (const float*)d_in[2];
    const int*   ts   = (const int*)d_in[3];
    const float* wq  = (const float*)d_in[4];  const float* bq  = (const float*)d_in[5];
    const float* wk  = (const float*)d_in[6];  const float* bk  = (const float*)d_in[7];
    const float* wv  = (const float*)d_in[8];  const float* bv  = (const float*)d_in[9];
    const float* wo  = (const float*)d_in[10]; const float* bo  = (const float*)d_in[11];
    const float* l1g = (const float*)d_in[12]; const float* l1b = (const float*)d_in[13];
    const float* wi  = (const float*)d_in[14]; const float* bi  = (const float*)d_in[15];
    const float* wo2 = (const float*)d_in[16]; const float* bo2 = (const float*)d_in[17];
    const float* l2g = (const float*)d_in[18]; const float* l2b = (const float*)d_in[19];

    float *x, *attn;
    cudaGetSymbolAddress((void**)&x,    g_x);
    cudaGetSymbolAddress((void**)&attn, g_attn);

    __nv_bfloat16 *qh, *ql, *kh, *kl, *vh, *vl, *ch, *cl, *xh, *xl, *th, *tl, *fh, *fl;
    cudaGetSymbolAddress((void**)&qh, g_qh); cudaGetSymbolAddress((void**)&ql, g_ql);
    cudaGetSymbolAddress((void**)&kh, g_kh); cudaGetSymbolAddress((void**)&kl, g_kl);
    cudaGetSymbolAddress((void**)&vh, g_vh); cudaGetSymbolAddress((void**)&vl, g_vl);
    cudaGetSymbolAddress((void**)&ch, g_ch); cudaGetSymbolAddress((void**)&cl, g_cl);
    cudaGetSymbolAddress((void**)&xh, g_xh); cudaGetSymbolAddress((void**)&xl, g_xl);
    cudaGetSymbolAddress((void**)&th, g_th); cudaGetSymbolAddress((void**)&tl, g_tl);
    cudaGetSymbolAddress((void**)&fh, g_fh); cudaGetSymbolAddress((void**)&fl, g_fl);

    __nv_bfloat16 *wqh, *wql, *wkh, *wkl, *wvh, *wvl, *woh, *wol, *wih, *wil, *w2h, *w2l;
    cudaGetSymbolAddress((void**)&wqh, g_wqh); cudaGetSymbolAddress((void**)&wql, g_wql);
    cudaGetSymbolAddress((void**)&wkh, g_wkh); cudaGetSymbolAddress((void**)&wkl, g_wkl);
    cudaGetSymbolAddress((void**)&wvh, g_wvh); cudaGetSymbolAddress((void**)&wvl, g_wvl);
    cudaGetSymbolAddress((void**)&woh, g_woh); cudaGetSymbolAddress((void**)&wol, g_wol);
    cudaGetSymbolAddress((void**)&wih, g_wih); cudaGetSymbolAddress((void**)&wil, g_wil);
    cudaGetSymbolAddress((void**)&w2h, g_w2h); cudaGetSymbolAddress((void**)&w2l, g_w2l);

    const int HM_SMEM = 2 * STAGE_BYTES;  // 75776
    const int FL_SMEM = 36864 + 2 * FSTG; // 110592
    cudaFuncSetAttribute(hmma_gemm<0>, cudaFuncAttributeMaxDynamicSharedMemorySize, HM_SMEM);
    cudaFuncSetAttribute(hmma_gemm<1>, cudaFuncAttributeMaxDynamicSharedMemorySize, HM_SMEM);
    cudaFuncSetAttribute(hmma_gemm<2>, cudaFuncAttributeMaxDynamicSharedMemorySize, HM_SMEM);
    cudaFuncSetAttribute(flash_kernel, cudaFuncAttributeMaxDynamicSharedMemorySize, FL_SMEM);

    // Weight + initial activation splits
    const int WNH = Ln * Hn * Hn, WNF = Ln * Hn * Fn;
    split_kernel<<<WNH / 2048, 256>>>(wq,  wqh, wql, WNH);
    split_kernel<<<WNH / 2048, 256>>>(wk,  wkh, wkl, WNH);
    split_kernel<<<WNH / 2048, 256>>>(wv,  wvh, wvl, WNH);
    split_kernel<<<WNH / 2048, 256>>>(wo,  woh, wol, WNH);
    split_kernel<<<WNF / 2048, 256>>>(wi,  wih, wil, WNF);
    split_kernel<<<WNF / 2048, 256>>>(wo2, w2h, w2l, WNF);
    split_kernel<<<(Mn * Hn) / 2048, 256>>>(qs, xh, xl, Mn * Hn);

    dim3 gproj(Hn / 128, Mn / 128);   // (4, 64)
    dim3 gff(Fn / 128, Mn / 128);     // (16, 64)
    dim3 gfl(Sn / 128, Bn * NHn);     // (16, 32)

    for (int l = 0; l < Ln; l++) {
        const size_t wOff  = (size_t)l * Hn * Hn;
        const size_t bOff  = (size_t)l * Hn;
        const size_t wiOff = (size_t)l * Hn * Fn;
        const size_t biOff = (size_t)l * Fn;
        const float* xres = (l == 0) ? qs : x;

        hmma_gemm<0><<<gproj, 256, HM_SMEM>>>(xh, xl, wqh + wOff, wql + wOff,
                                              bq + bOff, nullptr, nullptr, qh, ql, Hn, Hn);
        hmma_gemm<0><<<gproj, 256, HM_SMEM>>>(xh, xl, wkh + wOff, wkl + wOff,
                                              bk + bOff, nullptr, nullptr, kh, kl, Hn, Hn);
        hmma_gemm<0><<<gproj, 256, HM_SMEM>>>(xh, xl, wvh + wOff, wvl + wOff,
                                              bv + bOff, nullptr, nullptr, vh, vl, Hn, Hn);

        flash_kernel<<<gfl, 256, FL_SMEM>>>(qh, ql, kh, kl, vh, vl, ts, pb, mask, ch, cl);

        hmma_gemm<1><<<gproj, 256, HM_SMEM>>>(ch, cl, woh + wOff, wol + wOff,
                                              bo + bOff, xres, attn, nullptr, nullptr, Hn, Hn);
        ln_kernel<<<Mn, 256>>>(attn, l1g + bOff, l1b + bOff, attn, th, tl);

        hmma_gemm<2><<<gff, 256, HM_SMEM>>>(th, tl, wih + wiOff, wil + wiOff,
                                            bi + biOff, nullptr, nullptr, fh, fl, Hn, Fn);
        hmma_gemm<1><<<gproj, 256, HM_SMEM>>>(fh, fl, w2h + wiOff, w2l + wiOff,
                                              bo2 + bOff, attn, x, nullptr, nullptr, Fn, Hn);

        float* lnout = (l == Ln - 1) ? (float*)d_out : x;
        ln_kernel<<<Mn, 256>>>(x, l2g + bOff, l2b + bOff, lnout,
                               (l == Ln - 1) ? nullptr : xh,
                               (l == Ln - 1) ? nullptr : xl);
    }
}

// round 6
// speedup vs baseline: 2.4122x; 1.2326x over previous
#include <cuda_runtime.h>
#include <cuda_bf16.h>
#include <math.h>
#include <stdint.h>

// Problem constants
#define Bn 4
#define Sn 2048
#define Hn 512
#define NHn 8
#define DHn 64
#define Fn 2048
#define Ln 4
#define Mn (Bn * Sn)  // 8192
#define QKVS 1536
#define L2E 1.4426950408889634f

// ---------------- scratch (device globals; no allocation allowed) ----------
__device__ float g_x[Mn * Hn];
__device__ float g_attn[Mn * Hn];

__device__ __nv_bfloat16 g_qkvh[(size_t)Mn * QKVS], g_qkvl[(size_t)Mn * QKVS];
__device__ __nv_bfloat16 g_ch[Mn * Hn], g_cl[Mn * Hn];   // ctx
__device__ __nv_bfloat16 g_xh[Mn * Hn], g_xl[Mn * Hn];
__device__ __nv_bfloat16 g_th[Mn * Hn], g_tl[Mn * Hn];   // attn (post ln1)
__device__ __nv_bfloat16 g_fh[(size_t)Mn * Fn], g_fl[(size_t)Mn * Fn];

// weights hi/lo
__device__ __nv_bfloat16 g_wqkvh[Ln * Hn * QKVS], g_wqkvl[Ln * Hn * QKVS];
__device__ __nv_bfloat16 g_woh[Ln * Hn * Hn], g_wol[Ln * Hn * Hn];
__device__ __nv_bfloat16 g_wih[Ln * Hn * Fn], g_wil[Ln * Hn * Fn];
__device__ __nv_bfloat16 g_w2h[Ln * Fn * Hn], g_w2l[Ln * Fn * Hn];
__device__ float g_bqkv[Ln * QKVS];
__device__ __nv_bfloat16 g_pbb[(size_t)NHn * Sn * Sn];   // bf16 position bias

// ---------------- helpers ---------------------------------------------------
__device__ __forceinline__ uint32_t cvta_smem(const void* p) {
    uint32_t a;
    asm("{ .reg .u64 t; cvta.to.shared.u64 t, %1; cvt.u32.u64 %0, t; }"
        : "=r"(a) : "l"(p));
    return a;
}

#define CP16(dst, src) \
    asm volatile("cp.async.cg.shared.global [%0], [%1], 16;" :: "r"(dst), "l"(src))
#define CP_COMMIT() asm volatile("cp.async.commit_group;" ::: "memory")
#define CP_WAIT0()  asm volatile("cp.async.wait_group 0;" ::: "memory")
#define CP_WAIT1()  asm volatile("cp.async.wait_group 1;" ::: "memory")

#define LDSM4(r, addr)                                                          \
    asm volatile("ldmatrix.sync.aligned.m8n8.x4.shared.b16 {%0,%1,%2,%3}, [%4];"\
        : "=r"((r)[0]), "=r"((r)[1]), "=r"((r)[2]), "=r"((r)[3]) : "r"(addr))
#define LDSM4T(r01, r23, addr)                                                  \
    asm volatile("ldmatrix.sync.aligned.m8n8.x4.trans.shared.b16 {%0,%1,%2,%3}, [%4];"\
        : "=r"((r01)[0]), "=r"((r01)[1]), "=r"((r23)[0]), "=r"((r23)[1]) : "r"(addr))

__device__ __forceinline__ void mma16816(float* c, const uint32_t* a, const uint32_t* b) {
    asm volatile(
        "mma.sync.aligned.m16n8k16.row.col.f32.bf16.bf16.f32 "
        "{%0,%1,%2,%3}, {%4,%5,%6,%7}, {%8,%9}, {%0,%1,%2,%3};"
        : "+f"(c[0]), "+f"(c[1]), "+f"(c[2]), "+f"(c[3])
        : "r"(a[0]), "r"(a[1]), "r"(a[2]), "r"(a[3]), "r"(b[0]), "r"(b[1]));
}

__device__ __forceinline__ uint32_t pack_bf16(float lo, float hi) {
    uint32_t r;
    asm("cvt.rn.satfinite.bf16x2.f32 %0, %1, %2;" : "=r"(r) : "f"(hi), "f"(lo));
    return r;
}
__device__ __forceinline__ float bf16lo_f(uint32_t u) { return __uint_as_float(u << 16); }
__device__ __forceinline__ float bf16hi_f(uint32_t u) { return __uint_as_float(u & 0xffff0000u); }
__device__ __forceinline__ float ex2f(float x) {
    float y;
    asm("ex2.approx.ftz.f32 %0, %1;" : "=f"(y) : "f"(x));
    return y;
}
__device__ __forceinline__ float rcpf(float x) {
    float y;
    asm("rcp.approx.ftz.f32 %0, %1;" : "=f"(y) : "f"(x));
    return y;
}
// 1/scale = (u + 60000) / (9u + 480000) where u = max(dt_ms, 0)
__device__ __forceinline__ float sinv_of(int dt) {
    float u = fmaxf((float)dt, 0.0f);
    return (u + 60000.0f) * rcpf(fmaf(u, 9.0f, 480000.0f));
}

// smem stage layout for dense GEMM (padded rows: A 80B, B 272B)
#define OFF_AH 0
#define OFF_AL 10240
#define OFF_BH 20480
#define OFF_BL 29184
#define STAGE_BYTES 37888   // x2 stages = 75776

// ---------------------------------------------------------------------------
// Split fp32 -> bf16 hi + lo residual. n multiple of 8.
// ---------------------------------------------------------------------------
__global__ void __launch_bounds__(256) split_kernel(
    const float* __restrict__ x, __nv_bfloat16* __restrict__ h,
    __nv_bfloat16* __restrict__ l, int n)
{
    int i = (blockIdx.x * 256 + threadIdx.x) * 8;
    if (i >= n) return;
    float4 a = *(const float4*)(x + i);
    float4 b = *(const float4*)(x + i + 4);
    float v[8] = {a.x, a.y, a.z, a.w, b.x, b.y, b.z, b.w};
    __align__(16) __nv_bfloat16 hh[8];
    __align__(16) __nv_bfloat16 ll[8];
#pragma unroll
    for (int j = 0; j < 8; j++) {
        hh[j] = __float2bfloat16(v[j]);
        ll[j] = __float2bfloat16(v[j] - __bfloat162float(hh[j]));
    }
    *(uint4*)(h + i) = *(const uint4*)hh;
    *(uint4*)(l + i) = *(const uint4*)ll;
}

// Split + scatter into packed [rows, dstcols] at column offset. srccols=512.
__global__ void __launch_bounds__(256) split_pack_kernel(
    const float* __restrict__ x, __nv_bfloat16* __restrict__ h,
    __nv_bfloat16* __restrict__ l, int n, int coloff)
{
    int i = (blockIdx.x * 256 + threadIdx.x) * 8;
    if (i >= n) return;
    const int row = i >> 9, col = i & 511;
    float4 a = *(const float4*)(x + i);
    float4 b = *(const float4*)(x + i + 4);
    float v[8] = {a.x, a.y, a.z, a.w, b.x, b.y, b.z, b.w};
    __align__(16) __nv_bfloat16 hh[8];
    __align__(16) __nv_bfloat16 ll[8];
#pragma unroll
    for (int j = 0; j < 8; j++) {
        hh[j] = __float2bfloat16(v[j]);
        ll[j] = __float2bfloat16(v[j] - __bfloat162float(hh[j]));
    }
    const size_t d = (size_t)row * QKVS + coloff + col;
    *(uint4*)(h + d) = *(const uint4*)hh;
    *(uint4*)(l + d) = *(const uint4*)ll;
}

__global__ void __launch_bounds__(256) pack_bias_kernel(
    const float* __restrict__ bq, const float* __restrict__ bk,
    const float* __restrict__ bv, float* __restrict__ dst)
{
    int i = blockIdx.x * 256 + threadIdx.x;
    if (i >= Ln * QKVS) return;
    int l = i / QKVS, j = i % QKVS, seg = j >> 9, col = j & 511;
    const float* s = (seg == 0) ? bq : (seg == 1) ? bk : bv;
    dst[i] = s[l * Hn + col];
}

__global__ void __launch_bounds__(256) cvt_bf16_kernel(
    const float* __restrict__ x, __nv_bfloat16* __restrict__ y, int n)
{
    int i = (blockIdx.x * 256 + threadIdx.x) * 8;
    if (i >= n) return;
    float4 a = *(const float4*)(x + i);
    float4 b = *(const float4*)(x + i + 4);
    float v[8] = {a.x, a.y, a.z, a.w, b.x, b.y, b.z, b.w};
    __align__(16) __nv_bfloat16 hh[8];
#pragma unroll
    for (int j = 0; j < 8; j++) hh[j] = __float2bfloat16(v[j]);
    *(uint4*)(y + i) = *(const uint4*)hh;
}

// ---------------------------------------------------------------------------
// HMMA split-bf16 GEMM. CTA 128x128, BK=32, 8 warps, 3 passes.
// EPI 0: bias -> bf16 hi/lo out.  EPI 1: bias + res -> fp32 out.
// EPI 2: bias + GELU -> bf16 hi/lo out.
// ---------------------------------------------------------------------------
template <int EPI>
__global__ void __launch_bounds__(256) hmma_gemm(
    const __nv_bfloat16* __restrict__ Ahp, const __nv_bfloat16* __restrict__ Alp,
    const __nv_bfloat16* __restrict__ Bhp, const __nv_bfloat16* __restrict__ Blp,
    const float* __restrict__ bias, const float* __restrict__ res,
    float* __restrict__ C, __nv_bfloat16* __restrict__ Cho,
    __nv_bfloat16* __restrict__ Clo, int K, int N)
{
    extern __shared__ char smem[];
    const uint32_t sb = cvta_smem(smem);
    const int tid = threadIdx.x, lane = tid & 31, warp = tid >> 5;
    const int m0 = blockIdx.y << 7, n0 = blockIdx.x << 7;
    const int wm0 = (warp >> 2) << 6, wn0 = (warp & 3) << 5;

    const int ar = tid >> 2, ac = tid & 3;
    const int br = tid >> 4, bc = tid & 15;

    auto load_stage = [&](int st, int kc) {
        const int k0 = kc << 5;
        const uint32_t s = sb + st * STAGE_BYTES;
        const size_t aoff0 = (size_t)(m0 + ar) * K + k0 + ac * 8;
        const size_t aoff1 = (size_t)(m0 + ar + 64) * K + k0 + ac * 8;
        CP16(s + OFF_AH + ar * 80 + ac * 16, Ahp + aoff0);
        CP16(s + OFF_AH + (ar + 64) * 80 + ac * 16, Ahp + aoff1);
        CP16(s + OFF_AL + ar * 80 + ac * 16, Alp + aoff0);
        CP16(s + OFF_AL + (ar + 64) * 80 + ac * 16, Alp + aoff1);
        const size_t boff0 = (size_t)(k0 + br) * N + n0 + bc * 8;
        const size_t boff1 = (size_t)(k0 + br + 16) * N + n0 + bc * 8;
        CP16(s + OFF_BH + br * 272 + bc * 16, Bhp + boff0);
        CP16(s + OFF_BH + (br + 16) * 272 + bc * 16, Bhp + boff1);
        CP16(s + OFF_BL + br * 272 + bc * 16, Blp + boff0);
        CP16(s + OFF_BL + (br + 16) * 272 + bc * 16, Blp + boff1);
        CP_COMMIT();
    };

    float acc[4][4][4];
#pragma unroll
    for (int i = 0; i < 4; i++)
#pragma unroll
        for (int j = 0; j < 4; j++)
#pragma unroll
            for (int r = 0; r < 4; r++) acc[i][j][r] = 0.0f;

    const int nch = K >> 5;
    load_stage(0, 0);

    for (int kc = 0; kc < nch; kc++) {
        const int cur = kc & 1;
        CP_WAIT0();
        __syncthreads();
        if (kc + 1 < nch) load_stage(cur ^ 1, kc + 1);

        const uint32_t s = sb + cur * STAGE_BYTES;
#pragma unroll
        for (int ks = 0; ks < 2; ks++) {
            uint32_t a[2][4][4];
            uint32_t b[2][4][2];
            const uint32_t aoff =
                (wm0 + (lane & 15)) * 80 + ((ks << 4) + ((lane >> 4) << 3)) * 2;
#pragma unroll
            for (int v = 0; v < 2; v++) {
                const uint32_t base = s + (v ? OFF_AL : OFF_AH) + aoff;
#pragma unroll
                for (int mt = 0; mt < 4; mt++) LDSM4(a[v][mt], base + mt * (16 * 80));
            }
            const uint32_t boff =
                ((ks << 4) + (lane & 15)) * 272 + (wn0 + ((lane >> 4) << 3)) * 2;
#pragma unroll
            for (int v = 0; v < 2; v++) {
                const uint32_t base = s + (v ? OFF_BL : OFF_BH) + boff;
                LDSM4T(b[v][0], b[v][1], base);
                LDSM4T(b[v][2], b[v][3], base + 32);
            }
#pragma unroll
            for (int mt = 0; mt < 4; mt++)
#pragma unroll
                for (int nt = 0; nt < 4; nt++) mma16816(acc[mt][nt], a[0][mt], b[0][nt]);
#pragma unroll
            for (int mt = 0; mt < 4; mt++)
#pragma unroll
                for (int nt = 0; nt < 4; nt++) mma16816(acc[mt][nt], a[0][mt], b[1][nt]);
#pragma unroll
            for (int mt = 0; mt < 4; mt++)
#pragma unroll
                for (int nt = 0; nt < 4; nt++) mma16816(acc[mt][nt], a[1][mt], b[0][nt]);
        }
    }

#pragma unroll
    for (int mt = 0; mt < 4; mt++) {
        const int m = m0 + wm0 + mt * 16 + (lane >> 2);
#pragma unroll
        for (int nt = 0; nt < 4; nt++) {
            const int n = n0 + wn0 + nt * 8 + (lane & 3) * 2;
            float2 bv = *(const float2*)(bias + n);
            float o0 = acc[mt][nt][0] + bv.x;
            float o1 = acc[mt][nt][1] + bv.y;
            float o2 = acc[mt][nt][2] + bv.x;
            float o3 = acc[mt][nt][3] + bv.y;
            if (EPI == 1) {
                float2 r0 = *(const float2*)(res + (size_t)m * N + n);
                float2 r1 = *(const float2*)(res + (size_t)(m + 8) * N + n);
                o0 += r0.x; o1 += r0.y; o2 += r1.x; o3 += r1.y;
                *(float2*)(C + (size_t)m * N + n) = make_float2(o0, o1);
                *(float2*)(C + (size_t)(m + 8) * N + n) = make_float2(o2, o3);
            } else {
                if (EPI == 2) {
                    o0 = 0.5f * o0 * (1.0f + erff(o0 * 0.7071067811865475f));
                    o1 = 0.5f * o1 * (1.0f + erff(o1 * 0.7071067811865475f));
                    o2 = 0.5f * o2 * (1.0f + erff(o2 * 0.7071067811865475f));
                    o3 = 0.5f * o3 * (1.0f + erff(o3 * 0.7071067811865475f));
                }
                uint32_t h0 = pack_bf16(o0, o1);
                uint32_t h1 = pack_bf16(o2, o3);
                *(uint32_t*)(Cho + (size_t)m * N + n) = h0;
                *(uint32_t*)(Clo + (size_t)m * N + n) =
                    pack_bf16(o0 - bf16lo_f(h0), o1 - bf16hi_f(h0));
                *(uint32_t*)(Cho + (size_t)(m + 8) * N + n) = h1;
                *(uint32_t*)(Clo + (size_t)(m + 8) * N + n) =
                    pack_bf16(o2 - bf16lo_f(h1), o3 - bf16hi_f(h1));
            }
        }
    }
}

// ---------------------------------------------------------------------------
// Flash attention over packed QKV [M, 1536]. Per CTA one (b,h) x 128 q-rows.
// ---------------------------------------------------------------------------
#define FSTG 36864
__global__ void __launch_bounds__(256) flash_kernel(
    const __nv_bfloat16* __restrict__ QKVh, const __nv_bfloat16* __restrict__ QKVl,
    const int* __restrict__ ts, const __nv_bfloat16* __restrict__ pbb,
    const float* __restrict__ mask,
    __nv_bfloat16* __restrict__ Ch, __nv_bfloat16* __restrict__ Cl)
{
    extern __shared__ char smem[];
    const uint32_t sb = cvta_smem(smem);
    const int tid = threadIdx.x, lane = tid & 31, warp = tid >> 5;
    const int qb = blockIdx.x << 7;
    const int bh = blockIdx.y, b = bh & 3, h = bh >> 2;
    const uint32_t sQ = sb;
    const uint32_t sKV = sb + 36864;

    // Q + stage 0
#pragma unroll
    for (int i = 0; i < 4; i++) {
        int idx = tid + (i << 8);
        int r = idx >> 3, c = idx & 7;
        size_t off = ((size_t)(b * Sn + qb + r)) * QKVS + h * 64 + c * 8;
        CP16(sQ + r * 144 + c * 16, QKVh + off);
        CP16(sQ + 18432 + r * 144 + c * 16, QKVl + off);
    }
#pragma unroll
    for (int i = 0; i < 2; i++) {
        int idx = tid + (i << 8);
        int r = idx >> 3, c = idx & 7;
        size_t off = ((size_t)(b * Sn + r)) * QKVS + h * 64 + c * 8;
        uint32_t d = sKV + r * 144 + c * 16;
        CP16(d, QKVh + off + 512); CP16(d + 9216, QKVl + off + 512);
        CP16(d + 18432, QKVh + off + 1024); CP16(d + 27648, QKVl + off + 1024);
    }
    CP_COMMIT();

    const int qr0 = qb + (warp << 4) + (lane >> 2);
    const int tq0 = ts[b * Sn + qr0];
    const int tq1 = ts[b * Sn + qr0 + 8];

    uint32_t aqh[4][4], aql[4][4];
    float oacc[8][4];
#pragma unroll
    for (int t = 0; t < 8; t++)
#pragma unroll
        for (int r = 0; r < 4; r++) oacc[t][r] = 0.0f;
    float m0 = -1e30f, m1 = -1e30f, l0 = 0.0f, l1 = 0.0f;

    for (int it = 0; it < 32; it++) {
        if (it + 1 < 32) {
            const uint32_t s = sKV + ((it + 1) & 1) * FSTG;
            const int k0n = (it + 1) << 6;
#pragma unroll
            for (int i = 0; i < 2; i++) {
                int idx = tid + (i << 8);
                int r = idx >> 3, c = idx & 7;
                size_t off = ((size_t)(b * Sn + k0n + r)) * QKVS + h * 64 + c * 8;
                uint32_t d = s + r * 144 + c * 16;
                CP16(d, QKVh + off + 512); CP16(d + 9216, QKVl + off + 512);
                CP16(d + 18432, QKVh + off + 1024); CP16(d + 27648, QKVl + off + 1024);
            }
        }
        CP_COMMIT();
        CP_WAIT1();
        __syncthreads();

        if (it == 0) {
#pragma unroll
            for (int kc = 0; kc < 4; kc++) {
                uint32_t a = sQ + ((warp << 4) + (lane & 15)) * 144 +
                             ((kc << 4) + ((lane >> 4) << 3)) * 2;
                LDSM4(aqh[kc], a);
                LDSM4(aql[kc], a + 18432);
            }
        }

        const uint32_t stg = sKV + (it & 1) * FSTG;
        float sacc[8][4];
#pragma unroll
        for (int t = 0; t < 8; t++)
#pragma unroll
            for (int r = 0; r < 4; r++) sacc[t][r] = 0.0f;

#pragma unroll
        for (int kc = 0; kc < 4; kc++) {
            uint32_t kbh[4][4], kbl[4][4];
#pragma unroll
            for (int nb = 0; nb < 4; nb++) {
                uint32_t a = stg + ((nb << 4) + (lane & 15)) * 144 +
                             ((kc << 4) + ((lane >> 4) << 3)) * 2;
                LDSM4(kbh[nb], a);
                LDSM4(kbl[nb], a + 9216);
            }
#pragma unroll
            for (int t = 0; t < 8; t++) {
                uint32_t bh_[2] = {kbh[t >> 1][t & 1], kbh[t >> 1][(t & 1) + 2]};
                uint32_t bl_[2] = {kbl[t >> 1][t & 1], kbl[t >> 1][(t & 1) + 2]};
                mma16816(sacc[t], aqh[kc], bh_);
                mma16816(sacc[t], aqh[kc], bl_);
                mma16816(sacc[t], aql[kc], bh_);
            }
        }

        // epilogue: scale (rcp.approx) + pb(bf16) + mask, online softmax
        const int k0 = it << 6;
        float tm0 = -1e30f, tm1 = -1e30f;
#pragma unroll
        for (int t = 0; t < 8; t++) {
            const int n = k0 + (t << 3) + ((lane & 3) << 1);
            int2 tk = *(const int2*)(ts + b * Sn + n);
            float2 mk = *(const float2*)(mask + b * Sn + n);
            uint32_t pu0 = *(const uint32_t*)(pbb + ((size_t)h * Sn + qr0) * Sn + n);
            uint32_t pu1 = *(const uint32_t*)(pbb + ((size_t)h * Sn + qr0 + 8) * Sn + n);
            sacc[t][0] = sacc[t][0] * sinv_of(tq0 - tk.x) + bf16lo_f(pu0) + mk.x;
            sacc[t][1] = sacc[t][1] * sinv_of(tq0 - tk.y) + bf16hi_f(pu0) + mk.y;
            sacc[t][2] = sacc[t][2] * sinv_of(tq1 - tk.x) + bf16lo_f(pu1) + mk.x;
            sacc[t][3] = sacc[t][3] * sinv_of(tq1 - tk.y) + bf16hi_f(pu1) + mk.y;
            tm0 = fmaxf(tm0, fmaxf(sacc[t][0], sacc[t][1]));
            tm1 = fmaxf(tm1, fmaxf(sacc[t][2], sacc[t][3]));
        }
        tm0 = fmaxf(tm0, __shfl_xor_sync(0xffffffffu, tm0, 1));
        tm0 = fmaxf(tm0, __shfl_xor_sync(0xffffffffu, tm0, 2));
        tm1 = fmaxf(tm1, __shfl_xor_sync(0xffffffffu, tm1, 1));
        tm1 = fmaxf(tm1, __shfl_xor_sync(0xffffffffu, tm1, 2));
        const float mn0 = fmaxf(m0, tm0), mn1 = fmaxf(m1, tm1);
        const float c0 = ex2f((m0 - mn0) * L2E), c1 = ex2f((m1 - mn1) * L2E);
        m0 = mn0; m1 = mn1;

        float rs0 = 0.0f, rs1 = 0.0f;
        uint32_t aph[4][4], apl[4][4];
#pragma unroll
        for (int t = 0; t < 8; t++) {
            float p00 = ex2f((sacc[t][0] - m0) * L2E);
            float p01 = ex2f((sacc[t][1] - m0) * L2E);
            float p10 = ex2f((sacc[t][2] - m1) * L2E);
            float p11 = ex2f((sacc[t][3] - m1) * L2E);
            rs0 += p00 + p01; rs1 += p10 + p11;
            uint32_t h0 = pack_bf16(p00, p01);
            uint32_t h1 = pack_bf16(p10, p11);
            const int kc2 = t >> 1, hf = (t & 1) << 1;
            aph[kc2][hf] = h0; aph[kc2][hf + 1] = h1;
            apl[kc2][hf] = pack_bf16(p00 - bf16lo_f(h0), p01 - bf16hi_f(h0));
            apl[kc2][hf + 1] = pack_bf16(p10 - bf16lo_f(h1), p11 - bf16hi_f(h1));
        }
        rs0 += __shfl_xor_sync(0xffffffffu, rs0, 1);
        rs0 += __shfl_xor_sync(0xffffffffu, rs0, 2);
        rs1 += __shfl_xor_sync(0xffffffffu, rs1, 1);
        rs1 += __shfl_xor_sync(0xffffffffu, rs1, 2);
        l0 = l0 * c0 + rs0;
        l1 = l1 * c1 + rs1;
#pragma unroll
        for (int t = 0; t < 8; t++) {
            oacc[t][0] *= c0; oacc[t][1] *= c0;
            oacc[t][2] *= c1; oacc[t][3] *= c1;
        }

        // ctx: O += P * V
#pragma unroll
        for (int kc2 = 0; kc2 < 4; kc2++) {
            uint32_t vfh[8][2], vfl[8][2];
#pragma unroll
            for (int dnb = 0; dnb < 4; dnb++) {
                uint32_t a = stg + 18432 + ((kc2 << 4) + (lane & 15)) * 144 +
                             ((dnb << 4) + ((lane >> 4) << 3)) * 2;
                LDSM4T(vfh[2 * dnb], vfh[2 * dnb + 1], a);
                LDSM4T(vfl[2 * dnb], vfl[2 * dnb + 1], a + 9216);
            }
#pragma unroll
            for (int t = 0; t < 8; t++) {
                mma16816(oacc[t], aph[kc2], vfh[t]);
                mma16816(oacc[t], aph[kc2], vfl[t]);
                mma16816(oacc[t], apl[kc2], vfh[t]);
            }
        }
        __syncthreads();
    }

    const float inv0 = 1.0f / l0, inv1 = 1.0f / l1;
#pragma unroll
    for (int t = 0; t < 8; t++) {
        const int d = (t << 3) + ((lane & 3) << 1);
        const size_t o0 = ((size_t)(b * Sn + qr0)) * Hn + h * 64 + d;
        const size_t o1 = ((size_t)(b * Sn + qr0 + 8)) * Hn + h * 64 + d;
        float v0 = oacc[t][0] * inv0, v1 = oacc[t][1] * inv0;
        float v2 = oacc[t][2] * inv1, v3 = oacc[t][3] * inv1;
        uint32_t h0 = pack_bf16(v0, v1), h1 = pack_bf16(v2, v3);
        *(uint32_t*)(Ch + o0) = h0;
        *(uint32_t*)(Cl + o0) = pack_bf16(v0 - bf16lo_f(h0), v1 - bf16hi_f(h0));
        *(uint32_t*)(Ch + o1) = h1;
        *(uint32_t*)(Cl + o1) = pack_bf16(v2 - bf16lo_f(h1), v3 - bf16hi_f(h1));
    }
}

// ---------------------------------------------------------------------------
// LayerNorm over H=512; optional bf16 hi/lo outputs.
// ---------------------------------------------------------------------------
__global__ void __launch_bounds__(256) ln_kernel(
    const float* __restrict__ in, const float* __restrict__ g,
    const float* __restrict__ bta, float* __restrict__ out,
    __nv_bfloat16* __restrict__ ho, __nv_bfloat16* __restrict__ lo_)
{
    const size_t base = (size_t)blockIdx.x * Hn;
    const int tid = threadIdx.x;
    __shared__ float sh[8], sh2[8];
    float x0 = in[base + tid], x1 = in[base + tid + 256];
    float s = x0 + x1;
    for (int o = 16; o; o >>= 1) s += __shfl_xor_sync(0xffffffffu, s, o);
    if ((tid & 31) == 0) sh[tid >> 5] = s;
    __syncthreads();
    s = 0.0f;
#pragma unroll
    for (int i = 0; i < 8; i++) s += sh[i];
    const float mean = s * (1.0f / Hn);
    const float d0 = x0 - mean, d1 = x1 - mean;
    float vv = d0 * d0 + d1 * d1;
    for (int o = 16; o; o >>= 1) vv += __shfl_xor_sync(0xffffffffu, vv, o);
    if ((tid & 31) == 0) sh2[tid >> 5] = vv;
    __syncthreads();
    vv = 0.0f;
#pragma unroll
    for (int i = 0; i < 8; i++) vv += sh2[i];
    const float inv = rsqrtf(vv * (1.0f / Hn) + 1e-12f);
    const float y0 = d0 * inv * g[tid] + bta[tid];
    const float y1 = d1 * inv * g[tid + 256] + bta[tid + 256];
    out[base + tid] = y0;
    out[base + tid + 256] = y1;
    if (ho) {
        __nv_bfloat16 h0 = __float2bfloat16(y0);
        __nv_bfloat16 h1 = __float2bfloat16(y1);
        ho[base + tid] = h0;
        ho[base + tid + 256] = h1;
        lo_[base + tid] = __float2bfloat16(y0 - __bfloat162float(h0));
        lo_[base + tid + 256] = __float2bfloat16(y1 - __bfloat162float(h1));
    }
}

// ---------------------------------------------------------------------------
extern "C" void kernel_launch(void* const* d_in, const int* in_sizes, int n_in,
                              void* d_out, int out_size)
{
    (void)in_sizes; (void)n_in; (void)out_size;
    const float* qs   = (const float*)d_in[0];
    const float* mask = (const float*)d_in[1];
    const float* pb   = (const float*)d_in[2];
    const int*   ts   = (const int*)d_in[3];
    const float* wq  = (const float*)d_in[4];  const float* bq  = (const float*)d_in[5];
    const float* wk  = (const float*)d_in[6];  const float* bk  = (const float*)d_in[7];
    const float* wv  = (const float*)d_in[8];  const float* bv  = (const float*)d_in[9];
    const float* wo  = (const float*)d_in[10]; const float* bo  = (const float*)d_in[11];
    const float* l1g = (const float*)d_in[12]; const float* l1b = (const float*)d_in[13];
    const float* wi  = (const float*)d_in[14]; const float* bi  = (const float*)d_in[15];
    const float* wo2 = (const float*)d_in[16]; const float* bo2 = (const float*)d_in[17];
    const float* l2g = (const float*)d_in[18]; const float* l2b = (const float*)d_in[19];

    float *x, *attn, *bqkv;
    cudaGetSymbolAddress((void**)&x,    g_x);
    cudaGetSymbolAddress((void**)&attn, g_attn);
    cudaGetSymbolAddress((void**)&bqkv, g_bqkv);

    __nv_bfloat16 *qkvh, *qkvl, *ch, *cl, *xh, *xl, *th, *tl, *fh, *fl, *pbb;
    cudaGetSymbolAddress((void**)&qkvh, g_qkvh); cudaGetSymbolAddress((void**)&qkvl, g_qkvl);
    cudaGetSymbolAddress((void**)&ch, g_ch); cudaGetSymbolAddress((void**)&cl, g_cl);
    cudaGetSymbolAddress((void**)&xh, g_xh); cudaGetSymbolAddress((void**)&xl, g_xl);
    cudaGetSymbolAddress((void**)&th, g_th); cudaGetSymbolAddress((void**)&tl, g_tl);
    cudaGetSymbolAddress((void**)&fh, g_fh); cudaGetSymbolAddress((void**)&fl, g_fl);
    cudaGetSymbolAddress((void**)&pbb, g_pbb);

    __nv_bfloat16 *wqkvh, *wqkvl, *woh, *wol, *wih, *wil, *w2h, *w2l;
    cudaGetSymbolAddress((void**)&wqkvh, g_wqkvh); cudaGetSymbolAddress((void**)&wqkvl, g_wqkvl);
    cudaGetSymbolAddress((void**)&woh, g_woh); cudaGetSymbolAddress((void**)&wol, g_wol);
    cudaGetSymbolAddress((void**)&wih, g_wih); cudaGetSymbolAddress((void**)&wil, g_wil);
    cudaGetSymbolAddress((void**)&w2h, g_w2h); cudaGetSymbolAddress((void**)&w2l, g_w2l);

    const int HM_SMEM = 2 * STAGE_BYTES;  // 75776
    const int FL_SMEM = 36864 + 2 * FSTG; // 110592
    cudaFuncSetAttribute(hmma_gemm<0>, cudaFuncAttributeMaxDynamicSharedMemorySize, HM_SMEM);
    cudaFuncSetAttribute(hmma_gemm<1>, cudaFuncAttributeMaxDynamicSharedMemorySize, HM_SMEM);
    cudaFuncSetAttribute(hmma_gemm<2>, cudaFuncAttributeMaxDynamicSharedMemorySize, HM_SMEM);
    cudaFuncSetAttribute(flash_kernel, cudaFuncAttributeMaxDynamicSharedMemorySize, FL_SMEM);

    // Precompute: packed/split weights, packed bias, bf16 position bias, x split
    const int WNH = Ln * Hn * Hn, WNF = Ln * Hn * Fn;
    const int PBN = NHn * Sn * Sn;
    split_pack_kernel<<<WNH / 2048, 256>>>(wq, wqkvh, wqkvl, WNH, 0);
    split_pack_kernel<<<WNH / 2048, 256>>>(wk, wqkvh, wqkvl, WNH, 512);
    split_pack_kernel<<<WNH / 2048, 256>>>(wv, wqkvh, wqkvl, WNH, 1024);
    pack_bias_kernel<<<(Ln * QKVS + 255) / 256, 256>>>(bq, bk, bv, bqkv);
    split_kernel<<<WNH / 2048, 256>>>(wo,  woh, wol, WNH);
    split_kernel<<<WNF / 2048, 256>>>(wi,  wih, wil, WNF);
    split_kernel<<<WNF / 2048, 256>>>(wo2, w2h, w2l, WNF);
    cvt_bf16_kernel<<<PBN / 2048, 256>>>(pb, pbb, PBN);
    split_kernel<<<(Mn * Hn) / 2048, 256>>>(qs, xh, xl, Mn * Hn);

    dim3 gqkv(QKVS / 128, Mn / 128);  // (12, 64)
    dim3 gproj(Hn / 128, Mn / 128);   // (4, 64)
    dim3 gff(Fn / 128, Mn / 128);     // (16, 64)
    dim3 gfl(Sn / 128, Bn * NHn);     // (16, 32)

    for (int l = 0; l < Ln; l++) {
        const size_t wOff  = (size_t)l * Hn * Hn;
        const size_t bOff  = (size_t)l * Hn;
        const size_t wiOff = (size_t)l * Hn * Fn;
        const size_t biOff = (size_t)l * Fn;
        const float* xres = (l == 0) ? qs : x;

        hmma_gemm<0><<<gqkv, 256, HM_SMEM>>>(xh, xl,
            wqkvh + (size_t)l * Hn * QKVS, wqkvl + (size_t)l * Hn * QKVS,
            bqkv + l * QKVS, nullptr, nullptr, qkvh, qkvl, Hn, QKVS);

        flash_kernel<<<gfl, 256, FL_SMEM>>>(qkvh, qkvl, ts, pbb, mask, ch, cl);

        hmma_gemm<1><<<gproj, 256, HM_SMEM>>>(ch, cl, woh + wOff, wol + wOff,
                                              bo + bOff, xres, attn, nullptr, nullptr, Hn, Hn);
        ln_kernel<<<Mn, 256>>>(attn, l1g + bOff, l1b + bOff, attn, th, tl);

        hmma_gemm<2><<<gff, 256, HM_SMEM>>>(th, tl, wih + wiOff, wil + wiOff,
                                            bi + biOff, nullptr, nullptr, fh, fl, Hn, Fn);
        hmma_gemm<1><<<gproj, 256, HM_SMEM>>>(fh, fl, w2h + wiOff, w2l + wiOff,
                                              bo2 + bOff, attn, x, nullptr, nullptr, Fn, Hn);

        float* lnout = (l == Ln - 1) ? (float*)d_out : x;
        ln_kernel<<<Mn, 256>>>(x, l2g + bOff, l2b + bOff, lnout,
                               (l == Ln - 1) ? nullptr : xh,
                               (l == Ln - 1) ? nullptr : xl);
    }
}

// round 7
// speedup vs baseline: 2.6531x; 1.0999x over previous
#include <cuda_runtime.h>
#include <cuda_bf16.h>
#include <math.h>
#include <stdint.h>

// Problem constants
#define Bn 4
#define Sn 2048
#define Hn 512
#define NHn 8
#define DHn 64
#define Fn 2048
#define Ln 4
#define Mn (Bn * Sn)  // 8192
#define QKVS 1536
#define L2E 1.4426950408889634f

// ---------------- scratch (device globals; no allocation allowed) ----------
__device__ float g_x[Mn * Hn];
__device__ float g_attn[Mn * Hn];
__device__ float g_sinv[(size_t)Bn * Sn * Sn];          // 67 MB inv-scale

__device__ __nv_bfloat16 g_qkvh[(size_t)Mn * QKVS], g_qkvl[(size_t)Mn * QKVS];
__device__ __nv_bfloat16 g_ch[Mn * Hn], g_cl[Mn * Hn];   // ctx
__device__ __nv_bfloat16 g_xh[Mn * Hn], g_xl[Mn * Hn];
__device__ __nv_bfloat16 g_th[Mn * Hn], g_tl[Mn * Hn];   // attn (post ln1)
__device__ __nv_bfloat16 g_fh[(size_t)Mn * Fn], g_fl[(size_t)Mn * Fn];

// weights hi/lo
__device__ __nv_bfloat16 g_wqkvh[Ln * Hn * QKVS], g_wqkvl[Ln * Hn * QKVS];
__device__ __nv_bfloat16 g_woh[Ln * Hn * Hn], g_wol[Ln * Hn * Hn];
__device__ __nv_bfloat16 g_wih[Ln * Hn * Fn], g_wil[Ln * Hn * Fn];
__device__ __nv_bfloat16 g_w2h[Ln * Fn * Hn], g_w2l[Ln * Fn * Hn];
__device__ float g_bqkv[Ln * QKVS];
__device__ __nv_bfloat16 g_pbb[(size_t)NHn * Sn * Sn];   // bf16 position bias

// ---------------- helpers ---------------------------------------------------
__device__ __forceinline__ uint32_t cvta_smem(const void* p) {
    uint32_t a;
    asm("{ .reg .u64 t; cvta.to.shared.u64 t, %1; cvt.u32.u64 %0, t; }"
        : "=r"(a) : "l"(p));
    return a;
}

#define CP16(dst, src) \
    asm volatile("cp.async.cg.shared.global [%0], [%1], 16;" :: "r"(dst), "l"(src))
#define CP_COMMIT() asm volatile("cp.async.commit_group;" ::: "memory")
#define CP_WAIT0()  asm volatile("cp.async.wait_group 0;" ::: "memory")
#define CP_WAIT1()  asm volatile("cp.async.wait_group 1;" ::: "memory")

#define LDSM4(r, addr)                                                          \
    asm volatile("ldmatrix.sync.aligned.m8n8.x4.shared.b16 {%0,%1,%2,%3}, [%4];"\
        : "=r"((r)[0]), "=r"((r)[1]), "=r"((r)[2]), "=r"((r)[3]) : "r"(addr))
#define LDSM4T(r01, r23, addr)                                                  \
    asm volatile("ldmatrix.sync.aligned.m8n8.x4.trans.shared.b16 {%0,%1,%2,%3}, [%4];"\
        : "=r"((r01)[0]), "=r"((r01)[1]), "=r"((r23)[0]), "=r"((r23)[1]) : "r"(addr))

__device__ __forceinline__ void mma16816(float* c, const uint32_t* a, const uint32_t* b) {
    asm volatile(
        "mma.sync.aligned.m16n8k16.row.col.f32.bf16.bf16.f32 "
        "{%0,%1,%2,%3}, {%4,%5,%6,%7}, {%8,%9}, {%0,%1,%2,%3};"
        : "+f"(c[0]), "+f"(c[1]), "+f"(c[2]), "+f"(c[3])
        : "r"(a[0]), "r"(a[1]), "r"(a[2]), "r"(a[3]), "r"(b[0]), "r"(b[1]));
}

__device__ __forceinline__ uint32_t pack_bf16(float lo, float hi) {
    uint32_t r;
    asm("cvt.rn.satfinite.bf16x2.f32 %0, %1, %2;" : "=r"(r) : "f"(hi), "f"(lo));
    return r;
}
__device__ __forceinline__ float bf16lo_f(uint32_t u) { return __uint_as_float(u << 16); }
__device__ __forceinline__ float bf16hi_f(uint32_t u) { return __uint_as_float(u & 0xffff0000u); }
__device__ __forceinline__ float ex2f(float x) {
    float y;
    asm("ex2.approx.ftz.f32 %0, %1;" : "=f"(y) : "f"(x));
    return y;
}
__device__ __forceinline__ float rcpf(float x) {
    float y;
    asm("rcp.approx.ftz.f32 %0, %1;" : "=f"(y) : "f"(x));
    return y;
}
// 1/scale = (u + 60000) / (9u + 480000) where u = max(dt_ms, 0)
__device__ __forceinline__ float sinv_of(int dt) {
    float u = fmaxf((float)dt, 0.0f);
    return (u + 60000.0f) * rcpf(fmaf(u, 9.0f, 480000.0f));
}

// smem stage layout for dense GEMM (padded rows: A 80B, B 272B)
#define OFF_AH 0
#define OFF_AL 10240
#define OFF_BH 20480
#define OFF_BL 29184
#define STAGE_BYTES 37888   // x2 stages = 75776

// ---------------------------------------------------------------------------
// Split fp32 -> bf16 hi + lo residual. n multiple of 8.
// ---------------------------------------------------------------------------
__global__ void __launch_bounds__(256) split_kernel(
    const float* __restrict__ x, __nv_bfloat16* __restrict__ h,
    __nv_bfloat16* __restrict__ l, int n)
{
    int i = (blockIdx.x * 256 + threadIdx.x) * 8;
    if (i >= n) return;
    float4 a = *(const float4*)(x + i);
    float4 b = *(const float4*)(x + i + 4);
    float v[8] = {a.x, a.y, a.z, a.w, b.x, b.y, b.z, b.w};
    __align__(16) __nv_bfloat16 hh[8];
    __align__(16) __nv_bfloat16 ll[8];
#pragma unroll
    for (int j = 0; j < 8; j++) {
        hh[j] = __float2bfloat16(v[j]);
        ll[j] = __float2bfloat16(v[j] - __bfloat162float(hh[j]));
    }
    *(uint4*)(h + i) = *(const uint4*)hh;
    *(uint4*)(l + i) = *(const uint4*)ll;
}

// Split + scatter into packed [rows, QKVS] at column offset. srccols=512.
__global__ void __launch_bounds__(256) split_pack_kernel(
    const float* __restrict__ x, __nv_bfloat16* __restrict__ h,
    __nv_bfloat16* __restrict__ l, int n, int coloff)
{
    int i = (blockIdx.x * 256 + threadIdx.x) * 8;
    if (i >= n) return;
    const int row = i >> 9, col = i & 511;
    float4 a = *(const float4*)(x + i);
    float4 b = *(const float4*)(x + i + 4);
    float v[8] = {a.x, a.y, a.z, a.w, b.x, b.y, b.z, b.w};
    __align__(16) __nv_bfloat16 hh[8];
    __align__(16) __nv_bfloat16 ll[8];
#pragma unroll
    for (int j = 0; j < 8; j++) {
        hh[j] = __float2bfloat16(v[j]);
        ll[j] = __float2bfloat16(v[j] - __bfloat162float(hh[j]));
    }
    const size_t d = (size_t)row * QKVS + coloff + col;
    *(uint4*)(h + d) = *(const uint4*)hh;
    *(uint4*)(l + d) = *(const uint4*)ll;
}

__global__ void __launch_bounds__(256) pack_bias_kernel(
    const float* __restrict__ bq, const float* __restrict__ bk,
    const float* __restrict__ bv, float* __restrict__ dst)
{
    int i = blockIdx.x * 256 + threadIdx.x;
    if (i >= Ln * QKVS) return;
    int l = i / QKVS, j = i % QKVS, seg = j >> 9, col = j & 511;
    const float* s = (seg == 0) ? bq : (seg == 1) ? bk : bv;
    dst[i] = s[l * Hn + col];
}

__global__ void __launch_bounds__(256) cvt_bf16_kernel(
    const float* __restrict__ x, __nv_bfloat16* __restrict__ y, int n)
{
    int i = (blockIdx.x * 256 + threadIdx.x) * 8;
    if (i >= n) return;
    float4 a = *(const float4*)(x + i);
    float4 b = *(const float4*)(x + i + 4);
    float v[8] = {a.x, a.y, a.z, a.w, b.x, b.y, b.z, b.w};
    __align__(16) __nv_bfloat16 hh[8];
#pragma unroll
    for (int j = 0; j < 8; j++) hh[j] = __float2bfloat16(v[j]);
    *(uint4*)(y + i) = *(const uint4*)hh;
}

// sinv[b][q][k] = 1/scale. One block per (b,q) row.
__global__ void __launch_bounds__(256) sinv_kernel(
    const int* __restrict__ ts, float* __restrict__ sv)
{
    const int bq = blockIdx.x;
    const int b = bq >> 11;
    const int tq = ts[bq];
    const int* tr = ts + b * Sn;
    float* out = sv + (size_t)bq * Sn;
#pragma unroll
    for (int kk = 0; kk < 2; kk++) {
        int k = (threadIdx.x + (kk << 8)) << 2;
        int4 tk = *(const int4*)(tr + k);
        float4 o;
        o.x = sinv_of(tq - tk.x);
        o.y = sinv_of(tq - tk.y);
        o.z = sinv_of(tq - tk.z);
        o.w = sinv_of(tq - tk.w);
        *(float4*)(out + k) = o;
    }
}

// ---------------------------------------------------------------------------
// HMMA split-bf16 GEMM. CTA 128x128, BK=32, 8 warps, 3 passes.
// EPI 0: bias -> bf16 hi/lo out.  EPI 1: bias + res -> fp32 out.
// EPI 2: bias + GELU -> bf16 hi/lo out.
// ---------------------------------------------------------------------------
template <int EPI>
__global__ void __launch_bounds__(256) hmma_gemm(
    const __nv_bfloat16* __restrict__ Ahp, const __nv_bfloat16* __restrict__ Alp,
    const __nv_bfloat16* __restrict__ Bhp, const __nv_bfloat16* __restrict__ Blp,
    const float* __restrict__ bias, const float* __restrict__ res,
    float* __restrict__ C, __nv_bfloat16* __restrict__ Cho,
    __nv_bfloat16* __restrict__ Clo, int K, int N)
{
    extern __shared__ char smem[];
    const uint32_t sb = cvta_smem(smem);
    const int tid = threadIdx.x, lane = tid & 31, warp = tid >> 5;
    const int m0 = blockIdx.y << 7, n0 = blockIdx.x << 7;
    const int wm0 = (warp >> 2) << 6, wn0 = (warp & 3) << 5;

    const int ar = tid >> 2, ac = tid & 3;
    const int br = tid >> 4, bc = tid & 15;

    auto load_stage = [&](int st, int kc) {
        const int k0 = kc << 5;
        const uint32_t s = sb + st * STAGE_BYTES;
        const size_t aoff0 = (size_t)(m0 + ar) * K + k0 + ac * 8;
        const size_t aoff1 = (size_t)(m0 + ar + 64) * K + k0 + ac * 8;
        CP16(s + OFF_AH + ar * 80 + ac * 16, Ahp + aoff0);
        CP16(s + OFF_AH + (ar + 64) * 80 + ac * 16, Ahp + aoff1);
        CP16(s + OFF_AL + ar * 80 + ac * 16, Alp + aoff0);
        CP16(s + OFF_AL + (ar + 64) * 80 + ac * 16, Alp + aoff1);
        const size_t boff0 = (size_t)(k0 + br) * N + n0 + bc * 8;
        const size_t boff1 = (size_t)(k0 + br + 16) * N + n0 + bc * 8;
        CP16(s + OFF_BH + br * 272 + bc * 16, Bhp + boff0);
        CP16(s + OFF_BH + (br + 16) * 272 + bc * 16, Bhp + boff1);
        CP16(s + OFF_BL + br * 272 + bc * 16, Blp + boff0);
        CP16(s + OFF_BL + (br + 16) * 272 + bc * 16, Blp + boff1);
        CP_COMMIT();
    };

    float acc[4][4][4];
#pragma unroll
    for (int i = 0; i < 4; i++)
#pragma unroll
        for (int j = 0; j < 4; j++)
#pragma unroll
            for (int r = 0; r < 4; r++) acc[i][j][r] = 0.0f;

    const int nch = K >> 5;
    load_stage(0, 0);

    for (int kc = 0; kc < nch; kc++) {
        const int cur = kc & 1;
        CP_WAIT0();
        __syncthreads();
        if (kc + 1 < nch) load_stage(cur ^ 1, kc + 1);

        const uint32_t s = sb + cur * STAGE_BYTES;
#pragma unroll
        for (int ks = 0; ks < 2; ks++) {
            uint32_t a[2][4][4];
            uint32_t b[2][4][2];
            const uint32_t aoff =
                (wm0 + (lane & 15)) * 80 + ((ks << 4) + ((lane >> 4) << 3)) * 2;
#pragma unroll
            for (int v = 0; v < 2; v++) {
                const uint32_t base = s + (v ? OFF_AL : OFF_AH) + aoff;
#pragma unroll
                for (int mt = 0; mt < 4; mt++) LDSM4(a[v][mt], base + mt * (16 * 80));
            }
            const uint32_t boff =
                ((ks << 4) + (lane & 15)) * 272 + (wn0 + ((lane >> 4) << 3)) * 2;
#pragma unroll
            for (int v = 0; v < 2; v++) {
                const uint32_t base = s + (v ? OFF_BL : OFF_BH) + boff;
                LDSM4T(b[v][0], b[v][1], base);
                LDSM4T(b[v][2], b[v][3], base + 32);
            }
#pragma unroll
            for (int mt = 0; mt < 4; mt++)
#pragma unroll
                for (int nt = 0; nt < 4; nt++) mma16816(acc[mt][nt], a[0][mt], b[0][nt]);
#pragma unroll
            for (int mt = 0; mt < 4; mt++)
#pragma unroll
                for (int nt = 0; nt < 4; nt++) mma16816(acc[mt][nt], a[0][mt], b[1][nt]);
#pragma unroll
            for (int mt = 0; mt < 4; mt++)
#pragma unroll
                for (int nt = 0; nt < 4; nt++) mma16816(acc[mt][nt], a[1][mt], b[0][nt]);
        }
    }

#pragma unroll
    for (int mt = 0; mt < 4; mt++) {
        const int m = m0 + wm0 + mt * 16 + (lane >> 2);
#pragma unroll
        for (int nt = 0; nt < 4; nt++) {
            const int n = n0 + wn0 + nt * 8 + (lane & 3) * 2;
            float2 bv = *(const float2*)(bias + n);
            float o0 = acc[mt][nt][0] + bv.x;
            float o1 = acc[mt][nt][1] + bv.y;
            float o2 = acc[mt][nt][2] + bv.x;
            float o3 = acc[mt][nt][3] + bv.y;
            if (EPI == 1) {
                float2 r0 = *(const float2*)(res + (size_t)m * N + n);
                float2 r1 = *(const float2*)(res + (size_t)(m + 8) * N + n);
                o0 += r0.x; o1 += r0.y; o2 += r1.x; o3 += r1.y;
                *(float2*)(C + (size_t)m * N + n) = make_float2(o0, o1);
                *(float2*)(C + (size_t)(m + 8) * N + n) = make_float2(o2, o3);
            } else {
                if (EPI == 2) {
                    o0 = 0.5f * o0 * (1.0f + erff(o0 * 0.7071067811865475f));
                    o1 = 0.5f * o1 * (1.0f + erff(o1 * 0.7071067811865475f));
                    o2 = 0.5f * o2 * (1.0f + erff(o2 * 0.7071067811865475f));
                    o3 = 0.5f * o3 * (1.0f + erff(o3 * 0.7071067811865475f));
                }
                uint32_t h0 = pack_bf16(o0, o1);
                uint32_t h1 = pack_bf16(o2, o3);
                *(uint32_t*)(Cho + (size_t)m * N + n) = h0;
                *(uint32_t*)(Clo + (size_t)m * N + n) =
                    pack_bf16(o0 - bf16lo_f(h0), o1 - bf16hi_f(h0));
                *(uint32_t*)(Cho + (size_t)(m + 8) * N + n) = h1;
                *(uint32_t*)(Clo + (size_t)(m + 8) * N + n) =
                    pack_bf16(o2 - bf16lo_f(h1), o3 - bf16hi_f(h1));
            }
        }
    }
}

// ---------------------------------------------------------------------------
// Flash attention over packed QKV [M, 1536]. Per CTA one (b,h) x 128 q-rows.
// Register-lean variant: Q frags reloaded from smem each iter; K/V frags
// loaded in 8-reg groups. Targets 2 CTAs/SM.
// ---------------------------------------------------------------------------
#define FSTG 36864
__global__ void __launch_bounds__(256, 2) flash_kernel(
    const __nv_bfloat16* __restrict__ QKVh, const __nv_bfloat16* __restrict__ QKVl,
    const float* __restrict__ sinv, const __nv_bfloat16* __restrict__ pbb,
    const float* __restrict__ mask,
    __nv_bfloat16* __restrict__ Ch, __nv_bfloat16* __restrict__ Cl)
{
    extern __shared__ char smem[];
    const uint32_t sb = cvta_smem(smem);
    const int tid = threadIdx.x, lane = tid & 31, warp = tid >> 5;
    const int qb = blockIdx.x << 7;
    const int bh = blockIdx.y, b = bh & 3, h = bh >> 2;
    const uint32_t sQ = sb;
    const uint32_t sKV = sb + 36864;

    // Q + stage 0
#pragma unroll
    for (int i = 0; i < 4; i++) {
        int idx = tid + (i << 8);
        int r = idx >> 3, c = idx & 7;
        size_t off = ((size_t)(b * Sn + qb + r)) * QKVS + h * 64 + c * 8;
        CP16(sQ + r * 144 + c * 16, QKVh + off);
        CP16(sQ + 18432 + r * 144 + c * 16, QKVl + off);
    }
#pragma unroll
    for (int i = 0; i < 2; i++) {
        int idx = tid + (i << 8);
        int r = idx >> 3, c = idx & 7;
        size_t off = ((size_t)(b * Sn + r)) * QKVS + h * 64 + c * 8;
        uint32_t d = sKV + r * 144 + c * 16;
        CP16(d, QKVh + off + 512); CP16(d + 9216, QKVl + off + 512);
        CP16(d + 18432, QKVh + off + 1024); CP16(d + 27648, QKVl + off + 1024);
    }
    CP_COMMIT();

    const int qr0 = qb + (warp << 4) + (lane >> 2);
    const float* sv0 = sinv + ((size_t)(b * Sn + qr0)) * Sn;
    const float* sv1 = sv0 + (size_t)8 * Sn;
    const __nv_bfloat16* pb0 = pbb + ((size_t)(h * Sn + qr0)) * Sn;
    const __nv_bfloat16* pb1 = pb0 + (size_t)8 * Sn;
    const float* mrow = mask + b * Sn;

    float oacc[8][4];
#pragma unroll
    for (int t = 0; t < 8; t++)
#pragma unroll
        for (int r = 0; r < 4; r++) oacc[t][r] = 0.0f;
    float m0 = -1e30f, m1 = -1e30f, l0 = 0.0f, l1 = 0.0f;

    for (int it = 0; it < 32; it++) {
        if (it + 1 < 32) {
            const uint32_t s = sKV + ((it + 1) & 1) * FSTG;
            const int k0n = (it + 1) << 6;
#pragma unroll
            for (int i = 0; i < 2; i++) {
                int idx = tid + (i << 8);
                int r = idx >> 3, c = idx & 7;
                size_t off = ((size_t)(b * Sn + k0n + r)) * QKVS + h * 64 + c * 8;
                uint32_t d = s + r * 144 + c * 16;
                CP16(d, QKVh + off + 512); CP16(d + 9216, QKVl + off + 512);
                CP16(d + 18432, QKVh + off + 1024); CP16(d + 27648, QKVl + off + 1024);
            }
        }
        CP_COMMIT();
        CP_WAIT1();
        __syncthreads();

        const uint32_t stg = sKV + (it & 1) * FSTG;
        float sacc[8][4];
#pragma unroll
        for (int t = 0; t < 8; t++)
#pragma unroll
            for (int r = 0; r < 4; r++) sacc[t][r] = 0.0f;

        // S = Q K^T (3-pass), Q frags from persistent smem tile
#pragma unroll
        for (int kc = 0; kc < 4; kc++) {
            uint32_t aqh[4], aql[4];
            const uint32_t qa = sQ + ((warp << 4) + (lane & 15)) * 144 +
                                ((kc << 4) + ((lane >> 4) << 3)) * 2;
            LDSM4(aqh, qa);
            LDSM4(aql, qa + 18432);
#pragma unroll
            for (int nb = 0; nb < 4; nb++) {
                uint32_t kbh[4], kbl[4];
                const uint32_t ka = stg + ((nb << 4) + (lane & 15)) * 144 +
                                    ((kc << 4) + ((lane >> 4) << 3)) * 2;
                LDSM4(kbh, ka);
                LDSM4(kbl, ka + 9216);
#pragma unroll
                for (int tt = 0; tt < 2; tt++) {
                    const int t = (nb << 1) + tt;
                    uint32_t bh_[2] = {kbh[tt], kbh[tt + 2]};
                    uint32_t bl_[2] = {kbl[tt], kbl[tt + 2]};
                    mma16816(sacc[t], aqh, bh_);
                    mma16816(sacc[t], aqh, bl_);
                    mma16816(sacc[t], aql, bh_);
                }
            }
        }

        // epilogue: precomputed sinv + pb(bf16) + mask, online softmax
        const int k0 = it << 6;
        float tm0 = -1e30f, tm1 = -1e30f;
#pragma unroll
        for (int t = 0; t < 8; t++) {
            const int n = k0 + (t << 3) + ((lane & 3) << 1);
            float2 s0 = *(const float2*)(sv0 + n);
            float2 s1 = *(const float2*)(sv1 + n);
            float2 mk = *(const float2*)(mrow + n);
            uint32_t pu0 = *(const uint32_t*)(pb0 + n);
            uint32_t pu1 = *(const uint32_t*)(pb1 + n);
            sacc[t][0] = fmaf(sacc[t][0], s0.x, bf16lo_f(pu0) + mk.x);
            sacc[t][1] = fmaf(sacc[t][1], s0.y, bf16hi_f(pu0) + mk.y);
            sacc[t][2] = fmaf(sacc[t][2], s1.x, bf16lo_f(pu1) + mk.x);
            sacc[t][3] = fmaf(sacc[t][3], s1.y, bf16hi_f(pu1) + mk.y);
            tm0 = fmaxf(tm0, fmaxf(sacc[t][0], sacc[t][1]));
            tm1 = fmaxf(tm1, fmaxf(sacc[t][2], sacc[t][3]));
        }
        tm0 = fmaxf(tm0, __shfl_xor_sync(0xffffffffu, tm0, 1));
        tm0 = fmaxf(tm0, __shfl_xor_sync(0xffffffffu, tm0, 2));
        tm1 = fmaxf(tm1, __shfl_xor_sync(0xffffffffu, tm1, 1));
        tm1 = fmaxf(tm1, __shfl_xor_sync(0xffffffffu, tm1, 2));
        const float mn0 = fmaxf(m0, tm0), mn1 = fmaxf(m1, tm1);
        const float c0 = ex2f((m0 - mn0) * L2E), c1 = ex2f((m1 - mn1) * L2E);
        m0 = mn0; m1 = mn1;

        float rs0 = 0.0f, rs1 = 0.0f;
        uint32_t aph[4][4], apl[4][4];
#pragma unroll
        for (int t = 0; t < 8; t++) {
            float p00 = ex2f((sacc[t][0] - m0) * L2E);
            float p01 = ex2f((sacc[t][1] - m0) * L2E);
            float p10 = ex2f((sacc[t][2] - m1) * L2E);
            float p11 = ex2f((sacc[t][3] - m1) * L2E);
            rs0 += p00 + p01; rs1 += p10 + p11;
            uint32_t h0 = pack_bf16(p00, p01);
            uint32_t h1 = pack_bf16(p10, p11);
            const int kc2 = t >> 1, hf = (t & 1) << 1;
            aph[kc2][hf] = h0; aph[kc2][hf + 1] = h1;
            apl[kc2][hf] = pack_bf16(p00 - bf16lo_f(h0), p01 - bf16hi_f(h0));
            apl[kc2][hf + 1] = pack_bf16(p10 - bf16lo_f(h1), p11 - bf16hi_f(h1));
        }
        rs0 += __shfl_xor_sync(0xffffffffu, rs0, 1);
        rs0 += __shfl_xor_sync(0xffffffffu, rs0, 2);
        rs1 += __shfl_xor_sync(0xffffffffu, rs1, 1);
        rs1 += __shfl_xor_sync(0xffffffffu, rs1, 2);
        l0 = l0 * c0 + rs0;
        l1 = l1 * c1 + rs1;
#pragma unroll
        for (int t = 0; t < 8; t++) {
            oacc[t][0] *= c0; oacc[t][1] *= c0;
            oacc[t][2] *= c1; oacc[t][3] *= c1;
        }

        // ctx: O += P * V  (V frags in 8-reg groups)
#pragma unroll
        for (int kc2 = 0; kc2 < 4; kc2++) {
#pragma unroll
            for (int dnb = 0; dnb < 4; dnb++) {
                uint32_t vfh[2][2], vfl[2][2];
                const uint32_t va = stg + 18432 +
                    ((kc2 << 4) + (lane & 15)) * 144 +
                    ((dnb << 4) + ((lane >> 4) << 3)) * 2;
                LDSM4T(vfh[0], vfh[1], va);
                LDSM4T(vfl[0], vfl[1], va + 9216);
#pragma unroll
                for (int tt = 0; tt < 2; tt++) {
                    const int t = (dnb << 1) + tt;
                    mma16816(oacc[t], aph[kc2], vfh[tt]);
                    mma16816(oacc[t], aph[kc2], vfl[tt]);
                    mma16816(oacc[t], apl[kc2], vfh[tt]);
                }
            }
        }
        __syncthreads();
    }

    const float inv0 = 1.0f / l0, inv1 = 1.0f / l1;
#pragma unroll
    for (int t = 0; t < 8; t++) {
        const int d = (t << 3) + ((lane & 3) << 1);
        const size_t o0 = ((size_t)(b * Sn + qr0)) * Hn + h * 64 + d;
        const size_t o1 = ((size_t)(b * Sn + qr0 + 8)) * Hn + h * 64 + d;
        float v0 = oacc[t][0] * inv0, v1 = oacc[t][1] * inv0;
        float v2 = oacc[t][2] * inv1, v3 = oacc[t][3] * inv1;
        uint32_t h0 = pack_bf16(v0, v1), h1 = pack_bf16(v2, v3);
        *(uint32_t*)(Ch + o0) = h0;
        *(uint32_t*)(Cl + o0) = pack_bf16(v0 - bf16lo_f(h0), v1 - bf16hi_f(h0));
        *(uint32_t*)(Ch + o1) = h1;
        *(uint32_t*)(Cl + o1) = pack_bf16(v2 - bf16lo_f(h1), v3 - bf16hi_f(h1));
    }
}

// ---------------------------------------------------------------------------
// LayerNorm over H=512; optional bf16 hi/lo outputs.
// ---------------------------------------------------------------------------
__global__ void __launch_bounds__(256) ln_kernel(
    const float* __restrict__ in, const float* __restrict__ g,
    const float* __restrict__ bta, float* __restrict__ out,
    __nv_bfloat16* __restrict__ ho, __nv_bfloat16* __restrict__ lo_)
{
    const size_t base = (size_t)blockIdx.x * Hn;
    const int tid = threadIdx.x;
    __shared__ float sh[8], sh2[8];
    float x0 = in[base + tid], x1 = in[base + tid + 256];
    float s = x0 + x1;
    for (int o = 16; o; o >>= 1) s += __shfl_xor_sync(0xffffffffu, s, o);
    if ((tid & 31) == 0) sh[tid >> 5] = s;
    __syncthreads();
    s = 0.0f;
#pragma unroll
    for (int i = 0; i < 8; i++) s += sh[i];
    const float mean = s * (1.0f / Hn);
    const float d0 = x0 - mean, d1 = x1 - mean;
    float vv = d0 * d0 + d1 * d1;
    for (int o = 16; o; o >>= 1) vv += __shfl_xor_sync(0xffffffffu, vv, o);
    if ((tid & 31) == 0) sh2[tid >> 5] = vv;
    __syncthreads();
    vv = 0.0f;
#pragma unroll
    for (int i = 0; i < 8; i++) vv += sh2[i];
    const float inv = rsqrtf(vv * (1.0f / Hn) + 1e-12f);
    const float y0 = d0 * inv * g[tid] + bta[tid];
    const float y1 = d1 * inv * g[tid + 256] + bta[tid + 256];
    out[base + tid] = y0;
    out[base + tid + 256] = y1;
    if (ho) {
        __nv_bfloat16 h0 = __float2bfloat16(y0);
        __nv_bfloat16 h1 = __float2bfloat16(y1);
        ho[base + tid] = h0;
        ho[base + tid + 256] = h1;
        lo_[base + tid] = __float2bfloat16(y0 - __bfloat162float(h0));
        lo_[base + tid + 256] = __float2bfloat16(y1 - __bfloat162float(h1));
    }
}

// ---------------------------------------------------------------------------
extern "C" void kernel_launch(void* const* d_in, const int* in_sizes, int n_in,
                              void* d_out, int out_size)
{
    (void)in_sizes; (void)n_in; (void)out_size;
    const float* qs   = (const float*)d_in[0];
    const float* mask = (const float*)d_in[1];
    const float* pb   = (const float*)d_in[2];
    const int*   ts   = (const int*)d_in[3];
    const float* wq  = (const float*)d_in[4];  const float* bq  = (const float*)d_in[5];
    const float* wk  = (const float*)d_in[6];  const float* bk  = (const float*)d_in[7];
    const float* wv  = (const float*)d_in[8];  const float* bv  = (const float*)d_in[9];
    const float* wo  = (const float*)d_in[10]; const float* bo  = (const float*)d_in[11];
    const float* l1g = (const float*)d_in[12]; const float* l1b = (const float*)d_in[13];
    const float* wi  = (const float*)d_in[14]; const float* bi  = (const float*)d_in[15];
    const float* wo2 = (const float*)d_in[16]; const float* bo2 = (const float*)d_in[17];
    const float* l2g = (const float*)d_in[18]; const float* l2b = (const float*)d_in[19];

    float *x, *attn, *bqkv, *sinvp;
    cudaGetSymbolAddress((void**)&x,    g_x);
    cudaGetSymbolAddress((void**)&attn, g_attn);
    cudaGetSymbolAddress((void**)&bqkv, g_bqkv);
    cudaGetSymbolAddress((void**)&sinvp, g_sinv);

    __nv_bfloat16 *qkvh, *qkvl, *ch, *cl, *xh, *xl, *th, *tl, *fh, *fl, *pbb;
    cudaGetSymbolAddress((void**)&qkvh, g_qkvh); cudaGetSymbolAddress((void**)&qkvl, g_qkvl);
    cudaGetSymbolAddress((void**)&ch, g_ch); cudaGetSymbolAddress((void**)&cl, g_cl);
    cudaGetSymbolAddress((void**)&xh, g_xh); cudaGetSymbolAddress((void**)&xl, g_xl);
    cudaGetSymbolAddress((void**)&th, g_th); cudaGetSymbolAddress((void**)&tl, g_tl);
    cudaGetSymbolAddress((void**)&fh, g_fh); cudaGetSymbolAddress((void**)&fl, g_fl);
    cudaGetSymbolAddress((void**)&pbb, g_pbb);

    __nv_bfloat16 *wqkvh, *wqkvl, *woh, *wol, *wih, *wil, *w2h, *w2l;
    cudaGetSymbolAddress((void**)&wqkvh, g_wqkvh); cudaGetSymbolAddress((void**)&wqkvl, g_wqkvl);
    cudaGetSymbolAddress((void**)&woh, g_woh); cudaGetSymbolAddress((void**)&wol, g_wol);
    cudaGetSymbolAddress((void**)&wih, g_wih); cudaGetSymbolAddress((void**)&wil, g_wil);
    cudaGetSymbolAddress((void**)&w2h, g_w2h); cudaGetSymbolAddress((void**)&w2l, g_w2l);

    const int HM_SMEM = 2 * STAGE_BYTES;  // 75776
    const int FL_SMEM = 36864 + 2 * FSTG; // 110592
    cudaFuncSetAttribute(hmma_gemm<0>, cudaFuncAttributeMaxDynamicSharedMemorySize, HM_SMEM);
    cudaFuncSetAttribute(hmma_gemm<1>, cudaFuncAttributeMaxDynamicSharedMemorySize, HM_SMEM);
    cudaFuncSetAttribute(hmma_gemm<2>, cudaFuncAttributeMaxDynamicSharedMemorySize, HM_SMEM);
    cudaFuncSetAttribute(flash_kernel, cudaFuncAttributeMaxDynamicSharedMemorySize, FL_SMEM);

    // Precompute: packed/split weights, bias, bf16 pb, sinv, x split
    const int WNH = Ln * Hn * Hn, WNF = Ln * Hn * Fn;
    const int PBN = NHn * Sn * Sn;
    split_pack_kernel<<<WNH / 2048, 256>>>(wq, wqkvh, wqkvl, WNH, 0);
    split_pack_kernel<<<WNH / 2048, 256>>>(wk, wqkvh, wqkvl, WNH, 512);
    split_pack_kernel<<<WNH / 2048, 256>>>(wv, wqkvh, wqkvl, WNH, 1024);
    pack_bias_kernel<<<(Ln * QKVS + 255) / 256, 256>>>(bq, bk, bv, bqkv);
    split_kernel<<<WNH / 2048, 256>>>(wo,  woh, wol, WNH);
    split_kernel<<<WNF / 2048, 256>>>(wi,  wih, wil, WNF);
    split_kernel<<<WNF / 2048, 256>>>(wo2, w2h, w2l, WNF);
    cvt_bf16_kernel<<<PBN / 2048, 256>>>(pb, pbb, PBN);
    sinv_kernel<<<Bn * Sn, 256>>>(ts, sinvp);
    split_kernel<<<(Mn * Hn) / 2048, 256>>>(qs, xh, xl, Mn * Hn);

    dim3 gqkv(QKVS / 128, Mn / 128);  // (12, 64)
    dim3 gproj(Hn / 128, Mn / 128);   // (4, 64)
    dim3 gff(Fn / 128, Mn / 128);     // (16, 64)
    dim3 gfl(Sn / 128, Bn * NHn);     // (16, 32)

    for (int l = 0; l < Ln; l++) {
        const size_t wOff  = (size_t)l * Hn * Hn;
        const size_t bOff  = (size_t)l * Hn;
        const size_t wiOff = (size_t)l * Hn * Fn;
        const size_t biOff = (size_t)l * Fn;
        const float* xres = (l == 0) ? qs : x;

        hmma_gemm<0><<<gqkv, 256, HM_SMEM>>>(xh, xl,
            wqkvh + (size_t)l * Hn * QKVS, wqkvl + (size_t)l * Hn * QKVS,
            bqkv + l * QKVS, nullptr, nullptr, qkvh, qkvl, Hn, QKVS);

        flash_kernel<<<gfl, 256, FL_SMEM>>>(qkvh, qkvl, sinvp, pbb, mask, ch, cl);

        hmma_gemm<1><<<gproj, 256, HM_SMEM>>>(ch, cl, woh + wOff, wol + wOff,
                                              bo + bOff, xres, attn, nullptr, nullptr, Hn, Hn);
        ln_kernel<<<Mn, 256>>>(attn, l1g + bOff, l1b + bOff, attn, th, tl);

        hmma_gemm<2><<<gff, 256, HM_SMEM>>>(th, tl, wih + wiOff, wil + wiOff,
                                            bi + biOff, nullptr, nullptr, fh, fl, Hn, Fn);
        hmma_gemm<1><<<gproj, 256, HM_SMEM>>>(fh, fl, w2h + wiOff, w2l + wiOff,
                                              bo2 + bOff, attn, x, nullptr, nullptr, Fn, Hn);

        float* lnout = (l == Ln - 1) ? (float*)d_out : x;
        ln_kernel<<<Mn, 256>>>(x, l2g + bOff, l2b + bOff, lnout,
                               (l == Ln - 1) ? nullptr : xh,
                               (l == Ln - 1) ? nullptr : xl);
    }
}

// round 8
// speedup vs baseline: 2.6561x; 1.0011x over previous
#include <cuda_runtime.h>
#include <cuda_bf16.h>
#include <math.h>
#include <stdint.h>

// Problem constants
#define Bn 4
#define Sn 2048
#define Hn 512
#define NHn 8
#define DHn 64
#define Fn 2048
#define Ln 4
#define Mn (Bn * Sn)  // 8192
#define QKVS 1536
#define L2E 1.4426950408889634f

// ---------------- scratch (device globals; no allocation allowed) ----------
__device__ float g_x[Mn * Hn];
__device__ float g_attn[Mn * Hn];
__device__ float g_sinv[(size_t)Bn * Sn * Sn];          // 67 MB inv-scale

__device__ __nv_bfloat16 g_qkvh[(size_t)Mn * QKVS], g_qkvl[(size_t)Mn * QKVS];
__device__ __nv_bfloat16 g_ch[Mn * Hn], g_cl[Mn * Hn];   // ctx
__device__ __nv_bfloat16 g_xh[Mn * Hn], g_xl[Mn * Hn];
__device__ __nv_bfloat16 g_th[Mn * Hn], g_tl[Mn * Hn];   // attn (post ln1)
__device__ __nv_bfloat16 g_fh[(size_t)Mn * Fn], g_fl[(size_t)Mn * Fn];

// weights hi/lo
__device__ __nv_bfloat16 g_wqkvh[Ln * Hn * QKVS], g_wqkvl[Ln * Hn * QKVS];
__device__ __nv_bfloat16 g_woh[Ln * Hn * Hn], g_wol[Ln * Hn * Hn];
__device__ __nv_bfloat16 g_wih[Ln * Hn * Fn], g_wil[Ln * Hn * Fn];
__device__ __nv_bfloat16 g_w2h[Ln * Fn * Hn], g_w2l[Ln * Fn * Hn];
__device__ float g_bqkv[Ln * QKVS];
__device__ __nv_bfloat16 g_pbb[(size_t)NHn * Sn * Sn];   // bf16 position bias

// ---------------- helpers ---------------------------------------------------
__device__ __forceinline__ uint32_t cvta_smem(const void* p) {
    uint32_t a;
    asm("{ .reg .u64 t; cvta.to.shared.u64 t, %1; cvt.u32.u64 %0, t; }"
        : "=r"(a) : "l"(p));
    return a;
}

#define CP16(dst, src) \
    asm volatile("cp.async.cg.shared.global [%0], [%1], 16;" :: "r"(dst), "l"(src))
#define CP_COMMIT() asm volatile("cp.async.commit_group;" ::: "memory")
#define CP_WAIT0()  asm volatile("cp.async.wait_group 0;" ::: "memory")
#define CP_WAIT1()  asm volatile("cp.async.wait_group 1;" ::: "memory")

#define LDSM4(r, addr)                                                          \
    asm volatile("ldmatrix.sync.aligned.m8n8.x4.shared.b16 {%0,%1,%2,%3}, [%4];"\
        : "=r"((r)[0]), "=r"((r)[1]), "=r"((r)[2]), "=r"((r)[3]) : "r"(addr))
#define LDSM4T(r01, r23, addr)                                                  \
    asm volatile("ldmatrix.sync.aligned.m8n8.x4.trans.shared.b16 {%0,%1,%2,%3}, [%4];"\
        : "=r"((r01)[0]), "=r"((r01)[1]), "=r"((r23)[0]), "=r"((r23)[1]) : "r"(addr))

__device__ __forceinline__ void mma16816(float* c, const uint32_t* a, const uint32_t* b) {
    asm volatile(
        "mma.sync.aligned.m16n8k16.row.col.f32.bf16.bf16.f32 "
        "{%0,%1,%2,%3}, {%4,%5,%6,%7}, {%8,%9}, {%0,%1,%2,%3};"
        : "+f"(c[0]), "+f"(c[1]), "+f"(c[2]), "+f"(c[3])
        : "r"(a[0]), "r"(a[1]), "r"(a[2]), "r"(a[3]), "r"(b[0]), "r"(b[1]));
}

__device__ __forceinline__ uint32_t pack_bf16(float lo, float hi) {
    uint32_t r;
    asm("cvt.rn.satfinite.bf16x2.f32 %0, %1, %2;" : "=r"(r) : "f"(hi), "f"(lo));
    return r;
}
__device__ __forceinline__ float bf16lo_f(uint32_t u) { return __uint_as_float(u << 16); }
__device__ __forceinline__ float bf16hi_f(uint32_t u) { return __uint_as_float(u & 0xffff0000u); }
__device__ __forceinline__ float ex2f(float x) {
    float y;
    asm("ex2.approx.ftz.f32 %0, %1;" : "=f"(y) : "f"(x));
    return y;
}
__device__ __forceinline__ float rcpf(float x) {
    float y;
    asm("rcp.approx.ftz.f32 %0, %1;" : "=f"(y) : "f"(x));
    return y;
}
// 1/scale = (u + 60000) / (9u + 480000) where u = max(dt_ms, 0)
__device__ __forceinline__ float sinv_of(int dt) {
    float u = fmaxf((float)dt, 0.0f);
    return (u + 60000.0f) * rcpf(fmaf(u, 9.0f, 480000.0f));
}

// split 8 fp32 -> hi/lo bf16x8 and store
__device__ __forceinline__ void split8_store(
    const float* __restrict__ src, __nv_bfloat16* __restrict__ h,
    __nv_bfloat16* __restrict__ l)
{
    float4 a = *(const float4*)src;
    float4 b = *(const float4*)(src + 4);
    float v[8] = {a.x, a.y, a.z, a.w, b.x, b.y, b.z, b.w};
    __align__(16) __nv_bfloat16 hh[8];
    __align__(16) __nv_bfloat16 ll[8];
#pragma unroll
    for (int j = 0; j < 8; j++) {
        hh[j] = __float2bfloat16(v[j]);
        ll[j] = __float2bfloat16(v[j] - __bfloat162float(hh[j]));
    }
    *(uint4*)h = *(const uint4*)hh;
    *(uint4*)l = *(const uint4*)ll;
}

// smem stage layout for dense GEMM (padded rows: A 80B, B 272B)
#define OFF_AH 0
#define OFF_AL 10240
#define OFF_BH 20480
#define OFF_BL 29184
#define STAGE_BYTES 37888   // x2 stages = 75776

// ---------------------------------------------------------------------------
// Standalone split (activations at graph entry)
// ---------------------------------------------------------------------------
__global__ void __launch_bounds__(256) split_kernel(
    const float* __restrict__ x, __nv_bfloat16* __restrict__ h,
    __nv_bfloat16* __restrict__ l, int n)
{
    int i = (blockIdx.x * 256 + threadIdx.x) * 8;
    if (i >= n) return;
    split8_store(x + i, h + i, l + i);
}

__global__ void __launch_bounds__(256) cvt_bf16_kernel(
    const float* __restrict__ x, __nv_bfloat16* __restrict__ y, int n)
{
    int i = (blockIdx.x * 256 + threadIdx.x) * 8;
    if (i >= n) return;
    float4 a = *(const float4*)(x + i);
    float4 b = *(const float4*)(x + i + 4);
    float v[8] = {a.x, a.y, a.z, a.w, b.x, b.y, b.z, b.w};
    __align__(16) __nv_bfloat16 hh[8];
#pragma unroll
    for (int j = 0; j < 8; j++) hh[j] = __float2bfloat16(v[j]);
    *(uint4*)(y + i) = *(const uint4*)hh;
}

// sinv[b][q][k] = 1/scale. One block per (b,q) row.
__global__ void __launch_bounds__(256) sinv_kernel(
    const int* __restrict__ ts, float* __restrict__ sv)
{
    const int bq = blockIdx.x;
    const int b = bq >> 11;
    const int tq = ts[bq];
    const int* tr = ts + b * Sn;
    float* out = sv + (size_t)bq * Sn;
#pragma unroll
    for (int kk = 0; kk < 2; kk++) {
        int k = (threadIdx.x + (kk << 8)) << 2;
        int4 tk = *(const int4*)(tr + k);
        float4 o;
        o.x = sinv_of(tq - tk.x);
        o.y = sinv_of(tq - tk.y);
        o.z = sinv_of(tq - tk.z);
        o.w = sinv_of(tq - tk.w);
        *(float4*)(out + k) = o;
    }
}

// ---------------------------------------------------------------------------
// Mega weight-prep: all splits + qkv pack + bias pack in one launch.
// Block ranges: [0,512) wq-pack, [512,1024) wk-pack, [1024,1536) wv-pack,
// [1536,2048) wo, [2048,4096) wi, [4096,6144) wo2, [6144,6147) bias.
// ---------------------------------------------------------------------------
__global__ void __launch_bounds__(256) prep_kernel(
    const float* __restrict__ wq, const float* __restrict__ wk,
    const float* __restrict__ wv, const float* __restrict__ wo,
    const float* __restrict__ wi, const float* __restrict__ wo2,
    const float* __restrict__ bq, const float* __restrict__ bk,
    const float* __restrict__ bv,
    __nv_bfloat16* __restrict__ wqkvh, __nv_bfloat16* __restrict__ wqkvl,
    __nv_bfloat16* __restrict__ woh, __nv_bfloat16* __restrict__ wol,
    __nv_bfloat16* __restrict__ wih, __nv_bfloat16* __restrict__ wil,
    __nv_bfloat16* __restrict__ w2h, __nv_bfloat16* __restrict__ w2l,
    float* __restrict__ bqkv)
{
    const int blk = blockIdx.x;
    if (blk < 1536) {                    // qkv pack-split
        const int seg = blk >> 9, b2 = blk & 511;
        const float* src = (seg == 0) ? wq : (seg == 1) ? wk : wv;
        const int coloff = seg << 9;
        const int i = (b2 * 256 + threadIdx.x) * 8;
        const int row = i >> 9, col = i & 511;
        const size_t d = (size_t)row * QKVS + coloff + col;
        split8_store(src + i, wqkvh + d, wqkvl + d);
    } else if (blk < 2048) {             // wo
        const int i = ((blk - 1536) * 256 + threadIdx.x) * 8;
        split8_store(wo + i, woh + i, wol + i);
    } else if (blk < 4096) {             // wi
        const int i = ((blk - 2048) * 256 + threadIdx.x) * 8;
        split8_store(wi + i, wih + i, wil + i);
    } else if (blk < 6144) {             // wo2
        const int i = ((blk - 4096) * 256 + threadIdx.x) * 8;
        split8_store(wo2 + i, w2h + i, w2l + i);
    } else {                             // bias pack (Ln*QKVS = 6144 els)
        const int i0 = ((blk - 6144) * 256 + threadIdx.x) * 8;
#pragma unroll
        for (int j = 0; j < 8; j++) {
            const int idx = i0 + j;
            const int l = idx / QKVS, jj = idx % QKVS;
            const int seg = jj >> 9, col = jj & 511;
            const float* s = (seg == 0) ? bq : (seg == 1) ? bk : bv;
            bqkv[idx] = s[l * Hn + col];
        }
    }
}

// ---------------------------------------------------------------------------
// HMMA split-bf16 GEMM. CTA 128x128, BK=32, 8 warps, 3 passes, 2 CTAs/SM.
// EPI 0: bias -> bf16 hi/lo out.  EPI 1: bias + res -> fp32 out.
// EPI 2: bias + GELU -> bf16 hi/lo out.
// ---------------------------------------------------------------------------
template <int EPI>
__global__ void __launch_bounds__(256, 2) hmma_gemm(
    const __nv_bfloat16* __restrict__ Ahp, const __nv_bfloat16* __restrict__ Alp,
    const __nv_bfloat16* __restrict__ Bhp, const __nv_bfloat16* __restrict__ Blp,
    const float* __restrict__ bias, const float* __restrict__ res,
    float* __restrict__ C, __nv_bfloat16* __restrict__ Cho,
    __nv_bfloat16* __restrict__ Clo, int K, int N)
{
    extern __shared__ char smem[];
    const uint32_t sb = cvta_smem(smem);
    const int tid = threadIdx.x, lane = tid & 31, warp = tid >> 5;
    const int m0 = blockIdx.y << 7, n0 = blockIdx.x << 7;
    const int wm0 = (warp >> 2) << 6, wn0 = (warp & 3) << 5;

    const int ar = tid >> 2, ac = tid & 3;
    const int br = tid >> 4, bc = tid & 15;

    auto load_stage = [&](int st, int kc) {
        const int k0 = kc << 5;
        const uint32_t s = sb + st * STAGE_BYTES;
        const size_t aoff0 = (size_t)(m0 + ar) * K + k0 + ac * 8;
        const size_t aoff1 = (size_t)(m0 + ar + 64) * K + k0 + ac * 8;
        CP16(s + OFF_AH + ar * 80 + ac * 16, Ahp + aoff0);
        CP16(s + OFF_AH + (ar + 64) * 80 + ac * 16, Ahp + aoff1);
        CP16(s + OFF_AL + ar * 80 + ac * 16, Alp + aoff0);
        CP16(s + OFF_AL + (ar + 64) * 80 + ac * 16, Alp + aoff1);
        const size_t boff0 = (size_t)(k0 + br) * N + n0 + bc * 8;
        const size_t boff1 = (size_t)(k0 + br + 16) * N + n0 + bc * 8;
        CP16(s + OFF_BH + br * 272 + bc * 16, Bhp + boff0);
        CP16(s + OFF_BH + (br + 16) * 272 + bc * 16, Bhp + boff1);
        CP16(s + OFF_BL + br * 272 + bc * 16, Blp + boff0);
        CP16(s + OFF_BL + (br + 16) * 272 + bc * 16, Blp + boff1);
        CP_COMMIT();
    };

    float acc[4][4][4];
#pragma unroll
    for (int i = 0; i < 4; i++)
#pragma unroll
        for (int j = 0; j < 4; j++)
#pragma unroll
            for (int r = 0; r < 4; r++) acc[i][j][r] = 0.0f;

    const int nch = K >> 5;
    load_stage(0, 0);

    for (int kc = 0; kc < nch; kc++) {
        const int cur = kc & 1;
        CP_WAIT0();
        __syncthreads();
        if (kc + 1 < nch) load_stage(cur ^ 1, kc + 1);

        const uint32_t s = sb + cur * STAGE_BYTES;
#pragma unroll
        for (int ks = 0; ks < 2; ks++) {
            const uint32_t aoff =
                (wm0 + (lane & 15)) * 80 + ((ks << 4) + ((lane >> 4) << 3)) * 2;
            const uint32_t boff =
                ((ks << 4) + (lane & 15)) * 272 + (wn0 + ((lane >> 4) << 3)) * 2;

            uint32_t ah[4][4], al[4][4];
#pragma unroll
            for (int mt = 0; mt < 4; mt++) {
                LDSM4(ah[mt], s + OFF_AH + aoff + mt * (16 * 80));
                LDSM4(al[mt], s + OFF_AL + aoff + mt * (16 * 80));
            }
            {   // B hi: pass1 (Ah*Bh) + pass3 (Al*Bh)
                uint32_t b[4][2];
                LDSM4T(b[0], b[1], s + OFF_BH + boff);
                LDSM4T(b[2], b[3], s + OFF_BH + boff + 32);
#pragma unroll
                for (int mt = 0; mt < 4; mt++)
#pragma unroll
                    for (int nt = 0; nt < 4; nt++) mma16816(acc[mt][nt], ah[mt], b[nt]);
#pragma unroll
                for (int mt = 0; mt < 4; mt++)
#pragma unroll
                    for (int nt = 0; nt < 4; nt++) mma16816(acc[mt][nt], al[mt], b[nt]);
            }
            {   // B lo: pass2 (Ah*Bl)
                uint32_t b[4][2];
                LDSM4T(b[0], b[1], s + OFF_BL + boff);
                LDSM4T(b[2], b[3], s + OFF_BL + boff + 32);
#pragma unroll
                for (int mt = 0; mt < 4; mt++)
#pragma unroll
                    for (int nt = 0; nt < 4; nt++) mma16816(acc[mt][nt], ah[mt], b[nt]);
            }
        }
    }

#pragma unroll
    for (int mt = 0; mt < 4; mt++) {
        const int m = m0 + wm0 + mt * 16 + (lane >> 2);
#pragma unroll
        for (int nt = 0; nt < 4; nt++) {
            const int n = n0 + wn0 + nt * 8 + (lane & 3) * 2;
            float2 bv = *(const float2*)(bias + n);
            float o0 = acc[mt][nt][0] + bv.x;
            float o1 = acc[mt][nt][1] + bv.y;
            float o2 = acc[mt][nt][2] + bv.x;
            float o3 = acc[mt][nt][3] + bv.y;
            if (EPI == 1) {
                float2 r0 = *(const float2*)(res + (size_t)m * N + n);
                float2 r1 = *(const float2*)(res + (size_t)(m + 8) * N + n);
                o0 += r0.x; o1 += r0.y; o2 += r1.x; o3 += r1.y;
                *(float2*)(C + (size_t)m * N + n) = make_float2(o0, o1);
                *(float2*)(C + (size_t)(m + 8) * N + n) = make_float2(o2, o3);
            } else {
                if (EPI == 2) {
                    o0 = 0.5f * o0 * (1.0f + erff(o0 * 0.7071067811865475f));
                    o1 = 0.5f * o1 * (1.0f + erff(o1 * 0.7071067811865475f));
                    o2 = 0.5f * o2 * (1.0f + erff(o2 * 0.7071067811865475f));
                    o3 = 0.5f * o3 * (1.0f + erff(o3 * 0.7071067811865475f));
                }
                uint32_t h0 = pack_bf16(o0, o1);
                uint32_t h1 = pack_bf16(o2, o3);
                *(uint32_t*)(Cho + (size_t)m * N + n) = h0;
                *(uint32_t*)(Clo + (size_t)m * N + n) =
                    pack_bf16(o0 - bf16lo_f(h0), o1 - bf16hi_f(h0));
                *(uint32_t*)(Cho + (size_t)(m + 8) * N + n) = h1;
                *(uint32_t*)(Clo + (size_t)(m + 8) * N + n) =
                    pack_bf16(o2 - bf16lo_f(h1), o3 - bf16hi_f(h1));
            }
        }
    }
}

// ---------------------------------------------------------------------------
// Flash attention over packed QKV [M, 1536]. Per CTA one (b,h) x 128 q-rows.
// ---------------------------------------------------------------------------
#define FSTG 36864
__global__ void __launch_bounds__(256, 2) flash_kernel(
    const __nv_bfloat16* __restrict__ QKVh, const __nv_bfloat16* __restrict__ QKVl,
    const float* __restrict__ sinv, const __nv_bfloat16* __restrict__ pbb,
    const float* __restrict__ mask,
    __nv_bfloat16* __restrict__ Ch, __nv_bfloat16* __restrict__ Cl)
{
    extern __shared__ char smem[];
    const uint32_t sb = cvta_smem(smem);
    const int tid = threadIdx.x, lane = tid & 31, warp = tid >> 5;
    const int qb = blockIdx.x << 7;
    const int bh = blockIdx.y, b = bh & 3, h = bh >> 2;
    const uint32_t sQ = sb;
    const uint32_t sKV = sb + 36864;

    // Q + stage 0
#pragma unroll
    for (int i = 0; i < 4; i++) {
        int idx = tid + (i << 8);
        int r = idx >> 3, c = idx & 7;
        size_t off = ((size_t)(b * Sn + qb + r)) * QKVS + h * 64 + c * 8;
        CP16(sQ + r * 144 + c * 16, QKVh + off);
        CP16(sQ + 18432 + r * 144 + c * 16, QKVl + off);
    }
#pragma unroll
    for (int i = 0; i < 2; i++) {
        int idx = tid + (i << 8);
        int r = idx >> 3, c = idx & 7;
        size_t off = ((size_t)(b * Sn + r)) * QKVS + h * 64 + c * 8;
        uint32_t d = sKV + r * 144 + c * 16;
        CP16(d, QKVh + off + 512); CP16(d + 9216, QKVl + off + 512);
        CP16(d + 18432, QKVh + off + 1024); CP16(d + 27648, QKVl + off + 1024);
    }
    CP_COMMIT();

    const int qr0 = qb + (warp << 4) + (lane >> 2);
    const float* sv0 = sinv + ((size_t)(b * Sn + qr0)) * Sn;
    const float* sv1 = sv0 + (size_t)8 * Sn;
    const __nv_bfloat16* pb0 = pbb + ((size_t)(h * Sn + qr0)) * Sn;
    const __nv_bfloat16* pb1 = pb0 + (size_t)8 * Sn;
    const float* mrow = mask + b * Sn;

    float oacc[8][4];
#pragma unroll
    for (int t = 0; t < 8; t++)
#pragma unroll
        for (int r = 0; r < 4; r++) oacc[t][r] = 0.0f;
    float m0 = -1e30f, m1 = -1e30f, l0 = 0.0f, l1 = 0.0f;

    for (int it = 0; it < 32; it++) {
        if (it + 1 < 32) {
            const uint32_t s = sKV + ((it + 1) & 1) * FSTG;
            const int k0n = (it + 1) << 6;
#pragma unroll
            for (int i = 0; i < 2; i++) {
                int idx = tid + (i << 8);
                int r = idx >> 3, c = idx & 7;
                size_t off = ((size_t)(b * Sn + k0n + r)) * QKVS + h * 64 + c * 8;
                uint32_t d = s + r * 144 + c * 16;
                CP16(d, QKVh + off + 512); CP16(d + 9216, QKVl + off + 512);
                CP16(d + 18432, QKVh + off + 1024); CP16(d + 27648, QKVl + off + 1024);
            }
        }
        CP_COMMIT();
        CP_WAIT1();
        __syncthreads();

        const uint32_t stg = sKV + (it & 1) * FSTG;
        float sacc[8][4];
#pragma unroll
        for (int t = 0; t < 8; t++)
#pragma unroll
            for (int r = 0; r < 4; r++) sacc[t][r] = 0.0f;

        // S = Q K^T (3-pass), Q frags from persistent smem tile
#pragma unroll
        for (int kc = 0; kc < 4; kc++) {
            uint32_t aqh[4], aql[4];
            const uint32_t qa = sQ + ((warp << 4) + (lane & 15)) * 144 +
                                ((kc << 4) + ((lane >> 4) << 3)) * 2;
            LDSM4(aqh, qa);
            LDSM4(aql, qa + 18432);
#pragma unroll
            for (int nb = 0; nb < 4; nb++) {
                uint32_t kbh[4], kbl[4];
                const uint32_t ka = stg + ((nb << 4) + (lane & 15)) * 144 +
                                    ((kc << 4) + ((lane >> 4) << 3)) * 2;
                LDSM4(kbh, ka);
                LDSM4(kbl, ka + 9216);
#pragma unroll
                for (int tt = 0; tt < 2; tt++) {
                    const int t = (nb << 1) + tt;
                    uint32_t bh_[2] = {kbh[tt], kbh[tt + 2]};
                    uint32_t bl_[2] = {kbl[tt], kbl[tt + 2]};
                    mma16816(sacc[t], aqh, bh_);
                    mma16816(sacc[t], aqh, bl_);
                    mma16816(sacc[t], aql, bh_);
                }
            }
        }

        // epilogue: precomputed sinv + pb(bf16) + mask, online softmax
        const int k0 = it << 6;
        float tm0 = -1e30f, tm1 = -1e30f;
#pragma unroll
        for (int t = 0; t < 8; t++) {
            const int n = k0 + (t << 3) + ((lane & 3) << 1);
            float2 s0 = *(const float2*)(sv0 + n);
            float2 s1 = *(const float2*)(sv1 + n);
            float2 mk = *(const float2*)(mrow + n);
            uint32_t pu0 = *(const uint32_t*)(pb0 + n);
            uint32_t pu1 = *(const uint32_t*)(pb1 + n);
            sacc[t][0] = fmaf(sacc[t][0], s0.x, bf16lo_f(pu0) + mk.x);
            sacc[t][1] = fmaf(sacc[t][1], s0.y, bf16hi_f(pu0) + mk.y);
            sacc[t][2] = fmaf(sacc[t][2], s1.x, bf16lo_f(pu1) + mk.x);
            sacc[t][3] = fmaf(sacc[t][3], s1.y, bf16hi_f(pu1) + mk.y);
            tm0 = fmaxf(tm0, fmaxf(sacc[t][0], sacc[t][1]));
            tm1 = fmaxf(tm1, fmaxf(sacc[t][2], sacc[t][3]));
        }
        tm0 = fmaxf(tm0, __shfl_xor_sync(0xffffffffu, tm0, 1));
        tm0 = fmaxf(tm0, __shfl_xor_sync(0xffffffffu, tm0, 2));
        tm1 = fmaxf(tm1, __shfl_xor_sync(0xffffffffu, tm1, 1));
        tm1 = fmaxf(tm1, __shfl_xor_sync(0xffffffffu, tm1, 2));
        const float mn0 = fmaxf(m0, tm0), mn1 = fmaxf(m1, tm1);
        const float c0 = ex2f((m0 - mn0) * L2E), c1 = ex2f((m1 - mn1) * L2E);
        m0 = mn0; m1 = mn1;

        float rs0 = 0.0f, rs1 = 0.0f;
        uint32_t aph[4][4], apl[4][4];
#pragma unroll
        for (int t = 0; t < 8; t++) {
            float p00 = ex2f((sacc[t][0] - m0) * L2E);
            float p01 = ex2f((sacc[t][1] - m0) * L2E);
            float p10 = ex2f((sacc[t][2] - m1) * L2E);
            float p11 = ex2f((sacc[t][3] - m1) * L2E);
            rs0 += p00 + p01; rs1 += p10 + p11;
            uint32_t h0 = pack_bf16(p00, p01);
            uint32_t h1 = pack_bf16(p10, p11);
            const int kc2 = t >> 1, hf = (t & 1) << 1;
            aph[kc2][hf] = h0; aph[kc2][hf + 1] = h1;
            apl[kc2][hf] = pack_bf16(p00 - bf16lo_f(h0), p01 - bf16hi_f(h0));
            apl[kc2][hf + 1] = pack_bf16(p10 - bf16lo_f(h1), p11 - bf16hi_f(h1));
        }
        rs0 += __shfl_xor_sync(0xffffffffu, rs0, 1);
        rs0 += __shfl_xor_sync(0xffffffffu, rs0, 2);
        rs1 += __shfl_xor_sync(0xffffffffu, rs1, 1);
        rs1 += __shfl_xor_sync(0xffffffffu, rs1, 2);
        l0 = l0 * c0 + rs0;
        l1 = l1 * c1 + rs1;
#pragma unroll
        for (int t = 0; t < 8; t++) {
            oacc[t][0] *= c0; oacc[t][1] *= c0;
            oacc[t][2] *= c1; oacc[t][3] *= c1;
        }

        // ctx: O += P * V  (V frags in 8-reg groups)
#pragma unroll
        for (int kc2 = 0; kc2 < 4; kc2++) {
#pragma unroll
            for (int dnb = 0; dnb < 4; dnb++) {
                uint32_t vfh[2][2], vfl[2][2];
                const uint32_t va = stg + 18432 +
                    ((kc2 << 4) + (lane & 15)) * 144 +
                    ((dnb << 4) + ((lane >> 4) << 3)) * 2;
                LDSM4T(vfh[0], vfh[1], va);
                LDSM4T(vfl[0], vfl[1], va + 9216);
#pragma unroll
                for (int tt = 0; tt < 2; tt++) {
                    const int t = (dnb << 1) + tt;
                    mma16816(oacc[t], aph[kc2], vfh[tt]);
                    mma16816(oacc[t], aph[kc2], vfl[tt]);
                    mma16816(oacc[t], apl[kc2], vfh[tt]);
                }
            }
        }
        __syncthreads();
    }

    const float inv0 = 1.0f / l0, inv1 = 1.0f / l1;
#pragma unroll
    for (int t = 0; t < 8; t++) {
        const int d = (t << 3) + ((lane & 3) << 1);
        const size_t o0 = ((size_t)(b * Sn + qr0)) * Hn + h * 64 + d;
        const size_t o1 = ((size_t)(b * Sn + qr0 + 8)) * Hn + h * 64 + d;
        float v0 = oacc[t][0] * inv0, v1 = oacc[t][1] * inv0;
        float v2 = oacc[t][2] * inv1, v3 = oacc[t][3] * inv1;
        uint32_t h0 = pack_bf16(v0, v1), h1 = pack_bf16(v2, v3);
        *(uint32_t*)(Ch + o0) = h0;
        *(uint32_t*)(Cl + o0) = pack_bf16(v0 - bf16lo_f(h0), v1 - bf16hi_f(h0));
        *(uint32_t*)(Ch + o1) = h1;
        *(uint32_t*)(Cl + o1) = pack_bf16(v2 - bf16lo_f(h1), v3 - bf16hi_f(h1));
    }
}

// ---------------------------------------------------------------------------
// LayerNorm over H=512; optional bf16 hi/lo outputs.
// ---------------------------------------------------------------------------
__global__ void __launch_bounds__(256) ln_kernel(
    const float* __restrict__ in, const float* __restrict__ g,
    const float* __restrict__ bta, float* __restrict__ out,
    __nv_bfloat16* __restrict__ ho, __nv_bfloat16* __restrict__ lo_)
{
    const size_t base = (size_t)blockIdx.x * Hn;
    const int tid = threadIdx.x;
    __shared__ float sh[8], sh2[8];
    float x0 = in[base + tid], x1 = in[base + tid + 256];
    float s = x0 + x1;
    for (int o = 16; o; o >>= 1) s += __shfl_xor_sync(0xffffffffu, s, o);
    if ((tid & 31) == 0) sh[tid >> 5] = s;
    __syncthreads();
    s = 0.0f;
#pragma unroll
    for (int i = 0; i < 8; i++) s += sh[i];
    const float mean = s * (1.0f / Hn);
    const float d0 = x0 - mean, d1 = x1 - mean;
    float vv = d0 * d0 + d1 * d1;
    for (int o = 16; o; o >>= 1) vv += __shfl_xor_sync(0xffffffffu, vv, o);
    if ((tid & 31) == 0) sh2[tid >> 5] = vv;
    __syncthreads();
    vv = 0.0f;
#pragma unroll
    for (int i = 0; i < 8; i++) vv += sh2[i];
    const float inv = rsqrtf(vv * (1.0f / Hn) + 1e-12f);
    const float y0 = d0 * inv * g[tid] + bta[tid];
    const float y1 = d1 * inv * g[tid + 256] + bta[tid + 256];
    out[base + tid] = y0;
    out[base + tid + 256] = y1;
    if (ho) {
        __nv_bfloat16 h0 = __float2bfloat16(y0);
        __nv_bfloat16 h1 = __float2bfloat16(y1);
        ho[base + tid] = h0;
        ho[base + tid + 256] = h1;
        lo_[base + tid] = __float2bfloat16(y0 - __bfloat162float(h0));
        lo_[base + tid + 256] = __float2bfloat16(y1 - __bfloat162float(h1));
    }
}

// ---------------------------------------------------------------------------
extern "C" void kernel_launch(void* const* d_in, const int* in_sizes, int n_in,
                              void* d_out, int out_size)
{
    (void)in_sizes; (void)n_in; (void)out_size;
    const float* qs   = (const float*)d_in[0];
    const float* mask = (const float*)d_in[1];
    const float* pb   = (const float*)d_in[2];
    const int*   ts   = (const int*)d_in[3];
    const float* wq  = (const float*)d_in[4];  const float* bq  = (const float*)d_in[5];
    const float* wk  = (const float*)d_in[6];  const float* bk  = (const float*)d_in[7];
    const float* wv  = (const float*)d_in[8];  const float* bv  = (const float*)d_in[9];
    const float* wo  = (const float*)d_in[10]; const float* bo  = (const float*)d_in[11];
    const float* l1g = (const float*)d_in[12]; const float* l1b = (const float*)d_in[13];
    const float* wi  = (const float*)d_in[14]; const float* bi  = (const float*)d_in[15];
    const float* wo2 = (const float*)d_in[16]; const float* bo2 = (const float*)d_in[17];
    const float* l2g = (const float*)d_in[18]; const float* l2b = (const float*)d_in[19];

    float *x, *attn, *bqkv, *sinvp;
    cudaGetSymbolAddress((void**)&x,    g_x);
    cudaGetSymbolAddress((void**)&attn, g_attn);
    cudaGetSymbolAddress((void**)&bqkv, g_bqkv);
    cudaGetSymbolAddress((void**)&sinvp, g_sinv);

    __nv_bfloat16 *qkvh, *qkvl, *ch, *cl, *xh, *xl, *th, *tl, *fh, *fl, *pbb;
    cudaGetSymbolAddress((void**)&qkvh, g_qkvh); cudaGetSymbolAddress((void**)&qkvl, g_qkvl);
    cudaGetSymbolAddress((void**)&ch, g_ch); cudaGetSymbolAddress((void**)&cl, g_cl);
    cudaGetSymbolAddress((void**)&xh, g_xh); cudaGetSymbolAddress((void**)&xl, g_xl);
    cudaGetSymbolAddress((void**)&th, g_th); cudaGetSymbolAddress((void**)&tl, g_tl);
    cudaGetSymbolAddress((void**)&fh, g_fh); cudaGetSymbolAddress((void**)&fl, g_fl);
    cudaGetSymbolAddress((void**)&pbb, g_pbb);

    __nv_bfloat16 *wqkvh, *wqkvl, *woh, *wol, *wih, *wil, *w2h, *w2l;
    cudaGetSymbolAddress((void**)&wqkvh, g_wqkvh); cudaGetSymbolAddress((void**)&wqkvl, g_wqkvl);
    cudaGetSymbolAddress((void**)&woh, g_woh); cudaGetSymbolAddress((void**)&wol, g_wol);
    cudaGetSymbolAddress((void**)&wih, g_wih); cudaGetSymbolAddress((void**)&wil, g_wil);
    cudaGetSymbolAddress((void**)&w2h, g_w2h); cudaGetSymbolAddress((void**)&w2l, g_w2l);

    const int HM_SMEM = 2 * STAGE_BYTES;  // 75776
    const int FL_SMEM = 36864 + 2 * FSTG; // 110592
    cudaFuncSetAttribute(hmma_gemm<0>, cudaFuncAttributeMaxDynamicSharedMemorySize, HM_SMEM);
    cudaFuncSetAttribute(hmma_gemm<1>, cudaFuncAttributeMaxDynamicSharedMemorySize, HM_SMEM);
    cudaFuncSetAttribute(hmma_gemm<2>, cudaFuncAttributeMaxDynamicSharedMemorySize, HM_SMEM);
    cudaFuncSetAttribute(flash_kernel, cudaFuncAttributeMaxDynamicSharedMemorySize, FL_SMEM);

    // Precompute (4 launches, so flash_kernel is launch index 5 for ncu -s 5)
    const int PBN = NHn * Sn * Sn;
    prep_kernel<<<6147, 256>>>(wq, wk, wv, wo, wi, wo2, bq, bk, bv,
                               wqkvh, wqkvl, woh, wol, wih, wil, w2h, w2l, bqkv);
    cvt_bf16_kernel<<<PBN / 2048, 256>>>(pb, pbb, PBN);
    sinv_kernel<<<Bn * Sn, 256>>>(ts, sinvp);
    split_kernel<<<(Mn * Hn) / 2048, 256>>>(qs, xh, xl, Mn * Hn);

    dim3 gqkv(QKVS / 128, Mn / 128);  // (12, 64)
    dim3 gproj(Hn / 128, Mn / 128);   // (4, 64)
    dim3 gff(Fn / 128, Mn / 128);     // (16, 64)
    dim3 gfl(Sn / 128, Bn * NHn);     // (16, 32)

    for (int l = 0; l < Ln; l++) {
        const size_t wOff  = (size_t)l * Hn * Hn;
        const size_t bOff  = (size_t)l * Hn;
        const size_t wiOff = (size_t)l * Hn * Fn;
        const size_t biOff = (size_t)l * Fn;
        const float* xres = (l == 0) ? qs : x;

        hmma_gemm<0><<<gqkv, 256, HM_SMEM>>>(xh, xl,
            wqkvh + (size_t)l * Hn * QKVS, wqkvl + (size_t)l * Hn * QKVS,
            bqkv + l * QKVS, nullptr, nullptr, qkvh, qkvl, Hn, QKVS);

        flash_kernel<<<gfl, 256, FL_SMEM>>>(qkvh, qkvl, sinvp, pbb, mask, ch, cl);

        hmma_gemm<1><<<gproj, 256, HM_SMEM>>>(ch, cl, woh + wOff, wol + wOff,
                                              bo + bOff, xres, attn, nullptr, nullptr, Hn, Hn);
        ln_kernel<<<Mn, 256>>>(attn, l1g + bOff, l1b + bOff, attn, th, tl);

        hmma_gemm<2><<<gff, 256, HM_SMEM>>>(th, tl, wih + wiOff, wil + wiOff,
                                            bi + biOff, nullptr, nullptr, fh, fl, Hn, Fn);
        hmma_gemm<1><<<gproj, 256, HM_SMEM>>>(fh, fl, w2h + wiOff, w2l + wiOff,
                                              bo2 + bOff, attn, x, nullptr, nullptr, Fn, Hn);

        float* lnout = (l == Ln - 1) ? (float*)d_out : x;
        ln_kernel<<<Mn, 256>>>(x, l2g + bOff, l2b + bOff, lnout,
                               (l == Ln - 1) ? nullptr : xh,
                               (l == Ln - 1) ? nullptr : xl);
    }
}

// round 9
// speedup vs baseline: 3.2286x; 1.2155x over previous
#include <cuda_runtime.h>
#include <cuda_fp16.h>
#include <math.h>
#include <stdint.h>

// Problem constants
#define Bn 4
#define Sn 2048
#define Hn 512
#define NHn 8
#define DHn 64
#define Fn 2048
#define Ln 4
#define Mn (Bn * Sn)  // 8192
#define QKVS 1536
#define L2E 1.4426950408889634f

// ---------------- scratch (device globals; no allocation allowed) ----------
__device__ float g_x[Mn * Hn];
__device__ float g_attn[Mn * Hn];
__device__ float g_sinv[(size_t)Bn * Sn * Sn];          // 67 MB inv-scale

__device__ __half g_qkvh[(size_t)Mn * QKVS], g_qkvl[(size_t)Mn * QKVS];
__device__ __half g_ch[Mn * Hn], g_cl[Mn * Hn];   // ctx
__device__ __half g_xh[Mn * Hn], g_xl[Mn * Hn];
__device__ __half g_th[Mn * Hn], g_tl[Mn * Hn];   // attn (post ln1)
__device__ __half g_fh[(size_t)Mn * Fn], g_fl[(size_t)Mn * Fn];

// weights hi/lo
__device__ __half g_wqkvh[Ln * Hn * QKVS], g_wqkvl[Ln * Hn * QKVS];
__device__ __half g_woh[Ln * Hn * Hn], g_wol[Ln * Hn * Hn];
__device__ __half g_wih[Ln * Hn * Fn], g_wil[Ln * Hn * Fn];
__device__ __half g_w2h[Ln * Fn * Hn], g_w2l[Ln * Fn * Hn];
__device__ float g_bqkv[Ln * QKVS];
__device__ __half g_pbb[(size_t)NHn * Sn * Sn];   // fp16 position bias

// ---------------- helpers ---------------------------------------------------
__device__ __forceinline__ uint32_t cvta_smem(const void* p) {
    uint32_t a;
    asm("{ .reg .u64 t; cvta.to.shared.u64 t, %1; cvt.u32.u64 %0, t; }"
        : "=r"(a) : "l"(p));
    return a;
}

#define CP16(dst, src) \
    asm volatile("cp.async.cg.shared.global [%0], [%1], 16;" :: "r"(dst), "l"(src))
#define CP_COMMIT() asm volatile("cp.async.commit_group;" ::: "memory")
#define CP_WAIT0()  asm volatile("cp.async.wait_group 0;" ::: "memory")
#define CP_WAIT1()  asm volatile("cp.async.wait_group 1;" ::: "memory")

#define LDSM4(r, addr)                                                          \
    asm volatile("ldmatrix.sync.aligned.m8n8.x4.shared.b16 {%0,%1,%2,%3}, [%4];"\
        : "=r"((r)[0]), "=r"((r)[1]), "=r"((r)[2]), "=r"((r)[3]) : "r"(addr))
#define LDSM4T(r01, r23, addr)                                                  \
    asm volatile("ldmatrix.sync.aligned.m8n8.x4.trans.shared.b16 {%0,%1,%2,%3}, [%4];"\
        : "=r"((r01)[0]), "=r"((r01)[1]), "=r"((r23)[0]), "=r"((r23)[1]) : "r"(addr))

__device__ __forceinline__ void mma16816(float* c, const uint32_t* a, const uint32_t* b) {
    asm volatile(
        "mma.sync.aligned.m16n8k16.row.col.f32.f16.f16.f32 "
        "{%0,%1,%2,%3}, {%4,%5,%6,%7}, {%8,%9}, {%0,%1,%2,%3};"
        : "+f"(c[0]), "+f"(c[1]), "+f"(c[2]), "+f"(c[3])
        : "r"(a[0]), "r"(a[1]), "r"(a[2]), "r"(a[3]), "r"(b[0]), "r"(b[1]));
}

__device__ __forceinline__ uint32_t pack_h2(float lo, float hi) {
    __half2 p = __floats2half2_rn(lo, hi);
    return *reinterpret_cast<uint32_t*>(&p);
}
__device__ __forceinline__ float h_lo(uint32_t u) {
    return __half2float(__ushort_as_half((unsigned short)(u & 0xffffu)));
}
__device__ __forceinline__ float h_hi(uint32_t u) {
    return __half2float(__ushort_as_half((unsigned short)(u >> 16)));
}
__device__ __forceinline__ float ex2f(float x) {
    float y;
    asm("ex2.approx.ftz.f32 %0, %1;" : "=f"(y) : "f"(x));
    return y;
}
__device__ __forceinline__ float rcpf(float x) {
    float y;
    asm("rcp.approx.ftz.f32 %0, %1;" : "=f"(y) : "f"(x));
    return y;
}
// 1/scale = (u + 60000) / (9u + 480000) where u = max(dt_ms, 0)
__device__ __forceinline__ float sinv_of(int dt) {
    float u = fmaxf((float)dt, 0.0f);
    return (u + 60000.0f) * rcpf(fmaf(u, 9.0f, 480000.0f));
}

// split 8 fp32 -> hi/lo fp16x8 and store
__device__ __forceinline__ void split8_store(
    const float* __restrict__ src, __half* __restrict__ h, __half* __restrict__ l)
{
    float4 a = *(const float4*)src;
    float4 b = *(const float4*)(src + 4);
    float v[8] = {a.x, a.y, a.z, a.w, b.x, b.y, b.z, b.w};
    __align__(16) __half hh[8];
    __align__(16) __half ll[8];
#pragma unroll
    for (int j = 0; j < 8; j++) {
        hh[j] = __float2half_rn(v[j]);
        ll[j] = __float2half_rn(v[j] - __half2float(hh[j]));
    }
    *(uint4*)h = *(const uint4*)hh;
    *(uint4*)l = *(const uint4*)ll;
}

// smem stage layout for dense GEMM (padded rows: A 80B, B 272B)
#define OFF_AH 0
#define OFF_AL 10240
#define OFF_BH 20480
#define OFF_BL 29184
#define STAGE_BYTES 37888   // x2 stages = 75776

// ---------------------------------------------------------------------------
__global__ void __launch_bounds__(256) split_kernel(
    const float* __restrict__ x, __half* __restrict__ h,
    __half* __restrict__ l, int n)
{
    int i = (blockIdx.x * 256 + threadIdx.x) * 8;
    if (i >= n) return;
    split8_store(x + i, h + i, l + i);
}

__global__ void __launch_bounds__(256) cvt_h_kernel(
    const float* __restrict__ x, __half* __restrict__ y, int n)
{
    int i = (blockIdx.x * 256 + threadIdx.x) * 8;
    if (i >= n) return;
    float4 a = *(const float4*)(x + i);
    float4 b = *(const float4*)(x + i + 4);
    float v[8] = {a.x, a.y, a.z, a.w, b.x, b.y, b.z, b.w};
    __align__(16) __half hh[8];
#pragma unroll
    for (int j = 0; j < 8; j++) hh[j] = __float2half_rn(v[j]);
    *(uint4*)(y + i) = *(const uint4*)hh;
}

// sinv[b][q][k] = 1/scale. One block per (b,q) row.
__global__ void __launch_bounds__(256) sinv_kernel(
    const int* __restrict__ ts, float* __restrict__ sv)
{
    const int bq = blockIdx.x;
    const int b = bq >> 11;
    const int tq = ts[bq];
    const int* tr = ts + b * Sn;
    float* out = sv + (size_t)bq * Sn;
#pragma unroll
    for (int kk = 0; kk < 2; kk++) {
        int k = (threadIdx.x + (kk << 8)) << 2;
        int4 tk = *(const int4*)(tr + k);
        float4 o;
        o.x = sinv_of(tq - tk.x);
        o.y = sinv_of(tq - tk.y);
        o.z = sinv_of(tq - tk.z);
        o.w = sinv_of(tq - tk.w);
        *(float4*)(out + k) = o;
    }
}

// ---------------------------------------------------------------------------
// Mega weight-prep (splits + qkv pack + bias pack)
// ---------------------------------------------------------------------------
__global__ void __launch_bounds__(256) prep_kernel(
    const float* __restrict__ wq, const float* __restrict__ wk,
    const float* __restrict__ wv, const float* __restrict__ wo,
    const float* __restrict__ wi, const float* __restrict__ wo2,
    const float* __restrict__ bq, const float* __restrict__ bk,
    const float* __restrict__ bv,
    __half* __restrict__ wqkvh, __half* __restrict__ wqkvl,
    __half* __restrict__ woh, __half* __restrict__ wol,
    __half* __restrict__ wih, __half* __restrict__ wil,
    __half* __restrict__ w2h, __half* __restrict__ w2l,
    float* __restrict__ bqkv)
{
    const int blk = blockIdx.x;
    if (blk < 1536) {
        const int seg = blk >> 9, b2 = blk & 511;
        const float* src = (seg == 0) ? wq : (seg == 1) ? wk : wv;
        const int coloff = seg << 9;
        const int i = (b2 * 256 + threadIdx.x) * 8;
        const int row = i >> 9, col = i & 511;
        const size_t d = (size_t)row * QKVS + coloff + col;
        split8_store(src + i, wqkvh + d, wqkvl + d);
    } else if (blk < 2048) {
        const int i = ((blk - 1536) * 256 + threadIdx.x) * 8;
        split8_store(wo + i, woh + i, wol + i);
    } else if (blk < 4096) {
        const int i = ((blk - 2048) * 256 + threadIdx.x) * 8;
        split8_store(wi + i, wih + i, wil + i);
    } else if (blk < 6144) {
        const int i = ((blk - 4096) * 256 + threadIdx.x) * 8;
        split8_store(wo2 + i, w2h + i, w2l + i);
    } else {
        const int i0 = ((blk - 6144) * 256 + threadIdx.x) * 8;
#pragma unroll
        for (int j = 0; j < 8; j++) {
            const int idx = i0 + j;
            const int l = idx / QKVS, jj = idx % QKVS;
            const int seg = jj >> 9, col = jj & 511;
            const float* s = (seg == 0) ? bq : (seg == 1) ? bk : bv;
            bqkv[idx] = s[l * Hn + col];
        }
    }
}

// ---------------------------------------------------------------------------
// HMMA split-fp16 GEMM. CTA 128x128, BK=32, 8 warps, 3 passes.
// EPI 0: bias -> fp16 hi/lo.  EPI 1: bias+res -> fp32.  EPI 2: bias+GELU -> fp16 hi/lo.
// lo_mode: 1 = write lo always, 2 = write lo only for n0 in [512,1024) (K seg).
// ---------------------------------------------------------------------------
template <int EPI>
__global__ void __launch_bounds__(256, 2) hmma_gemm(
    const __half* __restrict__ Ahp, const __half* __restrict__ Alp,
    const __half* __restrict__ Bhp, const __half* __restrict__ Blp,
    const float* __restrict__ bias, const float* __restrict__ res,
    float* __restrict__ C, __half* __restrict__ Cho,
    __half* __restrict__ Clo, int K, int N, int lo_mode)
{
    extern __shared__ char smem[];
    const uint32_t sb = cvta_smem(smem);
    const int tid = threadIdx.x, lane = tid & 31, warp = tid >> 5;
    const int m0 = blockIdx.y << 7, n0 = blockIdx.x << 7;
    const int wm0 = (warp >> 2) << 6, wn0 = (warp & 3) << 5;
    const bool wlo = (lo_mode == 1) || (lo_mode == 2 && (n0 >> 9) == 1);

    const int ar = tid >> 2, ac = tid & 3;
    const int br = tid >> 4, bc = tid & 15;

    auto load_stage = [&](int st, int kc) {
        const int k0 = kc << 5;
        const uint32_t s = sb + st * STAGE_BYTES;
        const size_t aoff0 = (size_t)(m0 + ar) * K + k0 + ac * 8;
        const size_t aoff1 = (size_t)(m0 + ar + 64) * K + k0 + ac * 8;
        CP16(s + OFF_AH + ar * 80 + ac * 16, Ahp + aoff0);
        CP16(s + OFF_AH + (ar + 64) * 80 + ac * 16, Ahp + aoff1);
        CP16(s + OFF_AL + ar * 80 + ac * 16, Alp + aoff0);
        CP16(s + OFF_AL + (ar + 64) * 80 + ac * 16, Alp + aoff1);
        const size_t boff0 = (size_t)(k0 + br) * N + n0 + bc * 8;
        const size_t boff1 = (size_t)(k0 + br + 16) * N + n0 + bc * 8;
        CP16(s + OFF_BH + br * 272 + bc * 16, Bhp + boff0);
        CP16(s + OFF_BH + (br + 16) * 272 + bc * 16, Bhp + boff1);
        CP16(s + OFF_BL + br * 272 + bc * 16, Blp + boff0);
        CP16(s + OFF_BL + (br + 16) * 272 + bc * 16, Blp + boff1);
        CP_COMMIT();
    };

    float acc[4][4][4];
#pragma unroll
    for (int i = 0; i < 4; i++)
#pragma unroll
        for (int j = 0; j < 4; j++)
#pragma unroll
            for (int r = 0; r < 4; r++) acc[i][j][r] = 0.0f;

    const int nch = K >> 5;
    load_stage(0, 0);

    for (int kc = 0; kc < nch; kc++) {
        const int cur = kc & 1;
        CP_WAIT0();
        __syncthreads();
        if (kc + 1 < nch) load_stage(cur ^ 1, kc + 1);

        const uint32_t s = sb + cur * STAGE_BYTES;
#pragma unroll
        for (int ks = 0; ks < 2; ks++) {
            const uint32_t aoff =
                (wm0 + (lane & 15)) * 80 + ((ks << 4) + ((lane >> 4) << 3)) * 2;
            const uint32_t boff =
                ((ks << 4) + (lane & 15)) * 272 + (wn0 + ((lane >> 4) << 3)) * 2;

            uint32_t ah[4][4], al[4][4];
#pragma unroll
            for (int mt = 0; mt < 4; mt++) {
                LDSM4(ah[mt], s + OFF_AH + aoff + mt * (16 * 80));
                LDSM4(al[mt], s + OFF_AL + aoff + mt * (16 * 80));
            }
            {   // B hi: Ah*Bh + Al*Bh
                uint32_t b[4][2];
                LDSM4T(b[0], b[1], s + OFF_BH + boff);
                LDSM4T(b[2], b[3], s + OFF_BH + boff + 32);
#pragma unroll
                for (int mt = 0; mt < 4; mt++)
#pragma unroll
                    for (int nt = 0; nt < 4; nt++) mma16816(acc[mt][nt], ah[mt], b[nt]);
#pragma unroll
                for (int mt = 0; mt < 4; mt++)
#pragma unroll
                    for (int nt = 0; nt < 4; nt++) mma16816(acc[mt][nt], al[mt], b[nt]);
            }
            {   // B lo: Ah*Bl
                uint32_t b[4][2];
                LDSM4T(b[0], b[1], s + OFF_BL + boff);
                LDSM4T(b[2], b[3], s + OFF_BL + boff + 32);
#pragma unroll
                for (int mt = 0; mt < 4; mt++)
#pragma unroll
                    for (int nt = 0; nt < 4; nt++) mma16816(acc[mt][nt], ah[mt], b[nt]);
            }
        }
    }

#pragma unroll
    for (int mt = 0; mt < 4; mt++) {
        const int m = m0 + wm0 + mt * 16 + (lane >> 2);
#pragma unroll
        for (int nt = 0; nt < 4; nt++) {
            const int n = n0 + wn0 + nt * 8 + (lane & 3) * 2;
            float2 bv = *(const float2*)(bias + n);
            float o0 = acc[mt][nt][0] + bv.x;
            float o1 = acc[mt][nt][1] + bv.y;
            float o2 = acc[mt][nt][2] + bv.x;
            float o3 = acc[mt][nt][3] + bv.y;
            if (EPI == 1) {
                float2 r0 = *(const float2*)(res + (size_t)m * N + n);
                float2 r1 = *(const float2*)(res + (size_t)(m + 8) * N + n);
                o0 += r0.x; o1 += r0.y; o2 += r1.x; o3 += r1.y;
                *(float2*)(C + (size_t)m * N + n) = make_float2(o0, o1);
                *(float2*)(C + (size_t)(m + 8) * N + n) = make_float2(o2, o3);
            } else {
                if (EPI == 2) {
                    o0 = 0.5f * o0 * (1.0f + erff(o0 * 0.7071067811865475f));
                    o1 = 0.5f * o1 * (1.0f + erff(o1 * 0.7071067811865475f));
                    o2 = 0.5f * o2 * (1.0f + erff(o2 * 0.7071067811865475f));
                    o3 = 0.5f * o3 * (1.0f + erff(o3 * 0.7071067811865475f));
                }
                uint32_t h0 = pack_h2(o0, o1);
                uint32_t h1 = pack_h2(o2, o3);
                *(uint32_t*)(Cho + (size_t)m * N + n) = h0;
                *(uint32_t*)(Cho + (size_t)(m + 8) * N + n) = h1;
                if (wlo) {
                    *(uint32_t*)(Clo + (size_t)m * N + n) =
                        pack_h2(o0 - h_lo(h0), o1 - h_hi(h0));
                    *(uint32_t*)(Clo + (size_t)(m + 8) * N + n) =
                        pack_h2(o2 - h_lo(h1), o3 - h_hi(h1));
                }
            }
        }
    }
}

// ---------------------------------------------------------------------------
// Flash attention, fp16 2-pass: S = Qh*(Kh+Kl); O += (Ph+Pl)*Vh.
// Q single fp16; K hi/lo; V single fp16. Per CTA one (b,h) x 128 q-rows.
// smem: Q 18432; 2 KV stages of 27648 (Kh 9216, Kl 9216, V 9216).
// ---------------------------------------------------------------------------
#define FSTG 27648
__global__ void __launch_bounds__(256, 2) flash_kernel(
    const __half* __restrict__ QKVh, const __half* __restrict__ QKVl,
    const float* __restrict__ sinv, const __half* __restrict__ pbb,
    const float* __restrict__ mask,
    __half* __restrict__ Ch, __half* __restrict__ Cl)
{
    extern __shared__ char smem[];
    const uint32_t sb = cvta_smem(smem);
    const int tid = threadIdx.x, lane = tid & 31, warp = tid >> 5;
    const int qb = blockIdx.x << 7;
    const int bh = blockIdx.y, b = bh & 3, h = bh >> 2;
    const uint32_t sQ = sb;
    const uint32_t sKV = sb + 18432;

    // Q (hi only) + stage 0
#pragma unroll
    for (int i = 0; i < 4; i++) {
        int idx = tid + (i << 8);
        int r = idx >> 3, c = idx & 7;
        size_t off = ((size_t)(b * Sn + qb + r)) * QKVS + h * 64 + c * 8;
        CP16(sQ + r * 144 + c * 16, QKVh + off);
    }
#pragma unroll
    for (int i = 0; i < 2; i++) {
        int idx = tid + (i << 8);
        int r = idx >> 3, c = idx & 7;
        size_t off = ((size_t)(b * Sn + r)) * QKVS + h * 64 + c * 8;
        uint32_t d = sKV + r * 144 + c * 16;
        CP16(d, QKVh + off + 512);            // K hi
        CP16(d + 9216, QKVl + off + 512);     // K lo
        CP16(d + 18432, QKVh + off + 1024);   // V hi
    }
    CP_COMMIT();

    const int qr0 = qb + (warp << 4) + (lane >> 2);
    const float* sv0 = sinv + ((size_t)(b * Sn + qr0)) * Sn;
    const float* sv1 = sv0 + (size_t)8 * Sn;
    const __half* pb0 = pbb + ((size_t)(h * Sn + qr0)) * Sn;
    const __half* pb1 = pb0 + (size_t)8 * Sn;
    const float* mrow = mask + b * Sn;

    float oacc[8][4];
#pragma unroll
    for (int t = 0; t < 8; t++)
#pragma unroll
        for (int r = 0; r < 4; r++) oacc[t][r] = 0.0f;
    float m0 = -1e30f, m1 = -1e30f, l0 = 0.0f, l1 = 0.0f;

    for (int it = 0; it < 32; it++) {
        if (it + 1 < 32) {
            const uint32_t s = sKV + ((it + 1) & 1) * FSTG;
            const int k0n = (it + 1) << 6;
#pragma unroll
            for (int i = 0; i < 2; i++) {
                int idx = tid + (i << 8);
                int r = idx >> 3, c = idx & 7;
                size_t off = ((size_t)(b * Sn + k0n + r)) * QKVS + h * 64 + c * 8;
                uint32_t d = s + r * 144 + c * 16;
                CP16(d, QKVh + off + 512);
                CP16(d + 9216, QKVl + off + 512);
                CP16(d + 18432, QKVh + off + 1024);
            }
        }
        CP_COMMIT();
        CP_WAIT1();
        __syncthreads();

        const uint32_t stg = sKV + (it & 1) * FSTG;
        float sacc[8][4];
#pragma unroll
        for (int t = 0; t < 8; t++)
#pragma unroll
            for (int r = 0; r < 4; r++) sacc[t][r] = 0.0f;

        // S = Qh*(Kh+Kl)
#pragma unroll
        for (int kc = 0; kc < 4; kc++) {
            uint32_t aq[4];
            const uint32_t qa = sQ + ((warp << 4) + (lane & 15)) * 144 +
                                ((kc << 4) + ((lane >> 4) << 3)) * 2;
            LDSM4(aq, qa);
#pragma unroll
            for (int nb = 0; nb < 4; nb++) {
                uint32_t kbh[4], kbl[4];
                const uint32_t ka = stg + ((nb << 4) + (lane & 15)) * 144 +
                                    ((kc << 4) + ((lane >> 4) << 3)) * 2;
                LDSM4(kbh, ka);
                LDSM4(kbl, ka + 9216);
#pragma unroll
                for (int tt = 0; tt < 2; tt++) {
                    const int t = (nb << 1) + tt;
                    uint32_t bh_[2] = {kbh[tt], kbh[tt + 2]};
                    uint32_t bl_[2] = {kbl[tt], kbl[tt + 2]};
                    mma16816(sacc[t], aq, bh_);
                    mma16816(sacc[t], aq, bl_);
                }
            }
        }

        // epilogue: sinv + pb(fp16) + mask, online softmax
        const int k0 = it << 6;
        float tm0 = -1e30f, tm1 = -1e30f;
#pragma unroll
        for (int t = 0; t < 8; t++) {
            const int n = k0 + (t << 3) + ((lane & 3) << 1);
            float2 s0 = *(const float2*)(sv0 + n);
            float2 s1 = *(const float2*)(sv1 + n);
            float2 mk = *(const float2*)(mrow + n);
            uint32_t pu0 = *(const uint32_t*)(pb0 + n);
            uint32_t pu1 = *(const uint32_t*)(pb1 + n);
            sacc[t][0] = fmaf(sacc[t][0], s0.x, h_lo(pu0) + mk.x);
            sacc[t][1] = fmaf(sacc[t][1], s0.y, h_hi(pu0) + mk.y);
            sacc[t][2] = fmaf(sacc[t][2], s1.x, h_lo(pu1) + mk.x);
            sacc[t][3] = fmaf(sacc[t][3], s1.y, h_hi(pu1) + mk.y);
            tm0 = fmaxf(tm0, fmaxf(sacc[t][0], sacc[t][1]));
            tm1 = fmaxf(tm1, fmaxf(sacc[t][2], sacc[t][3]));
        }
        tm0 = fmaxf(tm0, __shfl_xor_sync(0xffffffffu, tm0, 1));
        tm0 = fmaxf(tm0, __shfl_xor_sync(0xffffffffu, tm0, 2));
        tm1 = fmaxf(tm1, __shfl_xor_sync(0xffffffffu, tm1, 1));
        tm1 = fmaxf(tm1, __shfl_xor_sync(0xffffffffu, tm1, 2));
        const float mn0 = fmaxf(m0, tm0), mn1 = fmaxf(m1, tm1);
        const float c0 = ex2f((m0 - mn0) * L2E), c1 = ex2f((m1 - mn1) * L2E);
        m0 = mn0; m1 = mn1;

        float rs0 = 0.0f, rs1 = 0.0f;
        uint32_t aph[4][4], apl[4][4];
#pragma unroll
        for (int t = 0; t < 8; t++) {
            float p00 = ex2f((sacc[t][0] - m0) * L2E);
            float p01 = ex2f((sacc[t][1] - m0) * L2E);
            float p10 = ex2f((sacc[t][2] - m1) * L2E);
            float p11 = ex2f((sacc[t][3] - m1) * L2E);
            rs0 += p00 + p01; rs1 += p10 + p11;
            uint32_t h0 = pack_h2(p00, p01);
            uint32_t h1 = pack_h2(p10, p11);
            const int kc2 = t >> 1, hf = (t & 1) << 1;
            aph[kc2][hf] = h0; aph[kc2][hf + 1] = h1;
            apl[kc2][hf] = pack_h2(p00 - h_lo(h0), p01 - h_hi(h0));
            apl[kc2][hf + 1] = pack_h2(p10 - h_lo(h1), p11 - h_hi(h1));
        }
        rs0 += __shfl_xor_sync(0xffffffffu, rs0, 1);
        rs0 += __shfl_xor_sync(0xffffffffu, rs0, 2);
        rs1 += __shfl_xor_sync(0xffffffffu, rs1, 1);
        rs1 += __shfl_xor_sync(0xffffffffu, rs1, 2);
        l0 = l0 * c0 + rs0;
        l1 = l1 * c1 + rs1;
#pragma unroll
        for (int t = 0; t < 8; t++) {
            oacc[t][0] *= c0; oacc[t][1] *= c0;
            oacc[t][2] *= c1; oacc[t][3] *= c1;
        }

        // O += (Ph+Pl)*Vh
#pragma unroll
        for (int kc2 = 0; kc2 < 4; kc2++) {
#pragma unroll
            for (int dnb = 0; dnb < 4; dnb++) {
                uint32_t vfh[2][2];
                const uint32_t va = stg + 18432 +
                    ((kc2 << 4) + (lane & 15)) * 144 +
                    ((dnb << 4) + ((lane >> 4) << 3)) * 2;
                LDSM4T(vfh[0], vfh[1], va);
#pragma unroll
                for (int tt = 0; tt < 2; tt++) {
                    const int t = (dnb << 1) + tt;
                    mma16816(oacc[t], aph[kc2], vfh[tt]);
                    mma16816(oacc[t], apl[kc2], vfh[tt]);
                }
            }
        }
        __syncthreads();
    }

    const float inv0 = 1.0f / l0, inv1 = 1.0f / l1;
#pragma unroll
    for (int t = 0; t < 8; t++) {
        const int d = (t << 3) + ((lane & 3) << 1);
        const size_t o0 = ((size_t)(b * Sn + qr0)) * Hn + h * 64 + d;
        const size_t o1 = ((size_t)(b * Sn + qr0 + 8)) * Hn + h * 64 + d;
        float v0 = oacc[t][0] * inv0, v1 = oacc[t][1] * inv0;
        float v2 = oacc[t][2] * inv1, v3 = oacc[t][3] * inv1;
        uint32_t h0 = pack_h2(v0, v1), h1 = pack_h2(v2, v3);
        *(uint32_t*)(Ch + o0) = h0;
        *(uint32_t*)(Cl + o0) = pack_h2(v0 - h_lo(h0), v1 - h_hi(h0));
        *(uint32_t*)(Ch + o1) = h1;
        *(uint32_t*)(Cl + o1) = pack_h2(v2 - h_lo(h1), v3 - h_hi(h1));
    }
}

// ---------------------------------------------------------------------------
// LayerNorm over H=512; optional fp16 hi/lo outputs.
// ---------------------------------------------------------------------------
__global__ void __launch_bounds__(256) ln_kernel(
    const float* __restrict__ in, const float* __restrict__ g,
    const float* __restrict__ bta, float* __restrict__ out,
    __half* __restrict__ ho, __half* __restrict__ lo_)
{
    const size_t base = (size_t)blockIdx.x * Hn;
    const int tid = threadIdx.x;
    __shared__ float sh[8], sh2[8];
    float x0 = in[base + tid], x1 = in[base + tid + 256];
    float s = x0 + x1;
    for (int o = 16; o; o >>= 1) s += __shfl_xor_sync(0xffffffffu, s, o);
    if ((tid & 31) == 0) sh[tid >> 5] = s;
    __syncthreads();
    s = 0.0f;
#pragma unroll
    for (int i = 0; i < 8; i++) s += sh[i];
    const float mean = s * (1.0f / Hn);
    const float d0 = x0 - mean, d1 = x1 - mean;
    float vv = d0 * d0 + d1 * d1;
    for (int o = 16; o; o >>= 1) vv += __shfl_xor_sync(0xffffffffu, vv, o);
    if ((tid & 31) == 0) sh2[tid >> 5] = vv;
    __syncthreads();
    vv = 0.0f;
#pragma unroll
    for (int i = 0; i < 8; i++) vv += sh2[i];
    const float inv = rsqrtf(vv * (1.0f / Hn) + 1e-12f);
    const float y0 = d0 * inv * g[tid] + bta[tid];
    const float y1 = d1 * inv * g[tid + 256] + bta[tid + 256];
    out[base + tid] = y0;
    out[base + tid + 256] = y1;
    if (ho) {
        __half h0 = __float2half_rn(y0);
        __half h1 = __float2half_rn(y1);
        ho[base + tid] = h0;
        ho[base + tid + 256] = h1;
        lo_[base + tid] = __float2half_rn(y0 - __half2float(h0));
        lo_[base + tid + 256] = __float2half_rn(y1 - __half2float(h1));
    }
}

// ---------------------------------------------------------------------------
extern "C" void kernel_launch(void* const* d_in, const int* in_sizes, int n_in,
                              void* d_out, int out_size)
{
    (void)in_sizes; (void)n_in; (void)out_size;
    const float* qs   = (const float*)d_in[0];
    const float* mask = (const float*)d_in[1];
    const float* pb   = (const float*)d_in[2];
    const int*   ts   = (const int*)d_in[3];
    const float* wq  = (const float*)d_in[4];  const float* bq  = (const float*)d_in[5];
    const float* wk  = (const float*)d_in[6];  const float* bk  = (const float*)d_in[7];
    const float* wv  = (const float*)d_in[8];  const float* bv  = (const float*)d_in[9];
    const float* wo  = (const float*)d_in[10]; const float* bo  = (const float*)d_in[11];
    const float* l1g = (const float*)d_in[12]; const float* l1b = (const float*)d_in[13];
    const float* wi  = (const float*)d_in[14]; const float* bi  = (const float*)d_in[15];
    const float* wo2 = (const float*)d_in[16]; const float* bo2 = (const float*)d_in[17];
    const float* l2g = (const float*)d_in[18]; const float* l2b = (const float*)d_in[19];

    float *x, *attn, *bqkv, *sinvp;
    cudaGetSymbolAddress((void**)&x,    g_x);
    cudaGetSymbolAddress((void**)&attn, g_attn);
    cudaGetSymbolAddress((void**)&bqkv, g_bqkv);
    cudaGetSymbolAddress((void**)&sinvp, g_sinv);

    __half *qkvh, *qkvl, *ch, *cl, *xh, *xl, *th, *tl, *fh, *fl, *pbb;
    cudaGetSymbolAddress((void**)&qkvh, g_qkvh); cudaGetSymbolAddress((void**)&qkvl, g_qkvl);
    cudaGetSymbolAddress((void**)&ch, g_ch); cudaGetSymbolAddress((void**)&cl, g_cl);
    cudaGetSymbolAddress((void**)&xh, g_xh); cudaGetSymbolAddress((void**)&xl, g_xl);
    cudaGetSymbolAddress((void**)&th, g_th); cudaGetSymbolAddress((void**)&tl, g_tl);
    cudaGetSymbolAddress((void**)&fh, g_fh); cudaGetSymbolAddress((void**)&fl, g_fl);
    cudaGetSymbolAddress((void**)&pbb, g_pbb);

    __half *wqkvh, *wqkvl, *woh, *wol, *wih, *wil, *w2h, *w2l;
    cudaGetSymbolAddress((void**)&wqkvh, g_wqkvh); cudaGetSymbolAddress((void**)&wqkvl, g_wqkvl);
    cudaGetSymbolAddress((void**)&woh, g_woh); cudaGetSymbolAddress((void**)&wol, g_wol);
    cudaGetSymbolAddress((void**)&wih, g_wih); cudaGetSymbolAddress((void**)&wil, g_wil);
    cudaGetSymbolAddress((void**)&w2h, g_w2h); cudaGetSymbolAddress((void**)&w2l, g_w2l);

    const int HM_SMEM = 2 * STAGE_BYTES;  // 75776
    const int FL_SMEM = 18432 + 2 * FSTG; // 73728
    cudaFuncSetAttribute(hmma_gemm<0>, cudaFuncAttributeMaxDynamicSharedMemorySize, HM_SMEM);
    cudaFuncSetAttribute(hmma_gemm<1>, cudaFuncAttributeMaxDynamicSharedMemorySize, HM_SMEM);
    cudaFuncSetAttribute(hmma_gemm<2>, cudaFuncAttributeMaxDynamicSharedMemorySize, HM_SMEM);
    cudaFuncSetAttribute(flash_kernel, cudaFuncAttributeMaxDynamicSharedMemorySize, FL_SMEM);

    const int PBN = NHn * Sn * Sn;
    prep_kernel<<<6147, 256>>>(wq, wk, wv, wo, wi, wo2, bq, bk, bv,
                               wqkvh, wqkvl, woh, wol, wih, wil, w2h, w2l, bqkv);
    cvt_h_kernel<<<PBN / 2048, 256>>>(pb, pbb, PBN);
    sinv_kernel<<<Bn * Sn, 256>>>(ts, sinvp);
    split_kernel<<<(Mn * Hn) / 2048, 256>>>(qs, xh, xl, Mn * Hn);

    dim3 gqkv(QKVS / 128, Mn / 128);  // (12, 64)
    dim3 gproj(Hn / 128, Mn / 128);   // (4, 64)
    dim3 gff(Fn / 128, Mn / 128);     // (16, 64)
    dim3 gfl(Sn / 128, Bn * NHn);     // (16, 32)

    for (int l = 0; l < Ln; l++) {
        const size_t wOff  = (size_t)l * Hn * Hn;
        const size_t bOff  = (size_t)l * Hn;
        const size_t wiOff = (size_t)l * Hn * Fn;
        const size_t biOff = (size_t)l * Fn;
        const float* xres = (l == 0) ? qs : x;

        hmma_gemm<0><<<gqkv, 256, HM_SMEM>>>(xh, xl,
            wqkvh + (size_t)l * Hn * QKVS, wqkvl + (size_t)l * Hn * QKVS,
            bqkv + l * QKVS, nullptr, nullptr, qkvh, qkvl, Hn, QKVS, 2);

        flash_kernel<<<gfl, 256, FL_SMEM>>>(qkvh, qkvl, sinvp, pbb, mask, ch, cl);

        hmma_gemm<1><<<gproj, 256, HM_SMEM>>>(ch, cl, woh + wOff, wol + wOff,
                                              bo + bOff, xres, attn, nullptr, nullptr,
                                              Hn, Hn, 0);
        ln_kernel<<<Mn, 256>>>(attn, l1g + bOff, l1b + bOff, attn, th, tl);

        hmma_gemm<2><<<gff, 256, HM_SMEM>>>(th, tl, wih + wiOff, wil + wiOff,
                                            bi + biOff, nullptr, nullptr, fh, fl,
                                            Hn, Fn, 1);
        hmma_gemm<1><<<gproj, 256, HM_SMEM>>>(fh, fl, w2h + wiOff, w2l + wiOff,
                                              bo2 + bOff, attn, x, nullptr, nullptr,
                                              Fn, Hn, 0);

        float* lnout = (l == Ln - 1) ? (float*)d_out : x;
        ln_kernel<<<Mn, 256>>>(x, l2g + bOff, l2b + bOff, lnout,
                               (l == Ln - 1) ? nullptr : xh,
                               (l == Ln - 1) ? nullptr : xl);
    }
}

// round 10
// speedup vs baseline: 4.3721x; 1.3542x over previous
#include <cuda_runtime.h>
#include <cuda_fp16.h>
#include <math.h>
#include <stdint.h>

// Problem constants
#define Bn 4
#define Sn 2048
#define Hn 512
#define NHn 8
#define DHn 64
#define Fn 2048
#define Ln 4
#define Mn (Bn * Sn)  // 8192
#define QKVS 1536
#define L2E 1.4426950408889634f

// ---------------- scratch (device globals; no allocation allowed) ----------
__device__ float g_x[Mn * Hn];
__device__ float g_attn[Mn * Hn];
__device__ float g_sinv[(size_t)Bn * Sn * Sn];          // 67 MB inv-scale

__device__ __half g_qkv[(size_t)Mn * QKVS];
__device__ __half g_ch[Mn * Hn];   // ctx
__device__ __half g_xh[Mn * Hn];
__device__ __half g_th[Mn * Hn];   // attn (post ln1)
__device__ __half g_fh[(size_t)Mn * Fn];

// weights hi/lo
__device__ __half g_wqkvh[Ln * Hn * QKVS], g_wqkvl[Ln * Hn * QKVS];
__device__ __half g_woh[Ln * Hn * Hn], g_wol[Ln * Hn * Hn];
__device__ __half g_wih[Ln * Hn * Fn], g_wil[Ln * Hn * Fn];
__device__ __half g_w2h[Ln * Fn * Hn], g_w2l[Ln * Fn * Hn];
__device__ float g_bqkv[Ln * QKVS];
__device__ __half g_pbb[(size_t)NHn * Sn * Sn];   // fp16 position bias

// ---------------- helpers ---------------------------------------------------
__device__ __forceinline__ uint32_t cvta_smem(const void* p) {
    uint32_t a;
    asm("{ .reg .u64 t; cvta.to.shared.u64 t, %1; cvt.u32.u64 %0, t; }"
        : "=r"(a) : "l"(p));
    return a;
}

#define CP16(dst, src) \
    asm volatile("cp.async.cg.shared.global [%0], [%1], 16;" :: "r"(dst), "l"(src))
#define CP_COMMIT() asm volatile("cp.async.commit_group;" ::: "memory")
#define CP_WAIT0()  asm volatile("cp.async.wait_group 0;" ::: "memory")
#define CP_WAIT1()  asm volatile("cp.async.wait_group 1;" ::: "memory")

#define LDSM4(r, addr)                                                          \
    asm volatile("ldmatrix.sync.aligned.m8n8.x4.shared.b16 {%0,%1,%2,%3}, [%4];"\
        : "=r"((r)[0]), "=r"((r)[1]), "=r"((r)[2]), "=r"((r)[3]) : "r"(addr))
#define LDSM4T(r01, r23, addr)                                                  \
    asm volatile("ldmatrix.sync.aligned.m8n8.x4.trans.shared.b16 {%0,%1,%2,%3}, [%4];"\
        : "=r"((r01)[0]), "=r"((r01)[1]), "=r"((r23)[0]), "=r"((r23)[1]) : "r"(addr))

__device__ __forceinline__ void mma16816(float* c, const uint32_t* a, const uint32_t* b) {
    asm volatile(
        "mma.sync.aligned.m16n8k16.row.col.f32.f16.f16.f32 "
        "{%0,%1,%2,%3}, {%4,%5,%6,%7}, {%8,%9}, {%0,%1,%2,%3};"
        : "+f"(c[0]), "+f"(c[1]), "+f"(c[2]), "+f"(c[3])
        : "r"(a[0]), "r"(a[1]), "r"(a[2]), "r"(a[3]), "r"(b[0]), "r"(b[1]));
}

__device__ __forceinline__ uint32_t pack_h2(float lo, float hi) {
    __half2 p = __floats2half2_rn(lo, hi);
    return *reinterpret_cast<uint32_t*>(&p);
}
__device__ __forceinline__ float h_lo(uint32_t u) {
    return __half2float(__ushort_as_half((unsigned short)(u & 0xffffu)));
}
__device__ __forceinline__ float h_hi(uint32_t u) {
    return __half2float(__ushort_as_half((unsigned short)(u >> 16)));
}
__device__ __forceinline__ float ex2f(float x) {
    float y;
    asm("ex2.approx.ftz.f32 %0, %1;" : "=f"(y) : "f"(x));
    return y;
}
__device__ __forceinline__ float rcpf(float x) {
    float y;
    asm("rcp.approx.ftz.f32 %0, %1;" : "=f"(y) : "f"(x));
    return y;
}
// 1/scale = (u + 60000) / (9u + 480000) where u = max(dt_ms, 0)
__device__ __forceinline__ float sinv_of(int dt) {
    float u = fmaxf((float)dt, 0.0f);
    return (u + 60000.0f) * rcpf(fmaf(u, 9.0f, 480000.0f));
}

// split 8 fp32 -> hi/lo fp16x8 and store (weights only)
__device__ __forceinline__ void split8_store(
    const float* __restrict__ src, __half* __restrict__ h, __half* __restrict__ l)
{
    float4 a = *(const float4*)src;
    float4 b = *(const float4*)(src + 4);
    float v[8] = {a.x, a.y, a.z, a.w, b.x, b.y, b.z, b.w};
    __align__(16) __half hh[8];
    __align__(16) __half ll[8];
#pragma unroll
    for (int j = 0; j < 8; j++) {
        hh[j] = __float2half_rn(v[j]);
        ll[j] = __float2half_rn(v[j] - __half2float(hh[j]));
    }
    *(uint4*)h = *(const uint4*)hh;
    *(uint4*)l = *(const uint4*)ll;
}

// smem stage layout for dense GEMM: A 128x80B, Bh 32x272B, Bl 32x272B
#define OFF_AH 0
#define OFF_BH 10240
#define OFF_BL 18944
#define STAGE_BYTES 27648   // x2 stages = 55296

// ---------------------------------------------------------------------------
__global__ void __launch_bounds__(256) cvt_h_kernel(
    const float* __restrict__ x, __half* __restrict__ y, int n)
{
    int i = (blockIdx.x * 256 + threadIdx.x) * 8;
    if (i >= n) return;
    float4 a = *(const float4*)(x + i);
    float4 b = *(const float4*)(x + i + 4);
    float v[8] = {a.x, a.y, a.z, a.w, b.x, b.y, b.z, b.w};
    __align__(16) __half hh[8];
#pragma unroll
    for (int j = 0; j < 8; j++) hh[j] = __float2half_rn(v[j]);
    *(uint4*)(y + i) = *(const uint4*)hh;
}

// sinv[b][q][k] = 1/scale. One block per (b,q) row.
__global__ void __launch_bounds__(256) sinv_kernel(
    const int* __restrict__ ts, float* __restrict__ sv)
{
    const int bq = blockIdx.x;
    const int b = bq >> 11;
    const int tq = ts[bq];
    const int* tr = ts + b * Sn;
    float* out = sv + (size_t)bq * Sn;
#pragma unroll
    for (int kk = 0; kk < 2; kk++) {
        int k = (threadIdx.x + (kk << 8)) << 2;
        int4 tk = *(const int4*)(tr + k);
        float4 o;
        o.x = sinv_of(tq - tk.x);
        o.y = sinv_of(tq - tk.y);
        o.z = sinv_of(tq - tk.z);
        o.w = sinv_of(tq - tk.w);
        *(float4*)(out + k) = o;
    }
}

// ---------------------------------------------------------------------------
// Mega weight-prep (splits + qkv pack + bias pack)
// ---------------------------------------------------------------------------
__global__ void __launch_bounds__(256) prep_kernel(
    const float* __restrict__ wq, const float* __restrict__ wk,
    const float* __restrict__ wv, const float* __restrict__ wo,
    const float* __restrict__ wi, const float* __restrict__ wo2,
    const float* __restrict__ bq, const float* __restrict__ bk,
    const float* __restrict__ bv,
    __half* __restrict__ wqkvh, __half* __restrict__ wqkvl,
    __half* __restrict__ woh, __half* __restrict__ wol,
    __half* __restrict__ wih, __half* __restrict__ wil,
    __half* __restrict__ w2h, __half* __restrict__ w2l,
    float* __restrict__ bqkv)
{
    const int blk = blockIdx.x;
    if (blk < 1536) {
        const int seg = blk >> 9, b2 = blk & 511;
        const float* src = (seg == 0) ? wq : (seg == 1) ? wk : wv;
        const int coloff = seg << 9;
        const int i = (b2 * 256 + threadIdx.x) * 8;
        const int row = i >> 9, col = i & 511;
        const size_t d = (size_t)row * QKVS + coloff + col;
        split8_store(src + i, wqkvh + d, wqkvl + d);
    } else if (blk < 2048) {
        const int i = ((blk - 1536) * 256 + threadIdx.x) * 8;
        split8_store(wo + i, woh + i, wol + i);
    } else if (blk < 4096) {
        const int i = ((blk - 2048) * 256 + threadIdx.x) * 8;
        split8_store(wi + i, wih + i, wil + i);
    } else if (blk < 6144) {
        const int i = ((blk - 4096) * 256 + threadIdx.x) * 8;
        split8_store(wo2 + i, w2h + i, w2l + i);
    } else {
        const int i0 = ((blk - 6144) * 256 + threadIdx.x) * 8;
#pragma unroll
        for (int j = 0; j < 8; j++) {
            const int idx = i0 + j;
            const int l = idx / QKVS, jj = idx % QKVS;
            const int seg = jj >> 9, col = jj & 511;
            const float* s = (seg == 0) ? bq : (seg == 1) ? bk : bv;
            bqkv[idx] = s[l * Hn + col];
        }
    }
}

// ---------------------------------------------------------------------------
// HMMA GEMM, A single fp16 x W hi/lo (2-pass): C = Ah*(Wh+Wl).
// CTA 128x128, BK=32, 8 warps.
// EPI 0: bias -> fp16.  EPI 1: bias+res -> fp32.  EPI 2: bias+GELU -> fp16.
// ---------------------------------------------------------------------------
template <int EPI>
__global__ void __launch_bounds__(256, 2) hmma_gemm(
    const __half* __restrict__ Ahp,
    const __half* __restrict__ Bhp, const __half* __restrict__ Blp,
    const float* __restrict__ bias, const float* __restrict__ res,
    float* __restrict__ C, __half* __restrict__ Cho, int K, int N)
{
    extern __shared__ char smem[];
    const uint32_t sb = cvta_smem(smem);
    const int tid = threadIdx.x, lane = tid & 31, warp = tid >> 5;
    const int m0 = blockIdx.y << 7, n0 = blockIdx.x << 7;
    const int wm0 = (warp >> 2) << 6, wn0 = (warp & 3) << 5;

    const int ar = tid >> 2, ac = tid & 3;
    const int br = tid >> 4, bc = tid & 15;

    auto load_stage = [&](int st, int kc) {
        const int k0 = kc << 5;
        const uint32_t s = sb + st * STAGE_BYTES;
        const size_t aoff0 = (size_t)(m0 + ar) * K + k0 + ac * 8;
        const size_t aoff1 = (size_t)(m0 + ar + 64) * K + k0 + ac * 8;
        CP16(s + OFF_AH + ar * 80 + ac * 16, Ahp + aoff0);
        CP16(s + OFF_AH + (ar + 64) * 80 + ac * 16, Ahp + aoff1);
        const size_t boff0 = (size_t)(k0 + br) * N + n0 + bc * 8;
        const size_t boff1 = (size_t)(k0 + br + 16) * N + n0 + bc * 8;
        CP16(s + OFF_BH + br * 272 + bc * 16, Bhp + boff0);
        CP16(s + OFF_BH + (br + 16) * 272 + bc * 16, Bhp + boff1);
        CP16(s + OFF_BL + br * 272 + bc * 16, Blp + boff0);
        CP16(s + OFF_BL + (br + 16) * 272 + bc * 16, Blp + boff1);
        CP_COMMIT();
    };

    float acc[4][4][4];
#pragma unroll
    for (int i = 0; i < 4; i++)
#pragma unroll
        for (int j = 0; j < 4; j++)
#pragma unroll
            for (int r = 0; r < 4; r++) acc[i][j][r] = 0.0f;

    const int nch = K >> 5;
    load_stage(0, 0);

    for (int kc = 0; kc < nch; kc++) {
        const int cur = kc & 1;
        CP_WAIT0();
        __syncthreads();
        if (kc + 1 < nch) load_stage(cur ^ 1, kc + 1);

        const uint32_t s = sb + cur * STAGE_BYTES;
#pragma unroll
        for (int ks = 0; ks < 2; ks++) {
            const uint32_t aoff =
                (wm0 + (lane & 15)) * 80 + ((ks << 4) + ((lane >> 4) << 3)) * 2;
            const uint32_t boff =
                ((ks << 4) + (lane & 15)) * 272 + (wn0 + ((lane >> 4) << 3)) * 2;

            uint32_t ah[4][4];
#pragma unroll
            for (int mt = 0; mt < 4; mt++)
                LDSM4(ah[mt], s + OFF_AH + aoff + mt * (16 * 80));
            {   // pass 1: Ah*Bh
                uint32_t b[4][2];
                LDSM4T(b[0], b[1], s + OFF_BH + boff);
                LDSM4T(b[2], b[3], s + OFF_BH + boff + 32);
#pragma unroll
                for (int mt = 0; mt < 4; mt++)
#pragma unroll
                    for (int nt = 0; nt < 4; nt++) mma16816(acc[mt][nt], ah[mt], b[nt]);
            }
            {   // pass 2: Ah*Bl
                uint32_t b[4][2];
                LDSM4T(b[0], b[1], s + OFF_BL + boff);
                LDSM4T(b[2], b[3], s + OFF_BL + boff + 32);
#pragma unroll
                for (int mt = 0; mt < 4; mt++)
#pragma unroll
                    for (int nt = 0; nt < 4; nt++) mma16816(acc[mt][nt], ah[mt], b[nt]);
            }
        }
    }

#pragma unroll
    for (int mt = 0; mt < 4; mt++) {
        const int m = m0 + wm0 + mt * 16 + (lane >> 2);
#pragma unroll
        for (int nt = 0; nt < 4; nt++) {
            const int n = n0 + wn0 + nt * 8 + (lane & 3) * 2;
            float2 bv = *(const float2*)(bias + n);
            float o0 = acc[mt][nt][0] + bv.x;
            float o1 = acc[mt][nt][1] + bv.y;
            float o2 = acc[mt][nt][2] + bv.x;
            float o3 = acc[mt][nt][3] + bv.y;
            if (EPI == 1) {
                float2 r0 = *(const float2*)(res + (size_t)m * N + n);
                float2 r1 = *(const float2*)(res + (size_t)(m + 8) * N + n);
                o0 += r0.x; o1 += r0.y; o2 += r1.x; o3 += r1.y;
                *(float2*)(C + (size_t)m * N + n) = make_float2(o0, o1);
                *(float2*)(C + (size_t)(m + 8) * N + n) = make_float2(o2, o3);
            } else {
                if (EPI == 2) {
                    o0 = 0.5f * o0 * (1.0f + erff(o0 * 0.7071067811865475f));
                    o1 = 0.5f * o1 * (1.0f + erff(o1 * 0.7071067811865475f));
                    o2 = 0.5f * o2 * (1.0f + erff(o2 * 0.7071067811865475f));
                    o3 = 0.5f * o3 * (1.0f + erff(o3 * 0.7071067811865475f));
                }
                *(uint32_t*)(Cho + (size_t)m * N + n) = pack_h2(o0, o1);
                *(uint32_t*)(Cho + (size_t)(m + 8) * N + n) = pack_h2(o2, o3);
            }
        }
    }
}

// ---------------------------------------------------------------------------
// Flash attention, fp16 1-pass both GEMMs: S = Qh*Kh; O += Ph*Vh.
// smem: Q 18432; 2 KV stages of 18432 (K 9216, V 9216).
// ---------------------------------------------------------------------------
#define FSTG 18432
__global__ void __launch_bounds__(256, 2) flash_kernel(
    const __half* __restrict__ QKV,
    const float* __restrict__ sinv, const __half* __restrict__ pbb,
    const float* __restrict__ mask, __half* __restrict__ Ch)
{
    extern __shared__ char smem[];
    const uint32_t sb = cvta_smem(smem);
    const int tid = threadIdx.x, lane = tid & 31, warp = tid >> 5;
    const int qb = blockIdx.x << 7;
    const int bh = blockIdx.y, b = bh & 3, h = bh >> 2;
    const uint32_t sQ = sb;
    const uint32_t sKV = sb + 18432;

    // Q + stage 0
#pragma unroll
    for (int i = 0; i < 4; i++) {
        int idx = tid + (i << 8);
        int r = idx >> 3, c = idx & 7;
        size_t off = ((size_t)(b * Sn + qb + r)) * QKVS + h * 64 + c * 8;
        CP16(sQ + r * 144 + c * 16, QKV + off);
    }
#pragma unroll
    for (int i = 0; i < 2; i++) {
        int idx = tid + (i << 8);
        int r = idx >> 3, c = idx & 7;
        size_t off = ((size_t)(b * Sn + r)) * QKVS + h * 64 + c * 8;
        uint32_t d = sKV + r * 144 + c * 16;
        CP16(d, QKV + off + 512);           // K
        CP16(d + 9216, QKV + off + 1024);   // V
    }
    CP_COMMIT();

    const int qr0 = qb + (warp << 4) + (lane >> 2);
    const float* sv0 = sinv + ((size_t)(b * Sn + qr0)) * Sn;
    const float* sv1 = sv0 + (size_t)8 * Sn;
    const __half* pb0 = pbb + ((size_t)(h * Sn + qr0)) * Sn;
    const __half* pb1 = pb0 + (size_t)8 * Sn;
    const float* mrow = mask + b * Sn;

    float oacc[8][4];
#pragma unroll
    for (int t = 0; t < 8; t++)
#pragma unroll
        for (int r = 0; r < 4; r++) oacc[t][r] = 0.0f;
    float m0 = -1e30f, m1 = -1e30f, l0 = 0.0f, l1 = 0.0f;

    for (int it = 0; it < 32; it++) {
        if (it + 1 < 32) {
            const uint32_t s = sKV + ((it + 1) & 1) * FSTG;
            const int k0n = (it + 1) << 6;
#pragma unroll
            for (int i = 0; i < 2; i++) {
                int idx = tid + (i << 8);
                int r = idx >> 3, c = idx & 7;
                size_t off = ((size_t)(b * Sn + k0n + r)) * QKVS + h * 64 + c * 8;
                uint32_t d = s + r * 144 + c * 16;
                CP16(d, QKV + off + 512);
                CP16(d + 9216, QKV + off + 1024);
            }
        }
        CP_COMMIT();
        CP_WAIT1();
        __syncthreads();

        const uint32_t stg = sKV + (it & 1) * FSTG;
        float sacc[8][4];
#pragma unroll
        for (int t = 0; t < 8; t++)
#pragma unroll
            for (int r = 0; r < 4; r++) sacc[t][r] = 0.0f;

        // S = Qh * Kh
#pragma unroll
        for (int kc = 0; kc < 4; kc++) {
            uint32_t aq[4];
            const uint32_t qa = sQ + ((warp << 4) + (lane & 15)) * 144 +
                                ((kc << 4) + ((lane >> 4) << 3)) * 2;
            LDSM4(aq, qa);
#pragma unroll
            for (int nb = 0; nb < 4; nb++) {
                uint32_t kb[4];
                const uint32_t ka = stg + ((nb << 4) + (lane & 15)) * 144 +
                                    ((kc << 4) + ((lane >> 4) << 3)) * 2;
                LDSM4(kb, ka);
#pragma unroll
                for (int tt = 0; tt < 2; tt++) {
                    const int t = (nb << 1) + tt;
                    uint32_t b_[2] = {kb[tt], kb[tt + 2]};
                    mma16816(sacc[t], aq, b_);
                }
            }
        }

        // epilogue: sinv + pb(fp16) + mask, online softmax
        const int k0 = it << 6;
        float tm0 = -1e30f, tm1 = -1e30f;
#pragma unroll
        for (int t = 0; t < 8; t++) {
            const int n = k0 + (t << 3) + ((lane & 3) << 1);
            float2 s0 = *(const float2*)(sv0 + n);
            float2 s1 = *(const float2*)(sv1 + n);
            float2 mk = *(const float2*)(mrow + n);
            uint32_t pu0 = *(const uint32_t*)(pb0 + n);
            uint32_t pu1 = *(const uint32_t*)(pb1 + n);
            sacc[t][0] = fmaf(sacc[t][0], s0.x, h_lo(pu0) + mk.x);
            sacc[t][1] = fmaf(sacc[t][1], s0.y, h_hi(pu0) + mk.y);
            sacc[t][2] = fmaf(sacc[t][2], s1.x, h_lo(pu1) + mk.x);
            sacc[t][3] = fmaf(sacc[t][3], s1.y, h_hi(pu1) + mk.y);
            tm0 = fmaxf(tm0, fmaxf(sacc[t][0], sacc[t][1]));
            tm1 = fmaxf(tm1, fmaxf(sacc[t][2], sacc[t][3]));
        }
        tm0 = fmaxf(tm0, __shfl_xor_sync(0xffffffffu, tm0, 1));
        tm0 = fmaxf(tm0, __shfl_xor_sync(0xffffffffu, tm0, 2));
        tm1 = fmaxf(tm1, __shfl_xor_sync(0xffffffffu, tm1, 1));
        tm1 = fmaxf(tm1, __shfl_xor_sync(0xffffffffu, tm1, 2));
        const float mn0 = fmaxf(m0, tm0), mn1 = fmaxf(m1, tm1);
        const float c0 = ex2f((m0 - mn0) * L2E), c1 = ex2f((m1 - mn1) * L2E);
        m0 = mn0; m1 = mn1;

        float rs0 = 0.0f, rs1 = 0.0f;
        uint32_t ap[4][4];
#pragma unroll
        for (int t = 0; t < 8; t++) {
            float p00 = ex2f((sacc[t][0] - m0) * L2E);
            float p01 = ex2f((sacc[t][1] - m0) * L2E);
            float p10 = ex2f((sacc[t][2] - m1) * L2E);
            float p11 = ex2f((sacc[t][3] - m1) * L2E);
            rs0 += p00 + p01; rs1 += p10 + p11;
            const int kc2 = t >> 1, hf = (t & 1) << 1;
            ap[kc2][hf] = pack_h2(p00, p01);
            ap[kc2][hf + 1] = pack_h2(p10, p11);
        }
        rs0 += __shfl_xor_sync(0xffffffffu, rs0, 1);
        rs0 += __shfl_xor_sync(0xffffffffu, rs0, 2);
        rs1 += __shfl_xor_sync(0xffffffffu, rs1, 1);
        rs1 += __shfl_xor_sync(0xffffffffu, rs1, 2);
        l0 = l0 * c0 + rs0;
        l1 = l1 * c1 + rs1;
#pragma unroll
        for (int t = 0; t < 8; t++) {
            oacc[t][0] *= c0; oacc[t][1] *= c0;
            oacc[t][2] *= c1; oacc[t][3] *= c1;
        }

        // O += Ph * Vh
#pragma unroll
        for (int kc2 = 0; kc2 < 4; kc2++) {
#pragma unroll
            for (int dnb = 0; dnb < 4; dnb++) {
                uint32_t vf[2][2];
                const uint32_t va = stg + 9216 +
                    ((kc2 << 4) + (lane & 15)) * 144 +
                    ((dnb << 4) + ((lane >> 4) << 3)) * 2;
                LDSM4T(vf[0], vf[1], va);
#pragma unroll
                for (int tt = 0; tt < 2; tt++)
                    mma16816(oacc[(dnb << 1) + tt], ap[kc2], vf[tt]);
            }
        }
        __syncthreads();
    }

    const float inv0 = 1.0f / l0, inv1 = 1.0f / l1;
#pragma unroll
    for (int t = 0; t < 8; t++) {
        const int d = (t << 3) + ((lane & 3) << 1);
        const size_t o0 = ((size_t)(b * Sn + qr0)) * Hn + h * 64 + d;
        const size_t o1 = ((size_t)(b * Sn + qr0 + 8)) * Hn + h * 64 + d;
        *(uint32_t*)(Ch + o0) = pack_h2(oacc[t][0] * inv0, oacc[t][1] * inv0);
        *(uint32_t*)(Ch + o1) = pack_h2(oacc[t][2] * inv1, oacc[t][3] * inv1);
    }
}

// ---------------------------------------------------------------------------
// LayerNorm over H=512; optional fp16 output.
// ---------------------------------------------------------------------------
__global__ void __launch_bounds__(256) ln_kernel(
    const float* __restrict__ in, const float* __restrict__ g,
    const float* __restrict__ bta, float* __restrict__ out,
    __half* __restrict__ ho)
{
    const size_t base = (size_t)blockIdx.x * Hn;
    const int tid = threadIdx.x;
    __shared__ float sh[8], sh2[8];
    float x0 = in[base + tid], x1 = in[base + tid + 256];
    float s = x0 + x1;
    for (int o = 16; o; o >>= 1) s += __shfl_xor_sync(0xffffffffu, s, o);
    if ((tid & 31) == 0) sh[tid >> 5] = s;
    __syncthreads();
    s = 0.0f;
#pragma unroll
    for (int i = 0; i < 8; i++) s += sh[i];
    const float mean = s * (1.0f / Hn);
    const float d0 = x0 - mean, d1 = x1 - mean;
    float vv = d0 * d0 + d1 * d1;
    for (int o = 16; o; o >>= 1) vv += __shfl_xor_sync(0xffffffffu, vv, o);
    if ((tid & 31) == 0) sh2[tid >> 5] = vv;
    __syncthreads();
    vv = 0.0f;
#pragma unroll
    for (int i = 0; i < 8; i++) vv += sh2[i];
    const float inv = rsqrtf(vv * (1.0f / Hn) + 1e-12f);
    const float y0 = d0 * inv * g[tid] + bta[tid];
    const float y1 = d1 * inv * g[tid + 256] + bta[tid + 256];
    out[base + tid] = y0;
    out[base + tid + 256] = y1;
    if (ho) {
        ho[base + tid] = __float2half_rn(y0);
        ho[base + tid + 256] = __float2half_rn(y1);
    }
}

// ---------------------------------------------------------------------------
extern "C" void kernel_launch(void* const* d_in, const int* in_sizes, int n_in,
                              void* d_out, int out_size)
{
    (void)in_sizes; (void)n_in; (void)out_size;
    const float* qs   = (const float*)d_in[0];
    const float* mask = (const float*)d_in[1];
    const float* pb   = (const float*)d_in[2];
    const int*   ts   = (const int*)d_in[3];
    const float* wq  = (const float*)d_in[4];  const float* bq  = (const float*)d_in[5];
    const float* wk  = (const float*)d_in[6];  const float* bk  = (const float*)d_in[7];
    const float* wv  = (const float*)d_in[8];  const float* bv  = (const float*)d_in[9];
    const float* wo  = (const float*)d_in[10]; const float* bo  = (const float*)d_in[11];
    const float* l1g = (const float*)d_in[12]; const float* l1b = (const float*)d_in[13];
    const float* wi  = (const float*)d_in[14]; const float* bi  = (const float*)d_in[15];
    const float* wo2 = (const float*)d_in[16]; const float* bo2 = (const float*)d_in[17];
    const float* l2g = (const float*)d_in[18]; const float* l2b = (const float*)d_in[19];

    float *x, *attn, *bqkv, *sinvp;
    cudaGetSymbolAddress((void**)&x,    g_x);
    cudaGetSymbolAddress((void**)&attn, g_attn);
    cudaGetSymbolAddress((void**)&bqkv, g_bqkv);
    cudaGetSymbolAddress((void**)&sinvp, g_sinv);

    __half *qkv, *ch, *xh, *th, *fh, *pbb;
    cudaGetSymbolAddress((void**)&qkv, g_qkv);
    cudaGetSymbolAddress((void**)&ch, g_ch);
    cudaGetSymbolAddress((void**)&xh, g_xh);
    cudaGetSymbolAddress((void**)&th, g_th);
    cudaGetSymbolAddress((void**)&fh, g_fh);
    cudaGetSymbolAddress((void**)&pbb, g_pbb);

    __half *wqkvh, *wqkvl, *woh, *wol, *wih, *wil, *w2h, *w2l;
    cudaGetSymbolAddress((void**)&wqkvh, g_wqkvh); cudaGetSymbolAddress((void**)&wqkvl, g_wqkvl);
    cudaGetSymbolAddress((void**)&woh, g_woh); cudaGetSymbolAddress((void**)&wol, g_wol);
    cudaGetSymbolAddress((void**)&wih, g_wih); cudaGetSymbolAddress((void**)&wil, g_wil);
    cudaGetSymbolAddress((void**)&w2h, g_w2h); cudaGetSymbolAddress((void**)&w2l, g_w2l);

    const int HM_SMEM = 2 * STAGE_BYTES;  // 55296
    const int FL_SMEM = 18432 + 2 * FSTG; // 55296
    cudaFuncSetAttribute(hmma_gemm<0>, cudaFuncAttributeMaxDynamicSharedMemorySize, HM_SMEM);
    cudaFuncSetAttribute(hmma_gemm<1>, cudaFuncAttributeMaxDynamicSharedMemorySize, HM_SMEM);
    cudaFuncSetAttribute(hmma_gemm<2>, cudaFuncAttributeMaxDynamicSharedMemorySize, HM_SMEM);
    cudaFuncSetAttribute(flash_kernel, cudaFuncAttributeMaxDynamicSharedMemorySize, FL_SMEM);

    const int PBN = NHn * Sn * Sn;
    prep_kernel<<<6147, 256>>>(wq, wk, wv, wo, wi, wo2, bq, bk, bv,
                               wqkvh, wqkvl, woh, wol, wih, wil, w2h, w2l, bqkv);
    cvt_h_kernel<<<PBN / 2048, 256>>>(pb, pbb, PBN);
    sinv_kernel<<<Bn * Sn, 256>>>(ts, sinvp);
    cvt_h_kernel<<<(Mn * Hn) / 2048, 256>>>(qs, xh, Mn * Hn);

    dim3 gqkv(QKVS / 128, Mn / 128);  // (12, 64)
    dim3 gproj(Hn / 128, Mn / 128);   // (4, 64)
    dim3 gff(Fn / 128, Mn / 128);     // (16, 64)
    dim3 gfl(Sn / 128, Bn * NHn);     // (16, 32)

    for (int l = 0; l < Ln; l++) {
        const size_t wOff  = (size_t)l * Hn * Hn;
        const size_t bOff  = (size_t)l * Hn;
        const size_t wiOff = (size_t)l * Hn * Fn;
        const size_t biOff = (size_t)l * Fn;
        const float* xres = (l == 0) ? qs : x;

        hmma_gemm<0><<<gqkv, 256, HM_SMEM>>>(xh,
            wqkvh + (size_t)l * Hn * QKVS, wqkvl + (size_t)l * Hn * QKVS,
            bqkv + l * QKVS, nullptr, nullptr, qkv, Hn, QKVS);

        flash_kernel<<<gfl, 256, FL_SMEM>>>(qkv, sinvp, pbb, mask, ch);

        hmma_gemm<1><<<gproj, 256, HM_SMEM>>>(ch, woh + wOff, wol + wOff,
                                              bo + bOff, xres, attn, nullptr, Hn, Hn);
        ln_kernel<<<Mn, 256>>>(attn, l1g + bOff, l1b + bOff, attn, th);

        hmma_gemm<2><<<gff, 256, HM_SMEM>>>(th, wih + wiOff, wil + wiOff,
                                            bi + biOff, nullptr, nullptr, fh, Hn, Fn);
        hmma_gemm<1><<<gproj, 256, HM_SMEM>>>(fh, w2h + wiOff, w2l + wiOff,
                                              bo2 + bOff, attn, x, nullptr, Fn, Hn);

        float* lnout = (l == Ln - 1) ? (float*)d_out : x;
        ln_kernel<<<Mn, 256>>>(x, l2g + bOff, l2b + bOff, lnout,
                               (l == Ln - 1) ? nullptr : xh);
    }
}

// round 11
// speedup vs baseline: 5.2202x; 1.1940x over previous
#include <cuda_runtime.h>
#include <cuda_fp16.h>
#include <math.h>
#include <stdint.h>

// Problem constants
#define Bn 4
#define Sn 2048
#define Hn 512
#define NHn 8
#define DHn 64
#define Fn 2048
#define Ln 4
#define Mn (Bn * Sn)  // 8192
#define QKVS 1536
#define L2E 1.4426950408889634f

// ---------------- scratch (device globals; no allocation allowed) ----------
__device__ float g_x[Mn * Hn];
__device__ float g_attn[Mn * Hn];
__device__ __half g_sinv[(size_t)Bn * Sn * Sn];   // 33 MB inv-scale (fp16)

__device__ __half g_qkv[(size_t)Mn * QKVS];
__device__ __half g_ch[Mn * Hn];   // ctx
__device__ __half g_xh[Mn * Hn];
__device__ __half g_th[Mn * Hn];   // attn (post ln1)
__device__ __half g_fh[(size_t)Mn * Fn];

// weights (single fp16)
__device__ __half g_wqkv[Ln * Hn * QKVS];
__device__ __half g_wo[Ln * Hn * Hn];
__device__ __half g_wi[Ln * Hn * Fn];
__device__ __half g_w2[Ln * Fn * Hn];
__device__ float g_bqkv[Ln * QKVS];
__device__ __half g_pbb[(size_t)NHn * Sn * Sn];   // fp16 position bias

// ---------------- helpers ---------------------------------------------------
__device__ __forceinline__ uint32_t cvta_smem(const void* p) {
    uint32_t a;
    asm("{ .reg .u64 t; cvta.to.shared.u64 t, %1; cvt.u32.u64 %0, t; }"
        : "=r"(a) : "l"(p));
    return a;
}

#define CP16(dst, src) \
    asm volatile("cp.async.cg.shared.global [%0], [%1], 16;" :: "r"(dst), "l"(src))
#define CP_COMMIT() asm volatile("cp.async.commit_group;" ::: "memory")
#define CP_WAIT0()  asm volatile("cp.async.wait_group 0;" ::: "memory")
#define CP_WAIT1()  asm volatile("cp.async.wait_group 1;" ::: "memory")

#define LDSM4(r, addr)                                                          \
    asm volatile("ldmatrix.sync.aligned.m8n8.x4.shared.b16 {%0,%1,%2,%3}, [%4];"\
        : "=r"((r)[0]), "=r"((r)[1]), "=r"((r)[2]), "=r"((r)[3]) : "r"(addr))
#define LDSM4T(r01, r23, addr)                                                  \
    asm volatile("ldmatrix.sync.aligned.m8n8.x4.trans.shared.b16 {%0,%1,%2,%3}, [%4];"\
        : "=r"((r01)[0]), "=r"((r01)[1]), "=r"((r23)[0]), "=r"((r23)[1]) : "r"(addr))

__device__ __forceinline__ void mma16816(float* c, const uint32_t* a, const uint32_t* b) {
    asm volatile(
        "mma.sync.aligned.m16n8k16.row.col.f32.f16.f16.f32 "
        "{%0,%1,%2,%3}, {%4,%5,%6,%7}, {%8,%9}, {%0,%1,%2,%3};"
        : "+f"(c[0]), "+f"(c[1]), "+f"(c[2]), "+f"(c[3])
        : "r"(a[0]), "r"(a[1]), "r"(a[2]), "r"(a[3]), "r"(b[0]), "r"(b[1]));
}

__device__ __forceinline__ uint32_t pack_h2(float lo, float hi) {
    __half2 p = __floats2half2_rn(lo, hi);
    return *reinterpret_cast<uint32_t*>(&p);
}
__device__ __forceinline__ float h_lo(uint32_t u) {
    return __half2float(__ushort_as_half((unsigned short)(u & 0xffffu)));
}
__device__ __forceinline__ float h_hi(uint32_t u) {
    return __half2float(__ushort_as_half((unsigned short)(u >> 16)));
}
__device__ __forceinline__ float ex2f(float x) {
    float y;
    asm("ex2.approx.ftz.f32 %0, %1;" : "=f"(y) : "f"(x));
    return y;
}
__device__ __forceinline__ float rcpf(float x) {
    float y;
    asm("rcp.approx.ftz.f32 %0, %1;" : "=f"(y) : "f"(x));
    return y;
}
// 1/scale = (u + 60000) / (9u + 480000) where u = max(dt_ms, 0)
__device__ __forceinline__ float sinv_of(int dt) {
    float u = fmaxf((float)dt, 0.0f);
    return (u + 60000.0f) * rcpf(fmaf(u, 9.0f, 480000.0f));
}

// convert 8 fp32 -> fp16x8 and store
__device__ __forceinline__ void cvt8_store(
    const float* __restrict__ src, __half* __restrict__ h)
{
    float4 a = *(const float4*)src;
    float4 b = *(const float4*)(src + 4);
    float v[8] = {a.x, a.y, a.z, a.w, b.x, b.y, b.z, b.w};
    __align__(16) __half hh[8];
#pragma unroll
    for (int j = 0; j < 8; j++) hh[j] = __float2half_rn(v[j]);
    *(uint4*)h = *(const uint4*)hh;
}

// smem stage layout for dense GEMM: A 128x80B, B 32x272B
#define OFF_AH 0
#define OFF_BH 10240
#define STAGE_BYTES 18944   // x2 stages = 37888

// ---------------------------------------------------------------------------
__global__ void __launch_bounds__(256) cvt_h_kernel(
    const float* __restrict__ x, __half* __restrict__ y, int n)
{
    int i = (blockIdx.x * 256 + threadIdx.x) * 8;
    if (i >= n) return;
    cvt8_store(x + i, y + i);
}

// sinv[b][q][k] = 1/scale (fp16). One block per (b,q) row.
__global__ void __launch_bounds__(256) sinv_kernel(
    const int* __restrict__ ts, __half* __restrict__ sv)
{
    const int bq = blockIdx.x;
    const int b = bq >> 11;
    const int tq = ts[bq];
    const int* tr = ts + b * Sn;
    __half* out = sv + (size_t)bq * Sn;
#pragma unroll
    for (int kk = 0; kk < 2; kk++) {
        int k = (threadIdx.x + (kk << 8)) << 2;
        int4 tk = *(const int4*)(tr + k);
        uint2 o;
        o.x = pack_h2(sinv_of(tq - tk.x), sinv_of(tq - tk.y));
        o.y = pack_h2(sinv_of(tq - tk.z), sinv_of(tq - tk.w));
        *(uint2*)(out + k) = o;
    }
}

// ---------------------------------------------------------------------------
// Mega weight-prep (fp16 cvt + qkv pack + bias pack)
// ---------------------------------------------------------------------------
__global__ void __launch_bounds__(256) prep_kernel(
    const float* __restrict__ wq, const float* __restrict__ wk,
    const float* __restrict__ wv, const float* __restrict__ wo,
    const float* __restrict__ wi, const float* __restrict__ wo2,
    const float* __restrict__ bq, const float* __restrict__ bk,
    const float* __restrict__ bv,
    __half* __restrict__ wqkv, __half* __restrict__ woh,
    __half* __restrict__ wih, __half* __restrict__ w2h,
    float* __restrict__ bqkv)
{
    const int blk = blockIdx.x;
    if (blk < 1536) {
        const int seg = blk >> 9, b2 = blk & 511;
        const float* src = (seg == 0) ? wq : (seg == 1) ? wk : wv;
        const int coloff = seg << 9;
        const int i = (b2 * 256 + threadIdx.x) * 8;
        const int row = i >> 9, col = i & 511;
        cvt8_store(src + i, wqkv + (size_t)row * QKVS + coloff + col);
    } else if (blk < 2048) {
        const int i = ((blk - 1536) * 256 + threadIdx.x) * 8;
        cvt8_store(wo + i, woh + i);
    } else if (blk < 4096) {
        const int i = ((blk - 2048) * 256 + threadIdx.x) * 8;
        cvt8_store(wi + i, wih + i);
    } else if (blk < 6144) {
        const int i = ((blk - 4096) * 256 + threadIdx.x) * 8;
        cvt8_store(wo2 + i, w2h + i);
    } else {
        const int i0 = ((blk - 6144) * 256 + threadIdx.x) * 8;
#pragma unroll
        for (int j = 0; j < 8; j++) {
            const int idx = i0 + j;
            const int l = idx / QKVS, jj = idx % QKVS;
            const int seg = jj >> 9, col = jj & 511;
            const float* s = (seg == 0) ? bq : (seg == 1) ? bk : bv;
            bqkv[idx] = s[l * Hn + col];
        }
    }
}

// ---------------------------------------------------------------------------
// HMMA GEMM, single fp16, 1-pass: C = Ah*Wh.  CTA 128x128, BK=32, 8 warps.
// EPI 0: bias -> fp16.  EPI 1: bias+res -> fp32.  EPI 2: bias+GELU -> fp16.
// ---------------------------------------------------------------------------
template <int EPI>
__global__ void __launch_bounds__(256, 2) hmma_gemm(
    const __half* __restrict__ Ahp, const __half* __restrict__ Bhp,
    const float* __restrict__ bias, const float* __restrict__ res,
    float* __restrict__ C, __half* __restrict__ Cho, int K, int N)
{
    extern __shared__ char smem[];
    const uint32_t sb = cvta_smem(smem);
    const int tid = threadIdx.x, lane = tid & 31, warp = tid >> 5;
    const int m0 = blockIdx.y << 7, n0 = blockIdx.x << 7;
    const int wm0 = (warp >> 2) << 6, wn0 = (warp & 3) << 5;

    const int ar = tid >> 2, ac = tid & 3;
    const int br = tid >> 4, bc = tid & 15;

    auto load_stage = [&](int st, int kc) {
        const int k0 = kc << 5;
        const uint32_t s = sb + st * STAGE_BYTES;
        const size_t aoff0 = (size_t)(m0 + ar) * K + k0 + ac * 8;
        const size_t aoff1 = (size_t)(m0 + ar + 64) * K + k0 + ac * 8;
        CP16(s + OFF_AH + ar * 80 + ac * 16, Ahp + aoff0);
        CP16(s + OFF_AH + (ar + 64) * 80 + ac * 16, Ahp + aoff1);
        const size_t boff0 = (size_t)(k0 + br) * N + n0 + bc * 8;
        const size_t boff1 = (size_t)(k0 + br + 16) * N + n0 + bc * 8;
        CP16(s + OFF_BH + br * 272 + bc * 16, Bhp + boff0);
        CP16(s + OFF_BH + (br + 16) * 272 + bc * 16, Bhp + boff1);
        CP_COMMIT();
    };

    float acc[4][4][4];
#pragma unroll
    for (int i = 0; i < 4; i++)
#pragma unroll
        for (int j = 0; j < 4; j++)
#pragma unroll
            for (int r = 0; r < 4; r++) acc[i][j][r] = 0.0f;

    const int nch = K >> 5;
    load_stage(0, 0);

    for (int kc = 0; kc < nch; kc++) {
        const int cur = kc & 1;
        CP_WAIT0();
        __syncthreads();
        if (kc + 1 < nch) load_stage(cur ^ 1, kc + 1);

        const uint32_t s = sb + cur * STAGE_BYTES;
#pragma unroll
        for (int ks = 0; ks < 2; ks++) {
            const uint32_t aoff =
                (wm0 + (lane & 15)) * 80 + ((ks << 4) + ((lane >> 4) << 3)) * 2;
            const uint32_t boff =
                ((ks << 4) + (lane & 15)) * 272 + (wn0 + ((lane >> 4) << 3)) * 2;

            uint32_t ah[4][4];
#pragma unroll
            for (int mt = 0; mt < 4; mt++)
                LDSM4(ah[mt], s + OFF_AH + aoff + mt * (16 * 80));
            uint32_t b[4][2];
            LDSM4T(b[0], b[1], s + OFF_BH + boff);
            LDSM4T(b[2], b[3], s + OFF_BH + boff + 32);
#pragma unroll
            for (int mt = 0; mt < 4; mt++)
#pragma unroll
                for (int nt = 0; nt < 4; nt++) mma16816(acc[mt][nt], ah[mt], b[nt]);
        }
    }

#pragma unroll
    for (int mt = 0; mt < 4; mt++) {
        const int m = m0 + wm0 + mt * 16 + (lane >> 2);
#pragma unroll
        for (int nt = 0; nt < 4; nt++) {
            const int n = n0 + wn0 + nt * 8 + (lane & 3) * 2;
            float2 bv = *(const float2*)(bias + n);
            float o0 = acc[mt][nt][0] + bv.x;
            float o1 = acc[mt][nt][1] + bv.y;
            float o2 = acc[mt][nt][2] + bv.x;
            float o3 = acc[mt][nt][3] + bv.y;
            if (EPI == 1) {
                float2 r0 = *(const float2*)(res + (size_t)m * N + n);
                float2 r1 = *(const float2*)(res + (size_t)(m + 8) * N + n);
                o0 += r0.x; o1 += r0.y; o2 += r1.x; o3 += r1.y;
                *(float2*)(C + (size_t)m * N + n) = make_float2(o0, o1);
                *(float2*)(C + (size_t)(m + 8) * N + n) = make_float2(o2, o3);
            } else {
                if (EPI == 2) {
                    o0 = 0.5f * o0 * (1.0f + erff(o0 * 0.7071067811865475f));
                    o1 = 0.5f * o1 * (1.0f + erff(o1 * 0.7071067811865475f));
                    o2 = 0.5f * o2 * (1.0f + erff(o2 * 0.7071067811865475f));
                    o3 = 0.5f * o3 * (1.0f + erff(o3 * 0.7071067811865475f));
                }
                *(uint32_t*)(Cho + (size_t)m * N + n) = pack_h2(o0, o1);
                *(uint32_t*)(Cho + (size_t)(m + 8) * N + n) = pack_h2(o2, o3);
            }
        }
    }
}

// ---------------------------------------------------------------------------
// Flash attention, fp16 1-pass both GEMMs: S = Qh*Kh; O += Ph*Vh.
// smem: Q 18432; 2 KV stages of 18432 (K 9216, V 9216).
// ---------------------------------------------------------------------------
#define FSTG 18432
__global__ void __launch_bounds__(256, 2) flash_kernel(
    const __half* __restrict__ QKV,
    const __half* __restrict__ sinv, const __half* __restrict__ pbb,
    const float* __restrict__ mask, __half* __restrict__ Ch)
{
    extern __shared__ char smem[];
    const uint32_t sb = cvta_smem(smem);
    const int tid = threadIdx.x, lane = tid & 31, warp = tid >> 5;
    const int qb = blockIdx.x << 7;
    const int bh = blockIdx.y, b = bh & 3, h = bh >> 2;
    const uint32_t sQ = sb;
    const uint32_t sKV = sb + 18432;

    // Q + stage 0
#pragma unroll
    for (int i = 0; i < 4; i++) {
        int idx = tid + (i << 8);
        int r = idx >> 3, c = idx & 7;
        size_t off = ((size_t)(b * Sn + qb + r)) * QKVS + h * 64 + c * 8;
        CP16(sQ + r * 144 + c * 16, QKV + off);
    }
#pragma unroll
    for (int i = 0; i < 2; i++) {
        int idx = tid + (i << 8);
        int r = idx >> 3, c = idx & 7;
        size_t off = ((size_t)(b * Sn + r)) * QKVS + h * 64 + c * 8;
        uint32_t d = sKV + r * 144 + c * 16;
        CP16(d, QKV + off + 512);           // K
        CP16(d + 9216, QKV + off + 1024);   // V
    }
    CP_COMMIT();

    const int qr0 = qb + (warp << 4) + (lane >> 2);
    const __half* sv0 = sinv + ((size_t)(b * Sn + qr0)) * Sn;
    const __half* sv1 = sv0 + (size_t)8 * Sn;
    const __half* pb0 = pbb + ((size_t)(h * Sn + qr0)) * Sn;
    const __half* pb1 = pb0 + (size_t)8 * Sn;
    const float* mrow = mask + b * Sn;

    float oacc[8][4];
#pragma unroll
    for (int t = 0; t < 8; t++)
#pragma unroll
        for (int r = 0; r < 4; r++) oacc[t][r] = 0.0f;
    float m0 = -1e30f, m1 = -1e30f, l0 = 0.0f, l1 = 0.0f;

    for (int it = 0; it < 32; it++) {
        if (it + 1 < 32) {
            const uint32_t s = sKV + ((it + 1) & 1) * FSTG;
            const int k0n = (it + 1) << 6;
#pragma unroll
            for (int i = 0; i < 2; i++) {
                int idx = tid + (i << 8);
                int r = idx >> 3, c = idx & 7;
                size_t off = ((size_t)(b * Sn + k0n + r)) * QKVS + h * 64 + c * 8;
                uint32_t d = s + r * 144 + c * 16;
                CP16(d, QKV + off + 512);
                CP16(d + 9216, QKV + off + 1024);
            }
        }
        CP_COMMIT();
        CP_WAIT1();
        __syncthreads();

        const uint32_t stg = sKV + (it & 1) * FSTG;
        float sacc[8][4];
#pragma unroll
        for (int t = 0; t < 8; t++)
#pragma unroll
            for (int r = 0; r < 4; r++) sacc[t][r] = 0.0f;

        // S = Qh * Kh
#pragma unroll
        for (int kc = 0; kc < 4; kc++) {
            uint32_t aq[4];
            const uint32_t qa = sQ + ((warp << 4) + (lane & 15)) * 144 +
                                ((kc << 4) + ((lane >> 4) << 3)) * 2;
            LDSM4(aq, qa);
#pragma unroll
            for (int nb = 0; nb < 4; nb++) {
                uint32_t kb[4];
                const uint32_t ka = stg + ((nb << 4) + (lane & 15)) * 144 +
                                    ((kc << 4) + ((lane >> 4) << 3)) * 2;
                LDSM4(kb, ka);
#pragma unroll
                for (int tt = 0; tt < 2; tt++) {
                    const int t = (nb << 1) + tt;
                    uint32_t b_[2] = {kb[tt], kb[tt + 2]};
                    mma16816(sacc[t], aq, b_);
                }
            }
        }

        // epilogue: sinv(fp16) + pb(fp16) + mask, online softmax
        const int k0 = it << 6;
        float tm0 = -1e30f, tm1 = -1e30f;
#pragma unroll
        for (int t = 0; t < 8; t++) {
            const int n = k0 + (t << 3) + ((lane & 3) << 1);
            uint32_t su0 = *(const uint32_t*)(sv0 + n);
            uint32_t su1 = *(const uint32_t*)(sv1 + n);
            float2 mk = *(const float2*)(mrow + n);
            uint32_t pu0 = *(const uint32_t*)(pb0 + n);
            uint32_t pu1 = *(const uint32_t*)(pb1 + n);
            sacc[t][0] = fmaf(sacc[t][0], h_lo(su0), h_lo(pu0) + mk.x);
            sacc[t][1] = fmaf(sacc[t][1], h_hi(su0), h_hi(pu0) + mk.y);
            sacc[t][2] = fmaf(sacc[t][2], h_lo(su1), h_lo(pu1) + mk.x);
            sacc[t][3] = fmaf(sacc[t][3], h_hi(su1), h_hi(pu1) + mk.y);
            tm0 = fmaxf(tm0, fmaxf(sacc[t][0], sacc[t][1]));
            tm1 = fmaxf(tm1, fmaxf(sacc[t][2], sacc[t][3]));
        }
        tm0 = fmaxf(tm0, __shfl_xor_sync(0xffffffffu, tm0, 1));
        tm0 = fmaxf(tm0, __shfl_xor_sync(0xffffffffu, tm0, 2));
        tm1 = fmaxf(tm1, __shfl_xor_sync(0xffffffffu, tm1, 1));
        tm1 = fmaxf(tm1, __shfl_xor_sync(0xffffffffu, tm1, 2));
        const float mn0 = fmaxf(m0, tm0), mn1 = fmaxf(m1, tm1);
        const float c0 = ex2f((m0 - mn0) * L2E), c1 = ex2f((m1 - mn1) * L2E);
        m0 = mn0; m1 = mn1;

        float rs0 = 0.0f, rs1 = 0.0f;
        uint32_t ap[4][4];
#pragma unroll
        for (int t = 0; t < 8; t++) {
            float p00 = ex2f((sacc[t][0] - m0) * L2E);
            float p01 = ex2f((sacc[t][1] - m0) * L2E);
            float p10 = ex2f((sacc[t][2] - m1) * L2E);
            float p11 = ex2f((sacc[t][3] - m1) * L2E);
            rs0 += p00 + p01; rs1 += p10 + p11;
            const int kc2 = t >> 1, hf = (t & 1) << 1;
            ap[kc2][hf] = pack_h2(p00, p01);
            ap[kc2][hf + 1] = pack_h2(p10, p11);
        }
        rs0 += __shfl_xor_sync(0xffffffffu, rs0, 1);
        rs0 += __shfl_xor_sync(0xffffffffu, rs0, 2);
        rs1 += __shfl_xor_sync(0xffffffffu, rs1, 1);
        rs1 += __shfl_xor_sync(0xffffffffu, rs1, 2);
        l0 = l0 * c0 + rs0;
        l1 = l1 * c1 + rs1;
#pragma unroll
        for (int t = 0; t < 8; t++) {
            oacc[t][0] *= c0; oacc[t][1] *= c0;
            oacc[t][2] *= c1; oacc[t][3] *= c1;
        }

        // O += Ph * Vh
#pragma unroll
        for (int kc2 = 0; kc2 < 4; kc2++) {
#pragma unroll
            for (int dnb = 0; dnb < 4; dnb++) {
                uint32_t vf[2][2];
                const uint32_t va = stg + 9216 +
                    ((kc2 << 4) + (lane & 15)) * 144 +
                    ((dnb << 4) + ((lane >> 4) << 3)) * 2;
                LDSM4T(vf[0], vf[1], va);
#pragma unroll
                for (int tt = 0; tt < 2; tt++)
                    mma16816(oacc[(dnb << 1) + tt], ap[kc2], vf[tt]);
            }
        }
        __syncthreads();
    }

    const float inv0 = 1.0f / l0, inv1 = 1.0f / l1;
#pragma unroll
    for (int t = 0; t < 8; t++) {
        const int d = (t << 3) + ((lane & 3) << 1);
        const size_t o0 = ((size_t)(b * Sn + qr0)) * Hn + h * 64 + d;
        const size_t o1 = ((size_t)(b * Sn + qr0 + 8)) * Hn + h * 64 + d;
        *(uint32_t*)(Ch + o0) = pack_h2(oacc[t][0] * inv0, oacc[t][1] * inv0);
        *(uint32_t*)(Ch + o1) = pack_h2(oacc[t][2] * inv1, oacc[t][3] * inv1);
    }
}

// ---------------------------------------------------------------------------
// LayerNorm over H=512; optional fp16 output.
// ---------------------------------------------------------------------------
__global__ void __launch_bounds__(256) ln_kernel(
    const float* __restrict__ in, const float* __restrict__ g,
    const float* __restrict__ bta, float* __restrict__ out,
    __half* __restrict__ ho)
{
    const size_t base = (size_t)blockIdx.x * Hn;
    const int tid = threadIdx.x;
    __shared__ float sh[8], sh2[8];
    float x0 = in[base + tid], x1 = in[base + tid + 256];
    float s = x0 + x1;
    for (int o = 16; o; o >>= 1) s += __shfl_xor_sync(0xffffffffu, s, o);
    if ((tid & 31) == 0) sh[tid >> 5] = s;
    __syncthreads();
    s = 0.0f;
#pragma unroll
    for (int i = 0; i < 8; i++) s += sh[i];
    const float mean = s * (1.0f / Hn);
    const float d0 = x0 - mean, d1 = x1 - mean;
    float vv = d0 * d0 + d1 * d1;
    for (int o = 16; o; o >>= 1) vv += __shfl_xor_sync(0xffffffffu, vv, o);
    if ((tid & 31) == 0) sh2[tid >> 5] = vv;
    __syncthreads();
    vv = 0.0f;
#pragma unroll
    for (int i = 0; i < 8; i++) vv += sh2[i];
    const float inv = rsqrtf(vv * (1.0f / Hn) + 1e-12f);
    const float y0 = d0 * inv * g[tid] + bta[tid];
    const float y1 = d1 * inv * g[tid + 256] + bta[tid + 256];
    out[base + tid] = y0;
    out[base + tid + 256] = y1;
    if (ho) {
        ho[base + tid] = __float2half_rn(y0);
        ho[base + tid + 256] = __float2half_rn(y1);
    }
}

// ---------------------------------------------------------------------------
extern "C" void kernel_launch(void* const* d_in, const int* in_sizes, int n_in,
                              void* d_out, int out_size)
{
    (void)in_sizes; (void)n_in; (void)out_size;
    const float* qs   = (const float*)d_in[0];
    const float* mask = (const float*)d_in[1];
    const float* pb   = (const float*)d_in[2];
    const int*   ts   = (const int*)d_in[3];
    const float* wq  = (const float*)d_in[4];  const float* bq  = (const float*)d_in[5];
    const float* wk  = (const float*)d_in[6];  const float* bk  = (const float*)d_in[7];
    const float* wv  = (const float*)d_in[8];  const float* bv  = (const float*)d_in[9];
    const float* wo  = (const float*)d_in[10]; const float* bo  = (const float*)d_in[11];
    const float* l1g = (const float*)d_in[12]; const float* l1b = (const float*)d_in[13];
    const float* wi  = (const float*)d_in[14]; const float* bi  = (const float*)d_in[15];
    const float* wo2 = (const float*)d_in[16]; const float* bo2 = (const float*)d_in[17];
    const float* l2g = (const float*)d_in[18]; const float* l2b = (const float*)d_in[19];

    float *x, *attn, *bqkv;
    cudaGetSymbolAddress((void**)&x,    g_x);
    cudaGetSymbolAddress((void**)&attn, g_attn);
    cudaGetSymbolAddress((void**)&bqkv, g_bqkv);

    __half *qkv, *ch, *xh, *th, *fh, *pbb, *sinvp;
    cudaGetSymbolAddress((void**)&qkv, g_qkv);
    cudaGetSymbolAddress((void**)&ch, g_ch);
    cudaGetSymbolAddress((void**)&xh, g_xh);
    cudaGetSymbolAddress((void**)&th, g_th);
    cudaGetSymbolAddress((void**)&fh, g_fh);
    cudaGetSymbolAddress((void**)&pbb, g_pbb);
    cudaGetSymbolAddress((void**)&sinvp, g_sinv);

    __half *wqkvp, *wop, *wip, *w2p;
    cudaGetSymbolAddress((void**)&wqkvp, g_wqkv);
    cudaGetSymbolAddress((void**)&wop, g_wo);
    cudaGetSymbolAddress((void**)&wip, g_wi);
    cudaGetSymbolAddress((void**)&w2p, g_w2);

    const int HM_SMEM = 2 * STAGE_BYTES;  // 37888
    const int FL_SMEM = 18432 + 2 * FSTG; // 55296
    cudaFuncSetAttribute(hmma_gemm<0>, cudaFuncAttributeMaxDynamicSharedMemorySize, HM_SMEM);
    cudaFuncSetAttribute(hmma_gemm<1>, cudaFuncAttributeMaxDynamicSharedMemorySize, HM_SMEM);
    cudaFuncSetAttribute(hmma_gemm<2>, cudaFuncAttributeMaxDynamicSharedMemorySize, HM_SMEM);
    cudaFuncSetAttribute(flash_kernel, cudaFuncAttributeMaxDynamicSharedMemorySize, FL_SMEM);

    const int PBN = NHn * Sn * Sn;
    prep_kernel<<<6147, 256>>>(wq, wk, wv, wo, wi, wo2, bq, bk, bv,
                               wqkvp, wop, wip, w2p, bqkv);
    cvt_h_kernel<<<PBN / 2048, 256>>>(pb, pbb, PBN);
    sinv_kernel<<<Bn * Sn, 256>>>(ts, sinvp);
    cvt_h_kernel<<<(Mn * Hn) / 2048, 256>>>(qs, xh, Mn * Hn);

    dim3 gqkv(QKVS / 128, Mn / 128);  // (12, 64)
    dim3 gproj(Hn / 128, Mn / 128);   // (4, 64)
    dim3 gff(Fn / 128, Mn / 128);     // (16, 64)
    dim3 gfl(Sn / 128, Bn * NHn);     // (16, 32)

    for (int l = 0; l < Ln; l++) {
        const size_t wOff  = (size_t)l * Hn * Hn;
        const size_t bOff  = (size_t)l * Hn;
        const size_t wiOff = (size_t)l * Hn * Fn;
        const size_t biOff = (size_t)l * Fn;
        const float* xres = (l == 0) ? qs : x;

        hmma_gemm<0><<<gqkv, 256, HM_SMEM>>>(xh,
            wqkvp + (size_t)l * Hn * QKVS, bqkv + l * QKVS,
            nullptr, nullptr, qkv, Hn, QKVS);

        flash_kernel<<<gfl, 256, FL_SMEM>>>(qkv, sinvp, pbb, mask, ch);

        hmma_gemm<1><<<gproj, 256, HM_SMEM>>>(ch, wop + wOff, bo + bOff,
                                              xres, attn, nullptr, Hn, Hn);
        ln_kernel<<<Mn, 256>>>(attn, l1g + bOff, l1b + bOff, attn, th);

        hmma_gemm<2><<<gff, 256, HM_SMEM>>>(th, wip + wiOff, bi + biOff,
                                            nullptr, nullptr, fh, Hn, Fn);
        hmma_gemm<1><<<gproj, 256, HM_SMEM>>>(fh, w2p + wiOff, bo2 + bOff,
                                              attn, x, nullptr, Fn, Hn);

        float* lnout = (l == Ln - 1) ? (float*)d_out : x;
        ln_kernel<<<Mn, 256>>>(x, l2g + bOff, l2b + bOff, lnout,
                               (l == Ln - 1) ? nullptr : xh);
    }
}